// round 8
// baseline (speedup 1.0000x reference)
#include <cuda_runtime.h>
#include <cuda_bf16.h>
#include <stdint.h>
#include <math.h>

#define BB 4
#define SS 2048
#define DM 768
#define NH 12
#define DK 64
#define NT (BB*SS)
#define BHN (BB*NH)

typedef __nv_bfloat16 bf16;
typedef __nv_bfloat162 bf162;

// ---------------- one scratch arena (single device symbol) ------------------
#define SZ_X   ((size_t)NT*DM*2)
#define SZ_W   ((size_t)DM*DM*2)
#define SZ_HS  ((size_t)BHN*SS*DK*2)
#define O_XQH  (0*SZ_X)
#define O_XQL  (1*SZ_X)
#define O_XKH  (2*SZ_X)
#define O_XKL  (3*SZ_X)
#define O_XVH  (4*SZ_X)
#define O_XVL  (5*SZ_X)
#define O_W    (6*SZ_X)
#define O_QH   (O_W + 8*SZ_W)
#define O_QL   (O_QH + 1*SZ_HS)
#define O_KH   (O_QH + 2*SZ_HS)
#define O_KL   (O_QH + 3*SZ_HS)
#define O_VH   (O_QH + 4*SZ_HS)         // V^T: [B,H,dk,S]
#define O_VL   (O_QH + 5*SZ_HS)
#define O_AOH  (O_QH + 6*SZ_HS)
#define O_AOL  (O_AOH + SZ_X)
#define O_PSUM (O_AOL + SZ_X)           // [BHN*SS][16] fp32
#define ARENA  (O_PSUM + (size_t)BHN*SS*16*4)

__device__ __align__(1024) char g_buf[ARENA];

// ---------------- helpers ----------------------------------------------------
#define SWZ(o) ((o) ^ (((o) >> 3) & 0x70))

__device__ __forceinline__ uint32_t s2u(const void* p) {
    uint32_t a;
    asm("{ .reg .u64 t; cvta.to.shared.u64 t, %1; cvt.u32.u64 %0, t; }" : "=r"(a) : "l"(p));
    return a;
}
__device__ __forceinline__ void ldsm4(uint32_t* r, uint32_t a) {
    asm volatile("ldmatrix.sync.aligned.m8n8.x4.shared.b16 {%0,%1,%2,%3}, [%4];"
                 : "=r"(r[0]), "=r"(r[1]), "=r"(r[2]), "=r"(r[3]) : "r"(a));
}
__device__ __forceinline__ void ldsm2(uint32_t* r, uint32_t a) {
    asm volatile("ldmatrix.sync.aligned.m8n8.x2.shared.b16 {%0,%1}, [%2];"
                 : "=r"(r[0]), "=r"(r[1]) : "r"(a));
}
__device__ __forceinline__ void hmma(float* c, const uint32_t* a, const uint32_t* b) {
    asm volatile("mma.sync.aligned.m16n8k16.row.col.f32.bf16.bf16.f32 "
                 "{%0,%1,%2,%3}, {%4,%5,%6,%7}, {%8,%9}, {%0,%1,%2,%3};"
                 : "+f"(c[0]), "+f"(c[1]), "+f"(c[2]), "+f"(c[3])
                 : "r"(a[0]), "r"(a[1]), "r"(a[2]), "r"(a[3]), "r"(b[0]), "r"(b[1]));
}
// ldmatrix address for m16k16 block at (rowBase, kb) inside SWZ tile (128B rows)
__device__ __forceinline__ uint32_t a_addr(uint32_t sbase, int rowBase, int kb, int lane) {
    int m = rowBase + (lane & 7) + ((lane >> 3) & 1) * 8;
    int kk = kb + (lane >> 4) * 8;
    return sbase + SWZ((uint32_t)(m * 128 + kk * 2));
}
// ldmatrix address for k16n8 block (B stored n-major [n][k]) — x2
__device__ __forceinline__ uint32_t b_addr(uint32_t sbase, int colBase, int kb, int lane) {
    int i = lane & 15;
    int n = colBase + (i & 7);
    int kk = kb + (i >> 3) * 8;
    return sbase + SWZ((uint32_t)(n * 128 + kk * 2));
}
// copy [rows x 64 bf16] (128B rows) gmem tile -> SW128 swizzled smem (256 thr)
__device__ __forceinline__ void load_tile(uint32_t dst, const bf16* __restrict__ src,
                                          int ld, int rows, int tid) {
    const int units = rows * 8;
    for (int u = tid; u < units; u += 256) {
        int r = u >> 3, j = u & 7;
        uint4 v = *reinterpret_cast<const uint4*>(src + (size_t)r * ld + j * 8);
        uint32_t off = SWZ((uint32_t)(r * 128 + j * 16));
        asm volatile("st.shared.v4.b32 [%0], {%1,%2,%3,%4};"
                     :: "r"(dst + off), "r"(v.x), "r"(v.y), "r"(v.z), "r"(v.w) : "memory");
    }
}
__device__ __forceinline__ uint32_t pk2(bf16 a, bf16 b) {
    bf162 t; t.x = a; t.y = b; return *reinterpret_cast<uint32_t*>(&t);
}
__device__ __forceinline__ void splitf(float f, bf16& h, bf16& l) {
    h = __float2bfloat16(f);
    l = __float2bfloat16(f - __bfloat162float(h));
}

// ---------------- pre-split kernels -----------------------------------------
__global__ __launch_bounds__(256) void split_f32(const float* __restrict__ x,
                                                 bf16* __restrict__ hi, bf16* __restrict__ lo, int n4) {
    int i = blockIdx.x * 256 + threadIdx.x;
    if (i >= n4) return;
    float4 v = reinterpret_cast<const float4*>(x)[i];
    bf16 h0, h1, h2, h3, l0, l1, l2, l3;
    splitf(v.x, h0, l0); splitf(v.y, h1, l1);
    splitf(v.z, h2, l2); splitf(v.w, h3, l3);
    uint2 hv = { pk2(h0, h1), pk2(h2, h3) };
    uint2 lv = { pk2(l0, l1), pk2(l2, l3) };
    reinterpret_cast<uint2*>(hi)[i] = hv;
    reinterpret_cast<uint2*>(lo)[i] = lv;
}
__global__ __launch_bounds__(256) void wsplit_t(const float* __restrict__ W,
                                                bf16* __restrict__ th, bf16* __restrict__ tl) {
    int idx = blockIdx.x * 256 + threadIdx.x;
    if (idx >= DM * DM) return;
    int n = idx / DM, k = idx % DM;
    bf16 h, l; splitf(W[(size_t)k * DM + n], h, l);
    th[idx] = h; tl[idx] = l;
}

// ---------------- generic bf16x3 GEMM via mma.sync, 128x128 tile -------------
// 8 warps: warp (wr = wid/4) covers 64 rows, (wc = wid%4) covers 32 cols.
// EPI 0: fp32 [NT,DM] (+bias)  EPI 1: head-split hi/lo [B,H,S,dk] (+bias)
// EPI 2: transposed hi/lo [B,H,dk,S] (+bias)
#define S_AH 0
#define S_AL 16384
#define S_BH 32768
#define S_BL 49152
#define S_RED 65536
#define SM_G 67584

template<int EPI>
__global__ __launch_bounds__(256) void gemm_mma(
    const bf16* __restrict__ Ahi, const bf16* __restrict__ Alo,
    const bf16* __restrict__ Bhi, const bf16* __restrict__ Blo,
    const float* __restrict__ bias,
    float* __restrict__ Cf, bf16* __restrict__ Ohi, bf16* __restrict__ Olo)
{
    extern __shared__ char smem[];
    const uint32_t sb = s2u(smem);
    const int tid = threadIdx.x, wid = tid >> 5, lane = tid & 31;
    const int wr = wid >> 2, wc = wid & 3;
    const int mBase = blockIdx.y * 128, nBase = blockIdx.x * 128;

    float c[4][4][4];
    #pragma unroll
    for (int i = 0; i < 4; i++)
        #pragma unroll
        for (int j = 0; j < 4; j++)
            #pragma unroll
            for (int q = 0; q < 4; q++) c[i][j][q] = 0.f;

    #pragma unroll 1
    for (int kc = 0; kc < DM / 64; kc++) {
        load_tile(sb + S_AH, Ahi + (size_t)mBase * DM + kc * 64, DM, 128, tid);
        load_tile(sb + S_AL, Alo + (size_t)mBase * DM + kc * 64, DM, 128, tid);
        load_tile(sb + S_BH, Bhi + (size_t)nBase * DM + kc * 64, DM, 128, tid);
        load_tile(sb + S_BL, Blo + (size_t)nBase * DM + kc * 64, DM, 128, tid);
        __syncthreads();
        #pragma unroll
        for (int ks = 0; ks < 4; ks++) {
            uint32_t ah[4][4], al[4][4], bh[4][2], bl[4][2];
            #pragma unroll
            for (int mf = 0; mf < 4; mf++) {
                ldsm4(ah[mf], a_addr(sb + S_AH, wr * 64 + mf * 16, ks * 16, lane));
                ldsm4(al[mf], a_addr(sb + S_AL, wr * 64 + mf * 16, ks * 16, lane));
            }
            #pragma unroll
            for (int nf = 0; nf < 4; nf++) {
                ldsm2(bh[nf], b_addr(sb + S_BH, wc * 32 + nf * 8, ks * 16, lane));
                ldsm2(bl[nf], b_addr(sb + S_BL, wc * 32 + nf * 8, ks * 16, lane));
            }
            #pragma unroll
            for (int mf = 0; mf < 4; mf++)
                #pragma unroll
                for (int nf = 0; nf < 4; nf++) {
                    hmma(c[mf][nf], ah[mf], bh[nf]);
                    hmma(c[mf][nf], ah[mf], bl[nf]);
                    hmma(c[mf][nf], al[mf], bh[nf]);
                }
        }
        __syncthreads();
    }

    const int gid = lane >> 2, tig = lane & 3;
    #pragma unroll
    for (int mf = 0; mf < 4; mf++) {
        #pragma unroll
        for (int nf = 0; nf < 4; nf++) {
            int row0 = mBase + wr * 64 + mf * 16 + gid;
            int col  = nBase + wc * 32 + nf * 8 + tig * 2;
            float v0 = c[mf][nf][0] + bias[col];
            float v1 = c[mf][nf][1] + bias[col + 1];
            float v2 = c[mf][nf][2] + bias[col];
            float v3 = c[mf][nf][3] + bias[col + 1];
            if (EPI == 0) {
                *reinterpret_cast<float2*>(&Cf[(size_t)row0 * DM + col])       = make_float2(v0, v1);
                *reinterpret_cast<float2*>(&Cf[(size_t)(row0 + 8) * DM + col]) = make_float2(v2, v3);
            } else if (EPI == 1) {
                int h = col >> 6, kk = col & 63;
                bf16 h0, h1, l0, l1;
                #pragma unroll
                for (int rr = 0; rr < 2; rr++) {
                    int m = row0 + rr * 8;
                    int b = m >> 11, s = m & 2047;
                    float f0 = rr ? v2 : v0, f1 = rr ? v3 : v1;
                    splitf(f0, h0, l0); splitf(f1, h1, l1);
                    size_t dst = (((size_t)b * NH + h) * SS + s) * DK + kk;
                    *reinterpret_cast<uint32_t*>(&Ohi[dst]) = pk2(h0, h1);
                    *reinterpret_cast<uint32_t*>(&Olo[dst]) = pk2(l0, l1);
                }
            } else {
                int h = col >> 6, kk = col & 63;
                #pragma unroll
                for (int rr = 0; rr < 2; rr++) {
                    int m = row0 + rr * 8;
                    int b = m >> 11, s = m & 2047;
                    float f0 = rr ? v2 : v0, f1 = rr ? v3 : v1;
                    bf16 hh, ll;
                    size_t dst0 = (((size_t)b * NH + h) * DK + kk) * SS + s;
                    splitf(f0, hh, ll); Ohi[dst0] = hh; Olo[dst0] = ll;
                    size_t dst1 = (((size_t)b * NH + h) * DK + kk + 1) * SS + s;
                    splitf(f1, hh, ll); Ohi[dst1] = hh; Olo[dst1] = ll;
                }
            }
        }
    }
}

// ---------------- scores: exp(Q.K^T/8) + deterministic partial row sums ------
__global__ __launch_bounds__(256) void scores_mma(
    const bf16* __restrict__ Qh, const bf16* __restrict__ Ql,
    const bf16* __restrict__ Kh, const bf16* __restrict__ Kl,
    float* __restrict__ attn, float* __restrict__ psum)
{
    extern __shared__ char smem[];
    const uint32_t sb = s2u(smem);
    float (*rowpart)[128] = reinterpret_cast<float(*)[128]>(smem + S_RED);
    const int tid = threadIdx.x, wid = tid >> 5, lane = tid & 31;
    const int wr = wid >> 2, wc = wid & 3;
    const int bh = blockIdx.z, qBase = blockIdx.y * 128, kBase = blockIdx.x * 128;

    const size_t qoff = ((size_t)bh * SS + qBase) * DK;
    const size_t koff = ((size_t)bh * SS + kBase) * DK;
    load_tile(sb + S_AH, Qh + qoff, DK, 128, tid);
    load_tile(sb + S_AL, Ql + qoff, DK, 128, tid);
    load_tile(sb + S_BH, Kh + koff, DK, 128, tid);
    load_tile(sb + S_BL, Kl + koff, DK, 128, tid);
    __syncthreads();

    float c[4][4][4];
    #pragma unroll
    for (int i = 0; i < 4; i++)
        #pragma unroll
        for (int j = 0; j < 4; j++)
            #pragma unroll
            for (int q = 0; q < 4; q++) c[i][j][q] = 0.f;

    #pragma unroll
    for (int ks = 0; ks < 4; ks++) {
        uint32_t ah[4][4], al[4][4], bhf[4][2], blf[4][2];
        #pragma unroll
        for (int mf = 0; mf < 4; mf++) {
            ldsm4(ah[mf], a_addr(sb + S_AH, wr * 64 + mf * 16, ks * 16, lane));
            ldsm4(al[mf], a_addr(sb + S_AL, wr * 64 + mf * 16, ks * 16, lane));
        }
        #pragma unroll
        for (int nf = 0; nf < 4; nf++) {
            ldsm2(bhf[nf], b_addr(sb + S_BH, wc * 32 + nf * 8, ks * 16, lane));
            ldsm2(blf[nf], b_addr(sb + S_BL, wc * 32 + nf * 8, ks * 16, lane));
        }
        #pragma unroll
        for (int mf = 0; mf < 4; mf++)
            #pragma unroll
            for (int nf = 0; nf < 4; nf++) {
                hmma(c[mf][nf], ah[mf], bhf[nf]);
                hmma(c[mf][nf], ah[mf], blf[nf]);
                hmma(c[mf][nf], al[mf], bhf[nf]);
            }
    }

    const int gid = lane >> 2, tig = lane & 3;
    #pragma unroll
    for (int mf = 0; mf < 4; mf++) {
        float p0 = 0.f, p1 = 0.f;
        int rloc0 = wr * 64 + mf * 16 + gid;
        #pragma unroll
        for (int nf = 0; nf < 4; nf++) {
            int col = kBase + wc * 32 + nf * 8 + tig * 2;
            float e0 = __expf(c[mf][nf][0] * 0.125f);
            float e1 = __expf(c[mf][nf][1] * 0.125f);
            float e2 = __expf(c[mf][nf][2] * 0.125f);
            float e3 = __expf(c[mf][nf][3] * 0.125f);
            p0 += e0 + e1; p1 += e2 + e3;
            *reinterpret_cast<float2*>(&attn[((size_t)bh * SS + qBase + rloc0) * SS + col])     = make_float2(e0, e1);
            *reinterpret_cast<float2*>(&attn[((size_t)bh * SS + qBase + rloc0 + 8) * SS + col]) = make_float2(e2, e3);
        }
        // deterministic quad reduction (lanes sharing gid)
        p0 += __shfl_xor_sync(0xffffffffu, p0, 1); p0 += __shfl_xor_sync(0xffffffffu, p0, 2);
        p1 += __shfl_xor_sync(0xffffffffu, p1, 1); p1 += __shfl_xor_sync(0xffffffffu, p1, 2);
        if (tig == 0) {
            rowpart[wc][rloc0]     = p0;
            rowpart[wc][rloc0 + 8] = p1;
        }
    }
    __syncthreads();
    if (tid < 128) {
        float s = rowpart[0][tid] + rowpart[1][tid] + rowpart[2][tid] + rowpart[3][tid];
        psum[((size_t)bh * SS + qBase + tid) * 16 + blockIdx.x] = s;
    }
}

// ---------------- fused normalize + final attn write + P.V -------------------
#define V_PH 0
#define V_PL 16384
#define V_VH 32768
#define V_VL 40960
#define V_RI 49152
#define SM_PV 49664

__global__ __launch_bounds__(256) void pv_mma(
    float* __restrict__ attn, const float* __restrict__ psum,
    const bf16* __restrict__ Vh, const bf16* __restrict__ Vl,
    bf16* __restrict__ AOh, bf16* __restrict__ AOl)
{
    extern __shared__ char smem[];
    const uint32_t sb = s2u(smem);
    float* rowinv = reinterpret_cast<float*>(smem + V_RI);
    const int tid = threadIdx.x, wid = tid >> 5, lane = tid & 31;
    const int wr = wid >> 1, wc = wid & 1;       // warp tile 32 rows x 32 cols
    const int bh = blockIdx.y, b = bh / NH, h = bh % NH;
    const int qBase = blockIdx.x * 128;

    if (tid < 128) {
        const float* pp = psum + ((size_t)bh * SS + qBase + tid) * 16;
        float s = 0.f;
        #pragma unroll
        for (int i = 0; i < 16; i++) s += pp[i];
        rowinv[tid] = 1.0f / s;
    }
    __syncthreads();

    float c[2][4][4];
    #pragma unroll
    for (int i = 0; i < 2; i++)
        #pragma unroll
        for (int j = 0; j < 4; j++)
            #pragma unroll
            for (int q = 0; q < 4; q++) c[i][j][q] = 0.f;

    #pragma unroll 1
    for (int kc = 0; kc < 32; kc++) {
        // stage P (128x64) hi/lo into swizzled smem; write normalized attn once
        {
            int r = tid >> 1, half = tid & 1;
            float inv = rowinv[r];
            float* ap = attn + ((size_t)bh * SS + qBase + r) * SS + kc * 64 + half * 32;
            #pragma unroll
            for (int j = 0; j < 16; j++) {
                float2 e = *reinterpret_cast<const float2*>(ap + j * 2);
                float p0 = e.x * inv, p1 = e.y * inv;
                *reinterpret_cast<float2*>(ap + j * 2) = make_float2(p0, p1);
                bf16 h0, h1, l0, l1;
                splitf(p0, h0, l0); splitf(p1, h1, l1);
                uint32_t off = SWZ((uint32_t)(r * 128 + (half * 32 + j * 2) * 2));
                asm volatile("st.shared.b32 [%0], %1;" :: "r"(sb + V_PH + off), "r"(pk2(h0, h1)) : "memory");
                asm volatile("st.shared.b32 [%0], %1;" :: "r"(sb + V_PL + off), "r"(pk2(l0, l1)) : "memory");
            }
        }
        load_tile(sb + V_VH, Vh + (size_t)bh * DK * SS + kc * 64, SS, 64, tid);
        load_tile(sb + V_VL, Vl + (size_t)bh * DK * SS + kc * 64, SS, 64, tid);
        __syncthreads();
        #pragma unroll
        for (int ks = 0; ks < 4; ks++) {
            uint32_t ah[2][4], al[2][4], bhf[4][2], blf[4][2];
            #pragma unroll
            for (int mf = 0; mf < 2; mf++) {
                ldsm4(ah[mf], a_addr(sb + V_PH, wr * 32 + mf * 16, ks * 16, lane));
                ldsm4(al[mf], a_addr(sb + V_PL, wr * 32 + mf * 16, ks * 16, lane));
            }
            #pragma unroll
            for (int nf = 0; nf < 4; nf++) {
                ldsm2(bhf[nf], b_addr(sb + V_VH, wc * 32 + nf * 8, ks * 16, lane));
                ldsm2(blf[nf], b_addr(sb + V_VL, wc * 32 + nf * 8, ks * 16, lane));
            }
            #pragma unroll
            for (int mf = 0; mf < 2; mf++)
                #pragma unroll
                for (int nf = 0; nf < 4; nf++) {
                    hmma(c[mf][nf], ah[mf], bhf[nf]);
                    hmma(c[mf][nf], ah[mf], blf[nf]);
                    hmma(c[mf][nf], al[mf], bhf[nf]);
                }
        }
        __syncthreads();
    }

    const int gid = lane >> 2, tig = lane & 3;
    #pragma unroll
    for (int mf = 0; mf < 2; mf++)
        #pragma unroll
        for (int nf = 0; nf < 4; nf++) {
            int rloc = wr * 32 + mf * 16 + gid;
            int col  = wc * 32 + nf * 8 + tig * 2;
            #pragma unroll
            for (int rr = 0; rr < 2; rr++) {
                int s = qBase + rloc + rr * 8;
                float f0 = c[mf][nf][rr * 2 + 0], f1 = c[mf][nf][rr * 2 + 1];
                bf16 h0, h1, l0, l1;
                splitf(f0, h0, l0); splitf(f1, h1, l1);
                size_t dst = ((size_t)b * SS + s) * DM + h * DK + col;
                *reinterpret_cast<uint32_t*>(&AOh[dst]) = pk2(h0, h1);
                *reinterpret_cast<uint32_t*>(&AOl[dst]) = pk2(l0, l1);
            }
        }
}

// ---------------------------------------------------------------------------
extern "C" void kernel_launch(void* const* d_in, const int* in_sizes, int n_in,
                              void* d_out, int out_size)
{
    (void)in_sizes; (void)n_in; (void)out_size;
    const float* q  = (const float*)d_in[0];
    const float* k  = (const float*)d_in[1];
    const float* v  = (const float*)d_in[2];
    const float* Wq = (const float*)d_in[3];
    const float* bq = (const float*)d_in[4];
    const float* Wk = (const float*)d_in[5];
    const float* bk = (const float*)d_in[6];
    const float* Wv = (const float*)d_in[7];
    const float* bv = (const float*)d_in[8];
    const float* Wo = (const float*)d_in[9];
    const float* bo = (const float*)d_in[10];

    float* out  = (float*)d_out;
    float* attn = out + (size_t)NT * DM;

    char* base = nullptr;
    cudaGetSymbolAddress((void**)&base, g_buf);
    bf16* xqh = (bf16*)(base + O_XQH); bf16* xql = (bf16*)(base + O_XQL);
    bf16* xkh = (bf16*)(base + O_XKH); bf16* xkl = (bf16*)(base + O_XKL);
    bf16* xvh = (bf16*)(base + O_XVH); bf16* xvl = (bf16*)(base + O_XVL);
    bf16* wqh = (bf16*)(base + O_W + 0*SZ_W); bf16* wql = (bf16*)(base + O_W + 1*SZ_W);
    bf16* wkh = (bf16*)(base + O_W + 2*SZ_W); bf16* wkl = (bf16*)(base + O_W + 3*SZ_W);
    bf16* wvh = (bf16*)(base + O_W + 4*SZ_W); bf16* wvl = (bf16*)(base + O_W + 5*SZ_W);
    bf16* woh = (bf16*)(base + O_W + 6*SZ_W); bf16* wol = (bf16*)(base + O_W + 7*SZ_W);
    bf16* Qh  = (bf16*)(base + O_QH);  bf16* Ql  = (bf16*)(base + O_QL);
    bf16* Kh  = (bf16*)(base + O_KH);  bf16* Kl  = (bf16*)(base + O_KL);
    bf16* Vh  = (bf16*)(base + O_VH);  bf16* Vl  = (bf16*)(base + O_VL);
    bf16* AOh = (bf16*)(base + O_AOH); bf16* AOl = (bf16*)(base + O_AOL);
    float* psum = (float*)(base + O_PSUM);

    cudaFuncSetAttribute(gemm_mma<0>, cudaFuncAttributeMaxDynamicSharedMemorySize, SM_G);
    cudaFuncSetAttribute(gemm_mma<1>, cudaFuncAttributeMaxDynamicSharedMemorySize, SM_G);
    cudaFuncSetAttribute(gemm_mma<2>, cudaFuncAttributeMaxDynamicSharedMemorySize, SM_G);
    cudaFuncSetAttribute(scores_mma,  cudaFuncAttributeMaxDynamicSharedMemorySize, SM_G);
    cudaFuncSetAttribute(pv_mma,      cudaFuncAttributeMaxDynamicSharedMemorySize, SM_PV);

    const int n4 = NT * DM / 4;
    split_f32<<<(n4 + 255) / 256, 256>>>(q, xqh, xql, n4);
    split_f32<<<(n4 + 255) / 256, 256>>>(k, xkh, xkl, n4);
    split_f32<<<(n4 + 255) / 256, 256>>>(v, xvh, xvl, n4);
    const int nw = DM * DM;
    wsplit_t<<<(nw + 255) / 256, 256>>>(Wq, wqh, wql);
    wsplit_t<<<(nw + 255) / 256, 256>>>(Wk, wkh, wkl);
    wsplit_t<<<(nw + 255) / 256, 256>>>(Wv, wvh, wvl);
    wsplit_t<<<(nw + 255) / 256, 256>>>(Wo, woh, wol);

    dim3 gProj(DM / 128, NT / 128);   // 6 x 64
    gemm_mma<1><<<gProj, 256, SM_G>>>(xqh, xql, wqh, wql, bq, nullptr, Qh, Ql);
    gemm_mma<1><<<gProj, 256, SM_G>>>(xkh, xkl, wkh, wkl, bk, nullptr, Kh, Kl);
    gemm_mma<2><<<gProj, 256, SM_G>>>(xvh, xvl, wvh, wvl, bv, nullptr, Vh, Vl);

    dim3 gS(SS / 128, SS / 128, BHN); // 16 x 16 x 48
    scores_mma<<<gS, 256, SM_G>>>(Qh, Ql, Kh, Kl, attn, psum);

    dim3 gPV(SS / 128, BHN);          // 16 x 48
    pv_mma<<<gPV, 256, SM_PV>>>(attn, psum, Vh, Vl, AOh, AOl);

    gemm_mma<0><<<gProj, 256, SM_G>>>(AOh, AOl, woh, wol, bo, out, nullptr, nullptr);
}

// round 11
// speedup vs baseline: 2.4075x; 2.4075x over previous
#include <cuda_runtime.h>
#include <cuda_bf16.h>
#include <stdint.h>
#include <math.h>

#define BB 4
#define SS 2048
#define DM 768
#define NH 12
#define DK 64
#define NT (BB*SS)
#define BHN (BB*NH)

typedef __nv_bfloat16 bf16;
typedef __nv_bfloat162 bf162;

// ---------------- scratch arena ---------------------------------------------
#define SZ_X   ((size_t)NT*DM*2)
#define SZ_W   ((size_t)DM*DM*2)
#define SZ_HS  ((size_t)BHN*SS*DK*2)
#define O_XQH  (0*SZ_X)
#define O_XQL  (1*SZ_X)
#define O_XKH  (2*SZ_X)
#define O_XKL  (3*SZ_X)
#define O_XVH  (4*SZ_X)
#define O_XVL  (5*SZ_X)
#define O_W    (6*SZ_X)
#define O_QH   (O_W + 8*SZ_W)
#define O_QL   (O_QH + 1*SZ_HS)
#define O_KH   (O_QH + 2*SZ_HS)
#define O_KL   (O_QH + 3*SZ_HS)
#define O_VH   (O_QH + 4*SZ_HS)         // V^T: [B,H,dk,S]
#define O_VL   (O_QH + 5*SZ_HS)
#define O_AOH  (O_QH + 6*SZ_HS)
#define O_AOL  (O_AOH + SZ_X)
#define O_PSUM (O_AOL + SZ_X)           // [BHN*SS][32] fp32
#define ARENA  (O_PSUM + (size_t)BHN*SS*32*4)

__device__ __align__(1024) char g_buf[ARENA];

// ---------------- helpers ----------------------------------------------------
#define SWZ(o) ((o) ^ (((o) >> 3) & 0x70))

__device__ __forceinline__ uint32_t s2u(const void* p) {
    uint32_t a;
    asm("{ .reg .u64 t; cvta.to.shared.u64 t, %1; cvt.u32.u64 %0, t; }" : "=r"(a) : "l"(p));
    return a;
}
__device__ __forceinline__ void ldsm4(uint32_t* r, uint32_t a) {
    asm volatile("ldmatrix.sync.aligned.m8n8.x4.shared.b16 {%0,%1,%2,%3}, [%4];"
                 : "=r"(r[0]), "=r"(r[1]), "=r"(r[2]), "=r"(r[3]) : "r"(a));
}
__device__ __forceinline__ void ldsm2(uint32_t* r, uint32_t a) {
    asm volatile("ldmatrix.sync.aligned.m8n8.x2.shared.b16 {%0,%1}, [%2];"
                 : "=r"(r[0]), "=r"(r[1]) : "r"(a));
}
__device__ __forceinline__ void hmma(float* c, const uint32_t* a, const uint32_t* b) {
    asm volatile("mma.sync.aligned.m16n8k16.row.col.f32.bf16.bf16.f32 "
                 "{%0,%1,%2,%3}, {%4,%5,%6,%7}, {%8,%9}, {%0,%1,%2,%3};"
                 : "+f"(c[0]), "+f"(c[1]), "+f"(c[2]), "+f"(c[3])
                 : "r"(a[0]), "r"(a[1]), "r"(a[2]), "r"(a[3]), "r"(b[0]), "r"(b[1]));
}
__device__ __forceinline__ uint32_t a_addr(uint32_t sbase, int rowBase, int kb, int lane) {
    int m = rowBase + (lane & 7) + ((lane >> 3) & 1) * 8;
    int kk = kb + (lane >> 4) * 8;
    return sbase + SWZ((uint32_t)(m * 128 + kk * 2));
}
__device__ __forceinline__ uint32_t b_addr(uint32_t sbase, int colBase, int kb, int lane) {
    int i = lane & 15;
    int n = colBase + (i & 7);
    int kk = kb + (i >> 3) * 8;
    return sbase + SWZ((uint32_t)(n * 128 + kk * 2));
}
__device__ __forceinline__ void cpasync16(uint32_t dst, const void* src) {
    asm volatile("cp.async.cg.shared.global [%0], [%1], 16;" :: "r"(dst), "l"(src));
}
#define CP_COMMIT() asm volatile("cp.async.commit_group;" ::: "memory")
#define CP_WAIT0()  asm volatile("cp.async.wait_group 0;" ::: "memory")
#define CP_WAIT1()  asm volatile("cp.async.wait_group 1;" ::: "memory")

// async copy [rows x 64 bf16] tile (128B rows) -> SW128 swizzled smem
__device__ __forceinline__ void tile_async(uint32_t dst, const bf16* __restrict__ src,
                                           int ld, int rows, int tid) {
    const int units = rows * 8;
    for (int u = tid; u < units; u += 256) {
        int r = u >> 3, j = u & 7;
        cpasync16(dst + SWZ((uint32_t)(r * 128 + j * 16)), src + (size_t)r * ld + j * 8);
    }
}
__device__ __forceinline__ uint32_t pk2(bf16 a, bf16 b) {
    bf162 t; t.x = a; t.y = b; return *reinterpret_cast<uint32_t*>(&t);
}
__device__ __forceinline__ void splitf(float f, bf16& h, bf16& l) {
    h = __float2bfloat16(f);
    l = __float2bfloat16(f - __bfloat162float(h));
}

// Shared mainloop: A 128x64 hi/lo, B 64x64 hi/lo (swizzled) -> c[2][4][4]
// warp wr (0..3): rows wr*32; wc (0..1): cols wc*32.
__device__ __forceinline__ void mma_stage(uint32_t ahb, uint32_t alb, uint32_t bhb, uint32_t blb,
                                          int wr, int wc, int lane, float (&c)[2][4][4]) {
    #pragma unroll
    for (int ks = 0; ks < 4; ks++) {
        uint32_t fah[2][4], fal[2][4], fbh[4][2], fbl[4][2];
        #pragma unroll
        for (int mf = 0; mf < 2; mf++) {
            ldsm4(fah[mf], a_addr(ahb, wr * 32 + mf * 16, ks * 16, lane));
            ldsm4(fal[mf], a_addr(alb, wr * 32 + mf * 16, ks * 16, lane));
        }
        #pragma unroll
        for (int nf = 0; nf < 4; nf++) {
            ldsm2(fbh[nf], b_addr(bhb, wc * 32 + nf * 8, ks * 16, lane));
            ldsm2(fbl[nf], b_addr(blb, wc * 32 + nf * 8, ks * 16, lane));
        }
        #pragma unroll
        for (int mf = 0; mf < 2; mf++)
            #pragma unroll
            for (int nf = 0; nf < 4; nf++) {
                hmma(c[mf][nf], fah[mf], fbh[nf]);
                hmma(c[mf][nf], fah[mf], fbl[nf]);
                hmma(c[mf][nf], fal[mf], fbh[nf]);
            }
    }
}

// ---------------- merged pre-split kernels ----------------------------------
__global__ __launch_bounds__(256) void split3(
    const float* __restrict__ q, const float* __restrict__ k, const float* __restrict__ v,
    bf16* __restrict__ qh, bf16* __restrict__ ql, bf16* __restrict__ kh, bf16* __restrict__ kl,
    bf16* __restrict__ vh, bf16* __restrict__ vl) {
    const int n4 = NT * DM / 4;
    int i = blockIdx.x * 256 + threadIdx.x;
    if (i >= n4) return;
    int sel = blockIdx.y;
    const float* x = sel == 0 ? q : sel == 1 ? k : v;
    bf16* hi = sel == 0 ? qh : sel == 1 ? kh : vh;
    bf16* lo = sel == 0 ? ql : sel == 1 ? kl : vl;
    float4 f = reinterpret_cast<const float4*>(x)[i];
    bf16 h0, h1, h2, h3, l0, l1, l2, l3;
    splitf(f.x, h0, l0); splitf(f.y, h1, l1);
    splitf(f.z, h2, l2); splitf(f.w, h3, l3);
    uint2 hv = { pk2(h0, h1), pk2(h2, h3) };
    uint2 lv = { pk2(l0, l1), pk2(l2, l3) };
    reinterpret_cast<uint2*>(hi)[i] = hv;
    reinterpret_cast<uint2*>(lo)[i] = lv;
}
__global__ __launch_bounds__(256) void wsplit4(
    const float* __restrict__ Wq, const float* __restrict__ Wk,
    const float* __restrict__ Wv, const float* __restrict__ Wo, bf16* __restrict__ wbase) {
    int idx = blockIdx.x * 256 + threadIdx.x;
    if (idx >= DM * DM) return;
    int sel = blockIdx.y;
    const float* W = sel == 0 ? Wq : sel == 1 ? Wk : sel == 2 ? Wv : Wo;
    bf16* th = wbase + (size_t)sel * 2 * (DM * DM);
    bf16* tl = th + DM * DM;
    int n = idx / DM, k = idx % DM;
    bf16 h, l; splitf(W[(size_t)k * DM + n], h, l);
    th[idx] = h; tl[idx] = l;
}

// ---------------- pipelined bf16x3 GEMM, 128x64 tile, K-chunk 64 ------------
// stage layout: st*49152 + {AH 0, AL 16384, BH 32768, BL 40960};  SM_G = 98304
#define G_ST 49152
#define SM_G 98304

template<int EPI>
__global__ __launch_bounds__(256, 2) void gemm_mma(
    const bf16* __restrict__ Ahi, const bf16* __restrict__ Alo,
    const bf16* __restrict__ Bhi, const bf16* __restrict__ Blo,
    const float* __restrict__ bias,
    float* __restrict__ Cf, bf16* __restrict__ Ohi, bf16* __restrict__ Olo)
{
    extern __shared__ char smem[];
    const uint32_t sb = s2u(smem);
    const int tid = threadIdx.x, wid = tid >> 5, lane = tid & 31;
    const int wr = wid >> 1, wc = wid & 1;
    const int mBase = blockIdx.y * 128, nBase = blockIdx.x * 64;
    const int NK = DM / 64;

    float c[2][4][4];
    #pragma unroll
    for (int i = 0; i < 2; i++)
        #pragma unroll
        for (int j = 0; j < 4; j++)
            #pragma unroll
            for (int q = 0; q < 4; q++) c[i][j][q] = 0.f;

    // prologue: stage 0
    tile_async(sb + 0,     Ahi + (size_t)mBase * DM, DM, 128, tid);
    tile_async(sb + 16384, Alo + (size_t)mBase * DM, DM, 128, tid);
    tile_async(sb + 32768, Bhi + (size_t)nBase * DM, DM, 64, tid);
    tile_async(sb + 40960, Blo + (size_t)nBase * DM, DM, 64, tid);
    CP_COMMIT();

    #pragma unroll 1
    for (int kc = 0; kc < NK; kc++) {
        if (kc + 1 < NK) {
            uint32_t st = ((kc + 1) & 1) * G_ST;
            tile_async(sb + st + 0,     Ahi + (size_t)mBase * DM + (kc + 1) * 64, DM, 128, tid);
            tile_async(sb + st + 16384, Alo + (size_t)mBase * DM + (kc + 1) * 64, DM, 128, tid);
            tile_async(sb + st + 32768, Bhi + (size_t)nBase * DM + (kc + 1) * 64, DM, 64, tid);
            tile_async(sb + st + 40960, Blo + (size_t)nBase * DM + (kc + 1) * 64, DM, 64, tid);
            CP_COMMIT();
            CP_WAIT1();
        } else {
            CP_WAIT0();
        }
        __syncthreads();
        uint32_t st = (kc & 1) * G_ST;
        mma_stage(sb + st, sb + st + 16384, sb + st + 32768, sb + st + 40960, wr, wc, lane, c);
        __syncthreads();
    }

    const int gid = lane >> 2, tig = lane & 3;
    #pragma unroll
    for (int mf = 0; mf < 2; mf++)
        #pragma unroll
        for (int nf = 0; nf < 4; nf++) {
            int row0 = mBase + wr * 32 + mf * 16 + gid;
            int col  = nBase + wc * 32 + nf * 8 + tig * 2;
            float v0 = c[mf][nf][0] + bias[col];
            float v1 = c[mf][nf][1] + bias[col + 1];
            float v2 = c[mf][nf][2] + bias[col];
            float v3 = c[mf][nf][3] + bias[col + 1];
            if (EPI == 0) {
                *reinterpret_cast<float2*>(&Cf[(size_t)row0 * DM + col])       = make_float2(v0, v1);
                *reinterpret_cast<float2*>(&Cf[(size_t)(row0 + 8) * DM + col]) = make_float2(v2, v3);
            } else if (EPI == 1) {
                int h = col >> 6, kk = col & 63;
                #pragma unroll
                for (int rr = 0; rr < 2; rr++) {
                    int m = row0 + rr * 8;
                    int b = m >> 11, s = m & 2047;
                    float f0 = rr ? v2 : v0, f1 = rr ? v3 : v1;
                    bf16 h0, h1, l0, l1;
                    splitf(f0, h0, l0); splitf(f1, h1, l1);
                    size_t dst = (((size_t)b * NH + h) * SS + s) * DK + kk;
                    *reinterpret_cast<uint32_t*>(&Ohi[dst]) = pk2(h0, h1);
                    *reinterpret_cast<uint32_t*>(&Olo[dst]) = pk2(l0, l1);
                }
            } else {
                int h = col >> 6, kk = col & 63;
                #pragma unroll
                for (int rr = 0; rr < 2; rr++) {
                    int m = row0 + rr * 8;
                    int b = m >> 11, s = m & 2047;
                    float f0 = rr ? v2 : v0, f1 = rr ? v3 : v1;
                    bf16 hh, ll;
                    size_t dst0 = (((size_t)b * NH + h) * DK + kk) * SS + s;
                    splitf(f0, hh, ll); Ohi[dst0] = hh; Olo[dst0] = ll;
                    size_t dst1 = (((size_t)b * NH + h) * DK + kk + 1) * SS + s;
                    splitf(f1, hh, ll); Ohi[dst1] = hh; Olo[dst1] = ll;
                }
            }
        }
}

// ---------------- scores: 128x64 tile, K=64, exp + partial sums --------------
// smem: QH 0(16K), QL 16384, KH 32768(8K), KL 40960, red 49152;  SM_S = 50176
#define SM_S 50176
__global__ __launch_bounds__(256, 2) void scores_mma(
    const bf16* __restrict__ Qh, const bf16* __restrict__ Ql,
    const bf16* __restrict__ Kh, const bf16* __restrict__ Kl,
    float* __restrict__ attn, float* __restrict__ psum)
{
    extern __shared__ char smem[];
    const uint32_t sb = s2u(smem);
    float (*rowpart)[128] = reinterpret_cast<float(*)[128]>(smem + 49152);
    const int tid = threadIdx.x, wid = tid >> 5, lane = tid & 31;
    const int wr = wid >> 1, wc = wid & 1;
    const int bh = blockIdx.z, qBase = blockIdx.y * 128, kBase = blockIdx.x * 64;

    tile_async(sb + 0,     Qh + ((size_t)bh * SS + qBase) * DK, DK, 128, tid);
    tile_async(sb + 16384, Ql + ((size_t)bh * SS + qBase) * DK, DK, 128, tid);
    tile_async(sb + 32768, Kh + ((size_t)bh * SS + kBase) * DK, DK, 64, tid);
    tile_async(sb + 40960, Kl + ((size_t)bh * SS + kBase) * DK, DK, 64, tid);
    CP_COMMIT();
    CP_WAIT0();
    __syncthreads();

    float c[2][4][4];
    #pragma unroll
    for (int i = 0; i < 2; i++)
        #pragma unroll
        for (int j = 0; j < 4; j++)
            #pragma unroll
            for (int q = 0; q < 4; q++) c[i][j][q] = 0.f;

    mma_stage(sb, sb + 16384, sb + 32768, sb + 40960, wr, wc, lane, c);

    const int gid = lane >> 2, tig = lane & 3;
    #pragma unroll
    for (int mf = 0; mf < 2; mf++) {
        float p0 = 0.f, p1 = 0.f;
        int rloc0 = wr * 32 + mf * 16 + gid;
        #pragma unroll
        for (int nf = 0; nf < 4; nf++) {
            int col = kBase + wc * 32 + nf * 8 + tig * 2;
            float e0 = __expf(c[mf][nf][0] * 0.125f);
            float e1 = __expf(c[mf][nf][1] * 0.125f);
            float e2 = __expf(c[mf][nf][2] * 0.125f);
            float e3 = __expf(c[mf][nf][3] * 0.125f);
            p0 += e0 + e1; p1 += e2 + e3;
            *reinterpret_cast<float2*>(&attn[((size_t)bh * SS + qBase + rloc0) * SS + col])     = make_float2(e0, e1);
            *reinterpret_cast<float2*>(&attn[((size_t)bh * SS + qBase + rloc0 + 8) * SS + col]) = make_float2(e2, e3);
        }
        p0 += __shfl_xor_sync(0xffffffffu, p0, 1); p0 += __shfl_xor_sync(0xffffffffu, p0, 2);
        p1 += __shfl_xor_sync(0xffffffffu, p1, 1); p1 += __shfl_xor_sync(0xffffffffu, p1, 2);
        if (tig == 0) {
            rowpart[wc][rloc0]     = p0;
            rowpart[wc][rloc0 + 8] = p1;
        }
    }
    __syncthreads();
    if (tid < 128) {
        float s = rowpart[0][tid] + rowpart[1][tid];
        psum[((size_t)bh * SS + qBase + tid) * 32 + blockIdx.x] = s;
    }
}

// ---------------- fused normalize + final attn write + P.V (pipelined) ------
// smem: PH 0(16K), PL 16384, V st: 32768+st*16384 {VH,VL 8K}, AT st: 65536+st*32768,
//       rowinv 131072;  SM_PV = 131584
#define PV_V(st)  (32768 + (st) * 16384)
#define PV_AT(st) (65536 + (st) * 32768)
#define SM_PV 131584

__global__ __launch_bounds__(256, 1) void pv_mma(
    float* __restrict__ attn, const float* __restrict__ psum,
    const bf16* __restrict__ Vh, const bf16* __restrict__ Vl,
    bf16* __restrict__ AOh, bf16* __restrict__ AOl)
{
    extern __shared__ char smem[];
    const uint32_t sb = s2u(smem);
    float* rowinv = reinterpret_cast<float*>(smem + 131072);
    const int tid = threadIdx.x, wid = tid >> 5, lane = tid & 31;
    const int wr = wid >> 1, wc = wid & 1;
    const int bh = blockIdx.y, b = bh / NH, h = bh % NH;
    const int qBase = blockIdx.x * 128;
    const float* arow0 = attn + ((size_t)bh * SS + qBase) * SS;

    if (tid < 128) {
        const float* pp = psum + ((size_t)bh * SS + qBase + tid) * 32;
        float s = 0.f;
        #pragma unroll
        for (int i = 0; i < 32; i++) s += pp[i];
        rowinv[tid] = 1.0f / s;
    }

    float c[2][4][4];
    #pragma unroll
    for (int i = 0; i < 2; i++)
        #pragma unroll
        for (int j = 0; j < 4; j++)
            #pragma unroll
            for (int q = 0; q < 4; q++) c[i][j][q] = 0.f;

    // prologue: stages for kc=0,1
    #pragma unroll
    for (int p = 0; p < 2; p++) {
        for (int u = tid; u < 2048; u += 256) {
            int r = u >> 4, j = u & 15;
            cpasync16(sb + PV_AT(p) + (uint32_t)(r * 256 + j * 16),
                      arow0 + (size_t)r * SS + p * 64 + j * 4);
        }
        tile_async(sb + PV_V(p),        Vh + (size_t)bh * DK * SS + p * 64, SS, 64, tid);
        tile_async(sb + PV_V(p) + 8192, Vl + (size_t)bh * DK * SS + p * 64, SS, 64, tid);
        CP_COMMIT();
    }

    #pragma unroll 1
    for (int kc = 0; kc < 32; kc++) {
        const int st = kc & 1;
        if (kc < 31) { CP_WAIT1(); } else { CP_WAIT0(); }
        __syncthreads();
        // normalize attn chunk from smem, write final attn, split -> P smem
        {
            int r = tid >> 1, half = tid & 1;
            float inv = rowinv[r];
            const char* atp = smem + PV_AT(st) + r * 256 + half * 128;
            float* gp = attn + ((size_t)bh * SS + qBase + r) * SS + kc * 64 + half * 32;
            #pragma unroll
            for (int j = 0; j < 16; j++) {
                float2 e = *reinterpret_cast<const float2*>(atp + j * 8);
                float p0 = e.x * inv, p1 = e.y * inv;
                *reinterpret_cast<float2*>(gp + j * 2) = make_float2(p0, p1);
                bf16 h0, h1, l0, l1;
                splitf(p0, h0, l0); splitf(p1, h1, l1);
                uint32_t off = SWZ((uint32_t)(r * 128 + (half * 32 + j * 2) * 2));
                asm volatile("st.shared.b32 [%0], %1;" :: "r"(sb + off), "r"(pk2(h0, h1)) : "memory");
                asm volatile("st.shared.b32 [%0], %1;" :: "r"(sb + 16384 + off), "r"(pk2(l0, l1)) : "memory");
            }
        }
        __syncthreads();
        mma_stage(sb, sb + 16384, sb + PV_V(st), sb + PV_V(st) + 8192, wr, wc, lane, c);
        __syncthreads();
        if (kc + 2 < 32) {
            for (int u = tid; u < 2048; u += 256) {
                int r = u >> 4, j = u & 15;
                cpasync16(sb + PV_AT(st) + (uint32_t)(r * 256 + j * 16),
                          arow0 + (size_t)r * SS + (kc + 2) * 64 + j * 4);
            }
            tile_async(sb + PV_V(st),        Vh + (size_t)bh * DK * SS + (kc + 2) * 64, SS, 64, tid);
            tile_async(sb + PV_V(st) + 8192, Vl + (size_t)bh * DK * SS + (kc + 2) * 64, SS, 64, tid);
            CP_COMMIT();
        }
    }

    const int gid = lane >> 2, tig = lane & 3;
    #pragma unroll
    for (int mf = 0; mf < 2; mf++)
        #pragma unroll
        for (int nf = 0; nf < 4; nf++) {
            int rloc = wr * 32 + mf * 16 + gid;
            int col  = wc * 32 + nf * 8 + tig * 2;
            #pragma unroll
            for (int rr = 0; rr < 2; rr++) {
                int s = qBase + rloc + rr * 8;
                float f0 = c[mf][nf][rr * 2 + 0], f1 = c[mf][nf][rr * 2 + 1];
                bf16 h0, h1, l0, l1;
                splitf(f0, h0, l0); splitf(f1, h1, l1);
                size_t dst = ((size_t)b * SS + s) * DM + h * DK + col;
                *reinterpret_cast<uint32_t*>(&AOh[dst]) = pk2(h0, h1);
                *reinterpret_cast<uint32_t*>(&AOl[dst]) = pk2(l0, l1);
            }
        }
}

// ---------------------------------------------------------------------------
extern "C" void kernel_launch(void* const* d_in, const int* in_sizes, int n_in,
                              void* d_out, int out_size)
{
    (void)in_sizes; (void)n_in; (void)out_size;
    const float* q  = (const float*)d_in[0];
    const float* k  = (const float*)d_in[1];
    const float* v  = (const float*)d_in[2];
    const float* Wq = (const float*)d_in[3];
    const float* bq = (const float*)d_in[4];
    const float* Wk = (const float*)d_in[5];
    const float* bk = (const float*)d_in[6];
    const float* Wv = (const float*)d_in[7];
    const float* bv = (const float*)d_in[8];
    const float* Wo = (const float*)d_in[9];
    const float* bo = (const float*)d_in[10];

    float* out  = (float*)d_out;
    float* attn = out + (size_t)NT * DM;

    char* base = nullptr;
    cudaGetSymbolAddress((void**)&base, g_buf);
    bf16* xqh = (bf16*)(base + O_XQH); bf16* xql = (bf16*)(base + O_XQL);
    bf16* xkh = (bf16*)(base + O_XKH); bf16* xkl = (bf16*)(base + O_XKL);
    bf16* xvh = (bf16*)(base + O_XVH); bf16* xvl = (bf16*)(base + O_XVL);
    bf16* wb  = (bf16*)(base + O_W);
    bf16* wqh = wb + 0*(size_t)DM*DM; bf16* wql = wb + 1*(size_t)DM*DM;
    bf16* wkh = wb + 2*(size_t)DM*DM; bf16* wkl = wb + 3*(size_t)DM*DM;
    bf16* wvh = wb + 4*(size_t)DM*DM; bf16* wvl = wb + 5*(size_t)DM*DM;
    bf16* woh = wb + 6*(size_t)DM*DM; bf16* wol = wb + 7*(size_t)DM*DM;
    bf16* Qh  = (bf16*)(base + O_QH);  bf16* Ql  = (bf16*)(base + O_QL);
    bf16* Kh  = (bf16*)(base + O_KH);  bf16* Kl  = (bf16*)(base + O_KL);
    bf16* Vh  = (bf16*)(base + O_VH);  bf16* Vl  = (bf16*)(base + O_VL);
    bf16* AOh = (bf16*)(base + O_AOH); bf16* AOl = (bf16*)(base + O_AOL);
    float* psum = (float*)(base + O_PSUM);

    cudaFuncSetAttribute(gemm_mma<0>, cudaFuncAttributeMaxDynamicSharedMemorySize, SM_G);
    cudaFuncSetAttribute(gemm_mma<1>, cudaFuncAttributeMaxDynamicSharedMemorySize, SM_G);
    cudaFuncSetAttribute(gemm_mma<2>, cudaFuncAttributeMaxDynamicSharedMemorySize, SM_G);
    cudaFuncSetAttribute(scores_mma,  cudaFuncAttributeMaxDynamicSharedMemorySize, SM_S);
    cudaFuncSetAttribute(pv_mma,      cudaFuncAttributeMaxDynamicSharedMemorySize, SM_PV);

    const int n4 = NT * DM / 4;
    split3<<<dim3((n4 + 255) / 256, 3), 256>>>(q, k, v, xqh, xql, xkh, xkl, xvh, xvl);
    wsplit4<<<dim3((DM * DM + 255) / 256, 4), 256>>>(Wq, Wk, Wv, Wo, wb);

    dim3 gProj(DM / 64, NT / 128);    // 12 x 64
    gemm_mma<1><<<gProj, 256, SM_G>>>(xqh, xql, wqh, wql, bq, nullptr, Qh, Ql);
    gemm_mma<1><<<gProj, 256, SM_G>>>(xkh, xkl, wkh, wkl, bk, nullptr, Kh, Kl);
    gemm_mma<2><<<gProj, 256, SM_G>>>(xvh, xvl, wvh, wvl, bv, nullptr, Vh, Vl);

    dim3 gS(SS / 64, SS / 128, BHN);  // 32 x 16 x 48  (launch #5 -> ncu capture)
    scores_mma<<<gS, 256, SM_S>>>(Qh, Ql, Kh, Kl, attn, psum);

    dim3 gPV(SS / 128, BHN);          // 16 x 48
    pv_mma<<<gPV, 256, SM_PV>>>(attn, psum, Vh, Vl, AOh, AOl);

    gemm_mma<0><<<gProj, 256, SM_G>>>(AOh, AOl, woh, wol, bo, out, nullptr, nullptr);
}

// round 12
// speedup vs baseline: 3.2449x; 1.3478x over previous
#include <cuda_runtime.h>
#include <cuda_bf16.h>
#include <stdint.h>
#include <math.h>

#define BB 4
#define SS 2048
#define DM 768
#define NH 12
#define DK 64
#define NT (BB*SS)
#define BHN (BB*NH)

typedef __nv_bfloat16 bf16;
typedef __nv_bfloat162 bf162;

// ---------------- scratch arena ---------------------------------------------
#define SZ_X   ((size_t)NT*DM*2)
#define SZ_W   ((size_t)DM*DM*2)
#define SZ_HS  ((size_t)BHN*SS*DK*2)
#define O_XQH  (0*SZ_X)
#define O_XQL  (1*SZ_X)
#define O_XKH  (2*SZ_X)
#define O_XKL  (3*SZ_X)
#define O_XVH  (4*SZ_X)
#define O_XVL  (5*SZ_X)
#define O_W    (6*SZ_X)
#define O_QH   (O_W + 8*SZ_W)
#define O_QL   (O_QH + 1*SZ_HS)
#define O_KH   (O_QH + 2*SZ_HS)
#define O_KL   (O_QH + 3*SZ_HS)
#define O_VH   (O_QH + 4*SZ_HS)         // V^T: [B,H,dk,S]
#define O_VL   (O_QH + 5*SZ_HS)
#define O_AOH  (O_QH + 6*SZ_HS)
#define O_AOL  (O_AOH + SZ_X)
#define O_PSUM (O_AOL + SZ_X)           // [BHN*SS][32] fp32
#define ARENA  (O_PSUM + (size_t)BHN*SS*32*4)

__device__ __align__(1024) char g_buf[ARENA];

// ---------------- helpers ----------------------------------------------------
#define SWZ(o) ((o) ^ (((o) >> 3) & 0x70))

__device__ __forceinline__ uint32_t s2u(const void* p) {
    uint32_t a;
    asm("{ .reg .u64 t; cvta.to.shared.u64 t, %1; cvt.u32.u64 %0, t; }" : "=r"(a) : "l"(p));
    return a;
}
__device__ __forceinline__ void ldsm4(uint32_t* r, uint32_t a) {
    asm volatile("ldmatrix.sync.aligned.m8n8.x4.shared.b16 {%0,%1,%2,%3}, [%4];"
                 : "=r"(r[0]), "=r"(r[1]), "=r"(r[2]), "=r"(r[3]) : "r"(a));
}
__device__ __forceinline__ void ldsm2(uint32_t* r, uint32_t a) {
    asm volatile("ldmatrix.sync.aligned.m8n8.x2.shared.b16 {%0,%1}, [%2];"
                 : "=r"(r[0]), "=r"(r[1]) : "r"(a));
}
__device__ __forceinline__ void hmma(float* c, const uint32_t* a, const uint32_t* b) {
    asm volatile("mma.sync.aligned.m16n8k16.row.col.f32.bf16.bf16.f32 "
                 "{%0,%1,%2,%3}, {%4,%5,%6,%7}, {%8,%9}, {%0,%1,%2,%3};"
                 : "+f"(c[0]), "+f"(c[1]), "+f"(c[2]), "+f"(c[3])
                 : "r"(a[0]), "r"(a[1]), "r"(a[2]), "r"(a[3]), "r"(b[0]), "r"(b[1]));
}
__device__ __forceinline__ uint32_t a_addr(uint32_t sbase, int rowBase, int kb, int lane) {
    int m = rowBase + (lane & 7) + ((lane >> 3) & 1) * 8;
    int kk = kb + (lane >> 4) * 8;
    return sbase + SWZ((uint32_t)(m * 128 + kk * 2));
}
__device__ __forceinline__ uint32_t b_addr(uint32_t sbase, int colBase, int kb, int lane) {
    int i = lane & 15;
    int n = colBase + (i & 7);
    int kk = kb + (i >> 3) * 8;
    return sbase + SWZ((uint32_t)(n * 128 + kk * 2));
}
__device__ __forceinline__ void cpasync16(uint32_t dst, const void* src) {
    asm volatile("cp.async.cg.shared.global [%0], [%1], 16;" :: "r"(dst), "l"(src));
}
#define CP_COMMIT() asm volatile("cp.async.commit_group;" ::: "memory")
#define CP_WAIT0()  asm volatile("cp.async.wait_group 0;" ::: "memory")
#define CP_WAIT1()  asm volatile("cp.async.wait_group 1;" ::: "memory")

// async copy [rows x 64 bf16] tile (128B rows) -> SW128 swizzled smem
__device__ __forceinline__ void tile_async(uint32_t dst, const bf16* __restrict__ src,
                                           int ld, int rows, int tid) {
    const int units = rows * 8;
    for (int u = tid; u < units; u += 256) {
        int r = u >> 3, j = u & 7;
        cpasync16(dst + SWZ((uint32_t)(r * 128 + j * 16)), src + (size_t)r * ld + j * 8);
    }
}
__device__ __forceinline__ uint32_t pk2(bf16 a, bf16 b) {
    bf162 t; t.x = a; t.y = b; return *reinterpret_cast<uint32_t*>(&t);
}
__device__ __forceinline__ void splitf(float f, bf16& h, bf16& l) {
    h = __float2bfloat16(f);
    l = __float2bfloat16(f - __bfloat162float(h));
}

// Shared mainloop: A 128x64 hi/lo, B 64x64 hi/lo (swizzled) -> c[2][4][4]
__device__ __forceinline__ void mma_stage(uint32_t ahb, uint32_t alb, uint32_t bhb, uint32_t blb,
                                          int wr, int wc, int lane, float (&c)[2][4][4]) {
    #pragma unroll
    for (int ks = 0; ks < 4; ks++) {
        uint32_t fah[2][4], fal[2][4], fbh[4][2], fbl[4][2];
        #pragma unroll
        for (int mf = 0; mf < 2; mf++) {
            ldsm4(fah[mf], a_addr(ahb, wr * 32 + mf * 16, ks * 16, lane));
            ldsm4(fal[mf], a_addr(alb, wr * 32 + mf * 16, ks * 16, lane));
        }
        #pragma unroll
        for (int nf = 0; nf < 4; nf++) {
            ldsm2(fbh[nf], b_addr(bhb, wc * 32 + nf * 8, ks * 16, lane));
            ldsm2(fbl[nf], b_addr(blb, wc * 32 + nf * 8, ks * 16, lane));
        }
        #pragma unroll
        for (int mf = 0; mf < 2; mf++)
            #pragma unroll
            for (int nf = 0; nf < 4; nf++) {
                hmma(c[mf][nf], fah[mf], fbh[nf]);
                hmma(c[mf][nf], fah[mf], fbl[nf]);
                hmma(c[mf][nf], fal[mf], fbh[nf]);
            }
    }
}

// ---------------- merged pre-split kernels ----------------------------------
__global__ __launch_bounds__(256) void split3(
    const float* __restrict__ q, const float* __restrict__ k, const float* __restrict__ v,
    bf16* __restrict__ qh, bf16* __restrict__ ql, bf16* __restrict__ kh, bf16* __restrict__ kl,
    bf16* __restrict__ vh, bf16* __restrict__ vl) {
    const int n4 = NT * DM / 4;
    int i = blockIdx.x * 256 + threadIdx.x;
    if (i >= n4) return;
    int sel = blockIdx.y;
    const float* x = sel == 0 ? q : sel == 1 ? k : v;
    bf16* hi = sel == 0 ? qh : sel == 1 ? kh : vh;
    bf16* lo = sel == 0 ? ql : sel == 1 ? kl : vl;
    float4 f = reinterpret_cast<const float4*>(x)[i];
    bf16 h0, h1, h2, h3, l0, l1, l2, l3;
    splitf(f.x, h0, l0); splitf(f.y, h1, l1);
    splitf(f.z, h2, l2); splitf(f.w, h3, l3);
    uint2 hv = { pk2(h0, h1), pk2(h2, h3) };
    uint2 lv = { pk2(l0, l1), pk2(l2, l3) };
    reinterpret_cast<uint2*>(hi)[i] = hv;
    reinterpret_cast<uint2*>(lo)[i] = lv;
}
__global__ __launch_bounds__(256) void wsplit4(
    const float* __restrict__ Wq, const float* __restrict__ Wk,
    const float* __restrict__ Wv, const float* __restrict__ Wo, bf16* __restrict__ wbase) {
    int idx = blockIdx.x * 256 + threadIdx.x;
    if (idx >= DM * DM) return;
    int sel = blockIdx.y;
    const float* W = sel == 0 ? Wq : sel == 1 ? Wk : sel == 2 ? Wv : Wo;
    bf16* th = wbase + (size_t)sel * 2 * (DM * DM);
    bf16* tl = th + DM * DM;
    int n = idx / DM, k = idx % DM;
    bf16 h, l; splitf(W[(size_t)k * DM + n], h, l);
    th[idx] = h; tl[idx] = l;
}

// ---------------- pipelined bf16x3 GEMM, 128x64 tile, K-chunk 64 ------------
#define G_ST 49152
#define SM_G 98304

template<int EPI>
__global__ __launch_bounds__(256, 2) void gemm_mma(
    const bf16* __restrict__ Ahi, const bf16* __restrict__ Alo,
    const bf16* __restrict__ Bhi, const bf16* __restrict__ Blo,
    const float* __restrict__ bias,
    float* __restrict__ Cf, bf16* __restrict__ Ohi, bf16* __restrict__ Olo)
{
    extern __shared__ char smem[];
    const uint32_t sb = s2u(smem);
    const int tid = threadIdx.x, wid = tid >> 5, lane = tid & 31;
    const int wr = wid >> 1, wc = wid & 1;
    const int mBase = blockIdx.y * 128, nBase = blockIdx.x * 64;
    const int NK = DM / 64;

    float c[2][4][4];
    #pragma unroll
    for (int i = 0; i < 2; i++)
        #pragma unroll
        for (int j = 0; j < 4; j++)
            #pragma unroll
            for (int q = 0; q < 4; q++) c[i][j][q] = 0.f;

    tile_async(sb + 0,     Ahi + (size_t)mBase * DM, DM, 128, tid);
    tile_async(sb + 16384, Alo + (size_t)mBase * DM, DM, 128, tid);
    tile_async(sb + 32768, Bhi + (size_t)nBase * DM, DM, 64, tid);
    tile_async(sb + 40960, Blo + (size_t)nBase * DM, DM, 64, tid);
    CP_COMMIT();

    #pragma unroll 1
    for (int kc = 0; kc < NK; kc++) {
        if (kc + 1 < NK) {
            uint32_t st = ((kc + 1) & 1) * G_ST;
            tile_async(sb + st + 0,     Ahi + (size_t)mBase * DM + (kc + 1) * 64, DM, 128, tid);
            tile_async(sb + st + 16384, Alo + (size_t)mBase * DM + (kc + 1) * 64, DM, 128, tid);
            tile_async(sb + st + 32768, Bhi + (size_t)nBase * DM + (kc + 1) * 64, DM, 64, tid);
            tile_async(sb + st + 40960, Blo + (size_t)nBase * DM + (kc + 1) * 64, DM, 64, tid);
            CP_COMMIT();
            CP_WAIT1();
        } else {
            CP_WAIT0();
        }
        __syncthreads();
        uint32_t st = (kc & 1) * G_ST;
        mma_stage(sb + st, sb + st + 16384, sb + st + 32768, sb + st + 40960, wr, wc, lane, c);
        __syncthreads();
    }

    const int gid = lane >> 2, tig = lane & 3;
    #pragma unroll
    for (int mf = 0; mf < 2; mf++)
        #pragma unroll
        for (int nf = 0; nf < 4; nf++) {
            int row0 = mBase + wr * 32 + mf * 16 + gid;
            int col  = nBase + wc * 32 + nf * 8 + tig * 2;
            float v0 = c[mf][nf][0] + bias[col];
            float v1 = c[mf][nf][1] + bias[col + 1];
            float v2 = c[mf][nf][2] + bias[col];
            float v3 = c[mf][nf][3] + bias[col + 1];
            if (EPI == 0) {
                *reinterpret_cast<float2*>(&Cf[(size_t)row0 * DM + col])       = make_float2(v0, v1);
                *reinterpret_cast<float2*>(&Cf[(size_t)(row0 + 8) * DM + col]) = make_float2(v2, v3);
            } else if (EPI == 1) {
                int h = col >> 6, kk = col & 63;
                #pragma unroll
                for (int rr = 0; rr < 2; rr++) {
                    int m = row0 + rr * 8;
                    int b = m >> 11, s = m & 2047;
                    float f0 = rr ? v2 : v0, f1 = rr ? v3 : v1;
                    bf16 h0, h1, l0, l1;
                    splitf(f0, h0, l0); splitf(f1, h1, l1);
                    size_t dst = (((size_t)b * NH + h) * SS + s) * DK + kk;
                    *reinterpret_cast<uint32_t*>(&Ohi[dst]) = pk2(h0, h1);
                    *reinterpret_cast<uint32_t*>(&Olo[dst]) = pk2(l0, l1);
                }
            } else {
                int h = col >> 6, kk = col & 63;
                #pragma unroll
                for (int rr = 0; rr < 2; rr++) {
                    int m = row0 + rr * 8;
                    int b = m >> 11, s = m & 2047;
                    float f0 = rr ? v2 : v0, f1 = rr ? v3 : v1;
                    bf16 hh, ll;
                    size_t dst0 = (((size_t)b * NH + h) * DK + kk) * SS + s;
                    splitf(f0, hh, ll); Ohi[dst0] = hh; Olo[dst0] = ll;
                    size_t dst1 = (((size_t)b * NH + h) * DK + kk + 1) * SS + s;
                    splitf(f1, hh, ll); Ohi[dst1] = hh; Olo[dst1] = ll;
                }
            }
        }
}

// ---------------- scores: 128x64 tile, K=64, exp + partial sums --------------
#define SM_S 50176
__global__ __launch_bounds__(256, 2) void scores_mma(
    const bf16* __restrict__ Qh, const bf16* __restrict__ Ql,
    const bf16* __restrict__ Kh, const bf16* __restrict__ Kl,
    float* __restrict__ attn, float* __restrict__ psum)
{
    extern __shared__ char smem[];
    const uint32_t sb = s2u(smem);
    float (*rowpart)[128] = reinterpret_cast<float(*)[128]>(smem + 49152);
    const int tid = threadIdx.x, wid = tid >> 5, lane = tid & 31;
    const int wr = wid >> 1, wc = wid & 1;
    const int bh = blockIdx.z, qBase = blockIdx.y * 128, kBase = blockIdx.x * 64;

    tile_async(sb + 0,     Qh + ((size_t)bh * SS + qBase) * DK, DK, 128, tid);
    tile_async(sb + 16384, Ql + ((size_t)bh * SS + qBase) * DK, DK, 128, tid);
    tile_async(sb + 32768, Kh + ((size_t)bh * SS + kBase) * DK, DK, 64, tid);
    tile_async(sb + 40960, Kl + ((size_t)bh * SS + kBase) * DK, DK, 64, tid);
    CP_COMMIT();
    CP_WAIT0();
    __syncthreads();

    float c[2][4][4];
    #pragma unroll
    for (int i = 0; i < 2; i++)
        #pragma unroll
        for (int j = 0; j < 4; j++)
            #pragma unroll
            for (int q = 0; q < 4; q++) c[i][j][q] = 0.f;

    mma_stage(sb, sb + 16384, sb + 32768, sb + 40960, wr, wc, lane, c);

    const int gid = lane >> 2, tig = lane & 3;
    #pragma unroll
    for (int mf = 0; mf < 2; mf++) {
        float p0 = 0.f, p1 = 0.f;
        int rloc0 = wr * 32 + mf * 16 + gid;
        #pragma unroll
        for (int nf = 0; nf < 4; nf++) {
            int col = kBase + wc * 32 + nf * 8 + tig * 2;
            float e0 = __expf(c[mf][nf][0] * 0.125f);
            float e1 = __expf(c[mf][nf][1] * 0.125f);
            float e2 = __expf(c[mf][nf][2] * 0.125f);
            float e3 = __expf(c[mf][nf][3] * 0.125f);
            p0 += e0 + e1; p1 += e2 + e3;
            *reinterpret_cast<float2*>(&attn[((size_t)bh * SS + qBase + rloc0) * SS + col])     = make_float2(e0, e1);
            *reinterpret_cast<float2*>(&attn[((size_t)bh * SS + qBase + rloc0 + 8) * SS + col]) = make_float2(e2, e3);
        }
        p0 += __shfl_xor_sync(0xffffffffu, p0, 1); p0 += __shfl_xor_sync(0xffffffffu, p0, 2);
        p1 += __shfl_xor_sync(0xffffffffu, p1, 1); p1 += __shfl_xor_sync(0xffffffffu, p1, 2);
        if (tig == 0) {
            rowpart[wc][rloc0]     = p0;
            rowpart[wc][rloc0 + 8] = p1;
        }
    }
    __syncthreads();
    if (tid < 128) {
        float s = rowpart[0][tid] + rowpart[1][tid];
        psum[((size_t)bh * SS + qBase + tid) * 32 + blockIdx.x] = s;
    }
}

// ---------------- fused normalize + final attn write + P.V ------------------
// smem: PH 0 (16K), PL 16384 (16K), V stage st: 32768+st*16384 {VH 8K, VL 8K},
//       rowinv 65536;  SM_PV = 66048  -> 2 CTAs/SM
#define PV_V(st)  (32768 + (st) * 16384)
#define SM_PV 66048

__global__ __launch_bounds__(256, 2) void pv_mma(
    float* __restrict__ attn, const float* __restrict__ psum,
    const bf16* __restrict__ Vh, const bf16* __restrict__ Vl,
    bf16* __restrict__ AOh, bf16* __restrict__ AOl)
{
    extern __shared__ char smem[];
    const uint32_t sb = s2u(smem);
    float* rowinv = reinterpret_cast<float*>(smem + 65536);
    const int tid = threadIdx.x, wid = tid >> 5, lane = tid & 31;
    const int wr = wid >> 1, wc = wid & 1;
    const int bh = blockIdx.y, b = bh / NH, h = bh % NH;
    const int qBase = blockIdx.x * 128;

    if (tid < 128) {
        const float* pp = psum + ((size_t)bh * SS + qBase + tid) * 32;
        float s = 0.f;
        #pragma unroll
        for (int i = 0; i < 32; i++) s += pp[i];
        rowinv[tid] = 1.0f / s;
    }

    float c[2][4][4];
    #pragma unroll
    for (int i = 0; i < 2; i++)
        #pragma unroll
        for (int j = 0; j < 4; j++)
            #pragma unroll
            for (int q = 0; q < 4; q++) c[i][j][q] = 0.f;

    // prologue: V stages for kc=0,1
    #pragma unroll
    for (int p = 0; p < 2; p++) {
        tile_async(sb + PV_V(p),        Vh + (size_t)bh * DK * SS + p * 64, SS, 64, tid);
        tile_async(sb + PV_V(p) + 8192, Vl + (size_t)bh * DK * SS + p * 64, SS, 64, tid);
        CP_COMMIT();
    }

    #pragma unroll 1
    for (int kc = 0; kc < 32; kc++) {
        const int st = kc & 1;
        if (kc < 31) { CP_WAIT1(); } else { CP_WAIT0(); }
        __syncthreads();   // V(kc) visible; previous mma done (P safe to overwrite)
        // normalize attn chunk (direct streaming LDG), write final attn, split -> P smem
        {
            int r = tid >> 1, half = tid & 1;
            float inv = rowinv[r];
            float* gp = attn + ((size_t)bh * SS + qBase + r) * SS + kc * 64 + half * 32;
            #pragma unroll
            for (int j = 0; j < 8; j++) {
                float4 e = __ldcs(reinterpret_cast<const float4*>(gp + j * 4));
                float p0 = e.x * inv, p1 = e.y * inv, p2 = e.z * inv, p3 = e.w * inv;
                __stcs(reinterpret_cast<float4*>(gp + j * 4), make_float4(p0, p1, p2, p3));
                bf16 h0, h1, l0, l1;
                int cb = half * 32 + j * 4;
                uint32_t off0 = SWZ((uint32_t)(r * 128 + cb * 2));
                splitf(p0, h0, l0); splitf(p1, h1, l1);
                asm volatile("st.shared.b32 [%0], %1;" :: "r"(sb + off0), "r"(pk2(h0, h1)) : "memory");
                asm volatile("st.shared.b32 [%0], %1;" :: "r"(sb + 16384 + off0), "r"(pk2(l0, l1)) : "memory");
                splitf(p2, h0, l0); splitf(p3, h1, l1);
                asm volatile("st.shared.b32 [%0], %1;" :: "r"(sb + off0 + 4), "r"(pk2(h0, h1)) : "memory");
                asm volatile("st.shared.b32 [%0], %1;" :: "r"(sb + 16384 + off0 + 4), "r"(pk2(l0, l1)) : "memory");
            }
        }
        __syncthreads();
        mma_stage(sb, sb + 16384, sb + PV_V(st), sb + PV_V(st) + 8192, wr, wc, lane, c);
        __syncthreads();
        if (kc + 2 < 32) {
            tile_async(sb + PV_V(st),        Vh + (size_t)bh * DK * SS + (kc + 2) * 64, SS, 64, tid);
            tile_async(sb + PV_V(st) + 8192, Vl + (size_t)bh * DK * SS + (kc + 2) * 64, SS, 64, tid);
            CP_COMMIT();
        }
    }

    const int gid = lane >> 2, tig = lane & 3;
    #pragma unroll
    for (int mf = 0; mf < 2; mf++)
        #pragma unroll
        for (int nf = 0; nf < 4; nf++) {
            int rloc = wr * 32 + mf * 16 + gid;
            int col  = wc * 32 + nf * 8 + tig * 2;
            #pragma unroll
            for (int rr = 0; rr < 2; rr++) {
                int s = qBase + rloc + rr * 8;
                float f0 = c[mf][nf][rr * 2 + 0], f1 = c[mf][nf][rr * 2 + 1];
                bf16 h0, h1, l0, l1;
                splitf(f0, h0, l0); splitf(f1, h1, l1);
                size_t dst = ((size_t)b * SS + s) * DM + h * DK + col;
                *reinterpret_cast<uint32_t*>(&AOh[dst]) = pk2(h0, h1);
                *reinterpret_cast<uint32_t*>(&AOl[dst]) = pk2(l0, l1);
            }
        }
}

// ---------------------------------------------------------------------------
extern "C" void kernel_launch(void* const* d_in, const int* in_sizes, int n_in,
                              void* d_out, int out_size)
{
    (void)in_sizes; (void)n_in; (void)out_size;
    const float* q  = (const float*)d_in[0];
    const float* k  = (const float*)d_in[1];
    const float* v  = (const float*)d_in[2];
    const float* Wq = (const float*)d_in[3];
    const float* bq = (const float*)d_in[4];
    const float* Wk = (const float*)d_in[5];
    const float* bk = (const float*)d_in[6];
    const float* Wv = (const float*)d_in[7];
    const float* bv = (const float*)d_in[8];
    const float* Wo = (const float*)d_in[9];
    const float* bo = (const float*)d_in[10];

    float* out  = (float*)d_out;
    float* attn = out + (size_t)NT * DM;

    char* base = nullptr;
    cudaGetSymbolAddress((void**)&base, g_buf);
    bf16* xqh = (bf16*)(base + O_XQH); bf16* xql = (bf16*)(base + O_XQL);
    bf16* xkh = (bf16*)(base + O_XKH); bf16* xkl = (bf16*)(base + O_XKL);
    bf16* xvh = (bf16*)(base + O_XVH); bf16* xvl = (bf16*)(base + O_XVL);
    bf16* wb  = (bf16*)(base + O_W);
    bf16* wqh = wb + 0*(size_t)DM*DM; bf16* wql = wb + 1*(size_t)DM*DM;
    bf16* wkh = wb + 2*(size_t)DM*DM; bf16* wkl = wb + 3*(size_t)DM*DM;
    bf16* wvh = wb + 4*(size_t)DM*DM; bf16* wvl = wb + 5*(size_t)DM*DM;
    bf16* woh = wb + 6*(size_t)DM*DM; bf16* wol = wb + 7*(size_t)DM*DM;
    bf16* Qh  = (bf16*)(base + O_QH);  bf16* Ql  = (bf16*)(base + O_QL);
    bf16* Kh  = (bf16*)(base + O_KH);  bf16* Kl  = (bf16*)(base + O_KL);
    bf16* Vh  = (bf16*)(base + O_VH);  bf16* Vl  = (bf16*)(base + O_VL);
    bf16* AOh = (bf16*)(base + O_AOH); bf16* AOl = (bf16*)(base + O_AOL);
    float* psum = (float*)(base + O_PSUM);

    cudaFuncSetAttribute(gemm_mma<0>, cudaFuncAttributeMaxDynamicSharedMemorySize, SM_G);
    cudaFuncSetAttribute(gemm_mma<1>, cudaFuncAttributeMaxDynamicSharedMemorySize, SM_G);
    cudaFuncSetAttribute(gemm_mma<2>, cudaFuncAttributeMaxDynamicSharedMemorySize, SM_G);
    cudaFuncSetAttribute(scores_mma,  cudaFuncAttributeMaxDynamicSharedMemorySize, SM_S);
    cudaFuncSetAttribute(pv_mma,      cudaFuncAttributeMaxDynamicSharedMemorySize, SM_PV);

    const int n4 = NT * DM / 4;
    split3<<<dim3((n4 + 255) / 256, 3), 256>>>(q, k, v, xqh, xql, xkh, xkl, xvh, xvl);
    wsplit4<<<dim3((DM * DM + 255) / 256, 4), 256>>>(Wq, Wk, Wv, Wo, wb);

    dim3 gProj(DM / 64, NT / 128);    // 12 x 64
    gemm_mma<1><<<gProj, 256, SM_G>>>(xqh, xql, wqh, wql, bq, nullptr, Qh, Ql);
    gemm_mma<1><<<gProj, 256, SM_G>>>(xkh, xkl, wkh, wkl, bk, nullptr, Kh, Kl);
    gemm_mma<2><<<gProj, 256, SM_G>>>(xvh, xvl, wvh, wvl, bv, nullptr, Vh, Vl);

    dim3 gS(SS / 64, SS / 128, BHN);  // 32 x 16 x 48
    scores_mma<<<gS, 256, SM_S>>>(Qh, Ql, Kh, Kl, attn, psum);

    dim3 gPV(SS / 128, BHN);          // 16 x 48
    pv_mma<<<gPV, 256, SM_PV>>>(attn, psum, Vh, Vl, AOh, AOl);

    gemm_mma<0><<<gProj, 256, SM_G>>>(AOh, AOl, woh, wol, bo, out, nullptr, nullptr);
}

// round 13
// speedup vs baseline: 3.4679x; 1.0687x over previous
#include <cuda_runtime.h>
#include <cuda_bf16.h>
#include <stdint.h>
#include <math.h>

#define BB 4
#define SS 2048
#define DM 768
#define NH 12
#define DK 64
#define NT (BB*SS)
#define BHN (BB*NH)

typedef __nv_bfloat16 bf16;
typedef __nv_bfloat162 bf162;

// ---------------- scratch arena ---------------------------------------------
#define SZ_X   ((size_t)NT*DM*2)
#define SZ_W   ((size_t)DM*DM*2)
#define SZ_HS  ((size_t)BHN*SS*DK*2)
#define O_XQH  (0*SZ_X)
#define O_XQL  (1*SZ_X)
#define O_XKH  (2*SZ_X)
#define O_XKL  (3*SZ_X)
#define O_XVH  (4*SZ_X)
#define O_XVL  (5*SZ_X)
#define O_W    (6*SZ_X)
#define O_QH   (O_W + 8*SZ_W)
#define O_QL   (O_QH + 1*SZ_HS)
#define O_KH   (O_QH + 2*SZ_HS)
#define O_KL   (O_QH + 3*SZ_HS)
#define O_VH   (O_QH + 4*SZ_HS)         // V^T: [B,H,dk,S]
#define O_VL   (O_QH + 5*SZ_HS)
#define O_AOH  (O_QH + 6*SZ_HS)
#define O_AOL  (O_AOH + SZ_X)
#define O_PSUM (O_AOL + SZ_X)           // [BHN*SS][8] fp32
#define ARENA  (O_PSUM + (size_t)BHN*SS*8*4)

__device__ __align__(1024) char g_buf[ARENA];

// ---------------- helpers ----------------------------------------------------
#define SWZ(o) ((o) ^ (((o) >> 3) & 0x70))

__device__ __forceinline__ uint32_t s2u(const void* p) {
    uint32_t a;
    asm("{ .reg .u64 t; cvta.to.shared.u64 t, %1; cvt.u32.u64 %0, t; }" : "=r"(a) : "l"(p));
    return a;
}
__device__ __forceinline__ void ldsm4(uint32_t* r, uint32_t a) {
    asm volatile("ldmatrix.sync.aligned.m8n8.x4.shared.b16 {%0,%1,%2,%3}, [%4];"
                 : "=r"(r[0]), "=r"(r[1]), "=r"(r[2]), "=r"(r[3]) : "r"(a));
}
__device__ __forceinline__ void hmma(float* c, const uint32_t* a, const uint32_t* b) {
    asm volatile("mma.sync.aligned.m16n8k16.row.col.f32.bf16.bf16.f32 "
                 "{%0,%1,%2,%3}, {%4,%5,%6,%7}, {%8,%9}, {%0,%1,%2,%3};"
                 : "+f"(c[0]), "+f"(c[1]), "+f"(c[2]), "+f"(c[3])
                 : "r"(a[0]), "r"(a[1]), "r"(a[2]), "r"(a[3]), "r"(b[0]), "r"(b[1]));
}
__device__ __forceinline__ uint32_t a_addr(uint32_t sbase, int rowBase, int kb, int lane) {
    int m = rowBase + (lane & 7) + ((lane >> 3) & 1) * 8;
    int kk = kb + (lane >> 4) * 8;
    return sbase + SWZ((uint32_t)(m * 128 + kk * 2));
}
// x4 B load: two n8 blocks (colBase.., colBase+8..) x k16
__device__ __forceinline__ uint32_t b_addr4(uint32_t sbase, int colBase, int kb, int lane) {
    int n = colBase + (lane & 7) + ((lane >> 4) & 1) * 8;
    int kk = kb + ((lane >> 3) & 1) * 8;
    return sbase + SWZ((uint32_t)(n * 128 + kk * 2));
}
__device__ __forceinline__ void cpasync16(uint32_t dst, const void* src) {
    asm volatile("cp.async.cg.shared.global [%0], [%1], 16;" :: "r"(dst), "l"(src));
}
#define CP_COMMIT() asm volatile("cp.async.commit_group;" ::: "memory")
#define CP_WAIT0()  asm volatile("cp.async.wait_group 0;" ::: "memory")
#define CP_WAIT1()  asm volatile("cp.async.wait_group 1;" ::: "memory")

__device__ __forceinline__ void tile_async(uint32_t dst, const bf16* __restrict__ src,
                                           int ld, int rows, int tid) {
    const int units = rows * 8;
    for (int u = tid; u < units; u += 256) {
        int r = u >> 3, j = u & 7;
        cpasync16(dst + SWZ((uint32_t)(r * 128 + j * 16)), src + (size_t)r * ld + j * 8);
    }
}
__device__ __forceinline__ uint32_t pk2(bf16 a, bf16 b) {
    bf162 t; t.x = a; t.y = b; return *reinterpret_cast<uint32_t*>(&t);
}
__device__ __forceinline__ void splitf(float f, bf16& h, bf16& l) {
    h = __float2bfloat16(f);
    l = __float2bfloat16(f - __bfloat162float(h));
}

// Shared mainloop: A 128x64 hi/lo, B 64x64 hi/lo (swizzled) -> c[2][4][4]
__device__ __forceinline__ void mma_stage(uint32_t ahb, uint32_t alb, uint32_t bhb, uint32_t blb,
                                          int wr, int wc, int lane, float (&c)[2][4][4]) {
    #pragma unroll
    for (int ks = 0; ks < 4; ks++) {
        uint32_t fah[2][4], fal[2][4], fbh[2][4], fbl[2][4];
        #pragma unroll
        for (int mf = 0; mf < 2; mf++) {
            ldsm4(fah[mf], a_addr(ahb, wr * 32 + mf * 16, ks * 16, lane));
            ldsm4(fal[mf], a_addr(alb, wr * 32 + mf * 16, ks * 16, lane));
        }
        #pragma unroll
        for (int g = 0; g < 2; g++) {
            ldsm4(fbh[g], b_addr4(bhb, wc * 32 + g * 16, ks * 16, lane));
            ldsm4(fbl[g], b_addr4(blb, wc * 32 + g * 16, ks * 16, lane));
        }
        #pragma unroll
        for (int mf = 0; mf < 2; mf++)
            #pragma unroll
            for (int nf = 0; nf < 4; nf++) {
                const uint32_t* bh_ = &fbh[nf >> 1][(nf & 1) * 2];
                const uint32_t* bl_ = &fbl[nf >> 1][(nf & 1) * 2];
                hmma(c[mf][nf], fah[mf], bh_);
                hmma(c[mf][nf], fah[mf], bl_);
                hmma(c[mf][nf], fal[mf], bh_);
            }
    }
}

// ---------------- merged pre-split kernels ----------------------------------
__global__ __launch_bounds__(256) void split3(
    const float* __restrict__ q, const float* __restrict__ k, const float* __restrict__ v) {
    const int n4 = NT * DM / 4;
    int i = blockIdx.x * 256 + threadIdx.x;
    if (i >= n4) return;
    int sel = blockIdx.y;
    const float* x = sel == 0 ? q : sel == 1 ? k : v;
    bf16* hi = (bf16*)(g_buf + (size_t)(2 * sel) * SZ_X);
    bf16* lo = (bf16*)(g_buf + (size_t)(2 * sel + 1) * SZ_X);
    float4 f = reinterpret_cast<const float4*>(x)[i];
    bf16 h0, h1, h2, h3, l0, l1, l2, l3;
    splitf(f.x, h0, l0); splitf(f.y, h1, l1);
    splitf(f.z, h2, l2); splitf(f.w, h3, l3);
    uint2 hv = { pk2(h0, h1), pk2(h2, h3) };
    uint2 lv = { pk2(l0, l1), pk2(l2, l3) };
    reinterpret_cast<uint2*>(hi)[i] = hv;
    reinterpret_cast<uint2*>(lo)[i] = lv;
}
__global__ __launch_bounds__(256) void wsplit4(
    const float* __restrict__ Wq, const float* __restrict__ Wk,
    const float* __restrict__ Wv, const float* __restrict__ Wo) {
    int idx = blockIdx.x * 256 + threadIdx.x;
    if (idx >= DM * DM) return;
    int sel = blockIdx.y;
    const float* W = sel == 0 ? Wq : sel == 1 ? Wk : sel == 2 ? Wv : Wo;
    bf16* th = (bf16*)(g_buf + O_W) + (size_t)sel * 2 * (DM * DM);
    bf16* tl = th + DM * DM;
    int n = idx / DM, k = idx % DM;
    bf16 h, l; splitf(W[(size_t)k * DM + n], h, l);
    th[idx] = h; tl[idx] = l;
}

// ---------------- merged QKV projection (grid.z = sel) -----------------------
#define G_ST 49152
#define SM_G 98304

__global__ __launch_bounds__(256, 2) void qkv_mma(
    const float* __restrict__ bq, const float* __restrict__ bk, const float* __restrict__ bv)
{
    extern __shared__ char smem[];
    const uint32_t sb = s2u(smem);
    const int tid = threadIdx.x, wid = tid >> 5, lane = tid & 31;
    const int wr = wid >> 1, wc = wid & 1;
    const int sel = blockIdx.z;
    const int mBase = blockIdx.y * 128, nBase = blockIdx.x * 64;
    const int NK = DM / 64;

    const bf16* Ahi = (const bf16*)(g_buf + (size_t)(2 * sel) * SZ_X);
    const bf16* Alo = (const bf16*)(g_buf + (size_t)(2 * sel + 1) * SZ_X);
    const bf16* Bhi = (const bf16*)(g_buf + O_W) + (size_t)sel * 2 * (DM * DM);
    const bf16* Blo = Bhi + DM * DM;
    const float* bias = sel == 0 ? bq : sel == 1 ? bk : bv;
    bf16* Ohi = (bf16*)(g_buf + O_QH + (size_t)(2 * sel) * SZ_HS);
    bf16* Olo = (bf16*)(g_buf + O_QH + (size_t)(2 * sel + 1) * SZ_HS);

    float c[2][4][4];
    #pragma unroll
    for (int i = 0; i < 2; i++)
        #pragma unroll
        for (int j = 0; j < 4; j++)
            #pragma unroll
            for (int q = 0; q < 4; q++) c[i][j][q] = 0.f;

    tile_async(sb + 0,     Ahi + (size_t)mBase * DM, DM, 128, tid);
    tile_async(sb + 16384, Alo + (size_t)mBase * DM, DM, 128, tid);
    tile_async(sb + 32768, Bhi + (size_t)nBase * DM, DM, 64, tid);
    tile_async(sb + 40960, Blo + (size_t)nBase * DM, DM, 64, tid);
    CP_COMMIT();

    #pragma unroll 1
    for (int kc = 0; kc < NK; kc++) {
        if (kc + 1 < NK) {
            uint32_t st = ((kc + 1) & 1) * G_ST;
            tile_async(sb + st + 0,     Ahi + (size_t)mBase * DM + (kc + 1) * 64, DM, 128, tid);
            tile_async(sb + st + 16384, Alo + (size_t)mBase * DM + (kc + 1) * 64, DM, 128, tid);
            tile_async(sb + st + 32768, Bhi + (size_t)nBase * DM + (kc + 1) * 64, DM, 64, tid);
            tile_async(sb + st + 40960, Blo + (size_t)nBase * DM + (kc + 1) * 64, DM, 64, tid);
            CP_COMMIT();
            CP_WAIT1();
        } else {
            CP_WAIT0();
        }
        __syncthreads();
        uint32_t st = (kc & 1) * G_ST;
        mma_stage(sb + st, sb + st + 16384, sb + st + 32768, sb + st + 40960, wr, wc, lane, c);
        __syncthreads();
    }

    const int gid = lane >> 2, tig = lane & 3;
    #pragma unroll
    for (int mf = 0; mf < 2; mf++)
        #pragma unroll
        for (int nf = 0; nf < 4; nf++) {
            int row0 = mBase + wr * 32 + mf * 16 + gid;
            int col  = nBase + wc * 32 + nf * 8 + tig * 2;
            float v0 = c[mf][nf][0] + bias[col];
            float v1 = c[mf][nf][1] + bias[col + 1];
            float v2 = c[mf][nf][2] + bias[col];
            float v3 = c[mf][nf][3] + bias[col + 1];
            int h = col >> 6, kk = col & 63;
            if (sel < 2) {
                #pragma unroll
                for (int rr = 0; rr < 2; rr++) {
                    int m = row0 + rr * 8;
                    int b = m >> 11, s = m & 2047;
                    float f0 = rr ? v2 : v0, f1 = rr ? v3 : v1;
                    bf16 h0, h1, l0, l1;
                    splitf(f0, h0, l0); splitf(f1, h1, l1);
                    size_t dst = (((size_t)b * NH + h) * SS + s) * DK + kk;
                    *reinterpret_cast<uint32_t*>(&Ohi[dst]) = pk2(h0, h1);
                    *reinterpret_cast<uint32_t*>(&Olo[dst]) = pk2(l0, l1);
                }
            } else {
                #pragma unroll
                for (int rr = 0; rr < 2; rr++) {
                    int m = row0 + rr * 8;
                    int b = m >> 11, s = m & 2047;
                    float f0 = rr ? v2 : v0, f1 = rr ? v3 : v1;
                    bf16 hh, ll;
                    size_t dst0 = (((size_t)b * NH + h) * DK + kk) * SS + s;
                    splitf(f0, hh, ll); Ohi[dst0] = hh; Olo[dst0] = ll;
                    size_t dst1 = (((size_t)b * NH + h) * DK + kk + 1) * SS + s;
                    splitf(f1, hh, ll); Ohi[dst1] = hh; Olo[dst1] = ll;
                }
            }
        }
}

// ---------------- output projection (fp32 epilogue) --------------------------
__global__ __launch_bounds__(256, 2) void oproj_mma(
    const bf16* __restrict__ Ahi, const bf16* __restrict__ Alo,
    const bf16* __restrict__ Bhi, const bf16* __restrict__ Blo,
    const float* __restrict__ bias, float* __restrict__ Cf)
{
    extern __shared__ char smem[];
    const uint32_t sb = s2u(smem);
    const int tid = threadIdx.x, wid = tid >> 5, lane = tid & 31;
    const int wr = wid >> 1, wc = wid & 1;
    const int mBase = blockIdx.y * 128, nBase = blockIdx.x * 64;
    const int NK = DM / 64;

    float c[2][4][4];
    #pragma unroll
    for (int i = 0; i < 2; i++)
        #pragma unroll
        for (int j = 0; j < 4; j++)
            #pragma unroll
            for (int q = 0; q < 4; q++) c[i][j][q] = 0.f;

    tile_async(sb + 0,     Ahi + (size_t)mBase * DM, DM, 128, tid);
    tile_async(sb + 16384, Alo + (size_t)mBase * DM, DM, 128, tid);
    tile_async(sb + 32768, Bhi + (size_t)nBase * DM, DM, 64, tid);
    tile_async(sb + 40960, Blo + (size_t)nBase * DM, DM, 64, tid);
    CP_COMMIT();

    #pragma unroll 1
    for (int kc = 0; kc < NK; kc++) {
        if (kc + 1 < NK) {
            uint32_t st = ((kc + 1) & 1) * G_ST;
            tile_async(sb + st + 0,     Ahi + (size_t)mBase * DM + (kc + 1) * 64, DM, 128, tid);
            tile_async(sb + st + 16384, Alo + (size_t)mBase * DM + (kc + 1) * 64, DM, 128, tid);
            tile_async(sb + st + 32768, Bhi + (size_t)nBase * DM + (kc + 1) * 64, DM, 64, tid);
            tile_async(sb + st + 40960, Blo + (size_t)nBase * DM + (kc + 1) * 64, DM, 64, tid);
            CP_COMMIT();
            CP_WAIT1();
        } else {
            CP_WAIT0();
        }
        __syncthreads();
        uint32_t st = (kc & 1) * G_ST;
        mma_stage(sb + st, sb + st + 16384, sb + st + 32768, sb + st + 40960, wr, wc, lane, c);
        __syncthreads();
    }

    const int gid = lane >> 2, tig = lane & 3;
    #pragma unroll
    for (int mf = 0; mf < 2; mf++)
        #pragma unroll
        for (int nf = 0; nf < 4; nf++) {
            int row0 = mBase + wr * 32 + mf * 16 + gid;
            int col  = nBase + wc * 32 + nf * 8 + tig * 2;
            float v0 = c[mf][nf][0] + bias[col];
            float v1 = c[mf][nf][1] + bias[col + 1];
            float v2 = c[mf][nf][2] + bias[col];
            float v3 = c[mf][nf][3] + bias[col + 1];
            *reinterpret_cast<float2*>(&Cf[(size_t)row0 * DM + col])       = make_float2(v0, v1);
            *reinterpret_cast<float2*>(&Cf[(size_t)(row0 + 8) * DM + col]) = make_float2(v2, v3);
        }
}

// ---------------- scores: Q-resident, 4 K-chunks, exp + row sums -------------
// smem: QH 0 (16K), QL 16384, K stage st: 32768+st*16384 {KH 8K, KL 8K},
//       rowpart 65536 (1K);  SM_S = 66560
#define SC_K(st) (32768 + (st) * 16384)
#define SM_S 66560

__global__ __launch_bounds__(256, 2) void scores_mma(
    float* __restrict__ attn, float* __restrict__ psum)
{
    extern __shared__ char smem[];
    const uint32_t sb = s2u(smem);
    float (*rowpart)[128] = reinterpret_cast<float(*)[128]>(smem + 65536);
    const int tid = threadIdx.x, wid = tid >> 5, lane = tid & 31;
    const int wr = wid >> 1, wc = wid & 1;
    const int bh = blockIdx.z, qBase = blockIdx.y * 128, kBase0 = blockIdx.x * 256;

    const bf16* Qh = (const bf16*)(g_buf + O_QH);
    const bf16* Ql = (const bf16*)(g_buf + O_QL);
    const bf16* Kh = (const bf16*)(g_buf + O_KH);
    const bf16* Kl = (const bf16*)(g_buf + O_KL);

    tile_async(sb + 0,     Qh + ((size_t)bh * SS + qBase) * DK, DK, 128, tid);
    tile_async(sb + 16384, Ql + ((size_t)bh * SS + qBase) * DK, DK, 128, tid);
    tile_async(sb + SC_K(0),        Kh + ((size_t)bh * SS + kBase0) * DK, DK, 64, tid);
    tile_async(sb + SC_K(0) + 8192, Kl + ((size_t)bh * SS + kBase0) * DK, DK, 64, tid);
    CP_COMMIT();
    tile_async(sb + SC_K(1),        Kh + ((size_t)bh * SS + kBase0 + 64) * DK, DK, 64, tid);
    tile_async(sb + SC_K(1) + 8192, Kl + ((size_t)bh * SS + kBase0 + 64) * DK, DK, 64, tid);
    CP_COMMIT();

    const int gid = lane >> 2, tig = lane & 3;
    float pacc[2][2] = {{0.f, 0.f}, {0.f, 0.f}};

    #pragma unroll 1
    for (int kc = 0; kc < 4; kc++) {
        const int st = kc & 1;
        if (kc < 3) { CP_WAIT1(); } else { CP_WAIT0(); }
        __syncthreads();

        float c[2][4][4];
        #pragma unroll
        for (int i = 0; i < 2; i++)
            #pragma unroll
            for (int j = 0; j < 4; j++)
                #pragma unroll
                for (int q = 0; q < 4; q++) c[i][j][q] = 0.f;

        mma_stage(sb, sb + 16384, sb + SC_K(st), sb + SC_K(st) + 8192, wr, wc, lane, c);
        __syncthreads();
        if (kc + 2 < 4) {
            tile_async(sb + SC_K(st),        Kh + ((size_t)bh * SS + kBase0 + (kc + 2) * 64) * DK, DK, 64, tid);
            tile_async(sb + SC_K(st) + 8192, Kl + ((size_t)bh * SS + kBase0 + (kc + 2) * 64) * DK, DK, 64, tid);
            CP_COMMIT();
        }

        #pragma unroll
        for (int mf = 0; mf < 2; mf++) {
            int rloc0 = wr * 32 + mf * 16 + gid;
            float* arow0 = attn + ((size_t)bh * SS + qBase + rloc0) * SS;
            float* arow1 = arow0 + (size_t)8 * SS;
            #pragma unroll
            for (int nf = 0; nf < 4; nf++) {
                int col = kBase0 + kc * 64 + wc * 32 + nf * 8 + tig * 2;
                float e0 = __expf(c[mf][nf][0] * 0.125f);
                float e1 = __expf(c[mf][nf][1] * 0.125f);
                float e2 = __expf(c[mf][nf][2] * 0.125f);
                float e3 = __expf(c[mf][nf][3] * 0.125f);
                pacc[mf][0] += e0 + e1; pacc[mf][1] += e2 + e3;
                *reinterpret_cast<float2*>(arow0 + col) = make_float2(e0, e1);
                *reinterpret_cast<float2*>(arow1 + col) = make_float2(e2, e3);
            }
        }
    }

    #pragma unroll
    for (int mf = 0; mf < 2; mf++) {
        float p0 = pacc[mf][0], p1 = pacc[mf][1];
        p0 += __shfl_xor_sync(0xffffffffu, p0, 1); p0 += __shfl_xor_sync(0xffffffffu, p0, 2);
        p1 += __shfl_xor_sync(0xffffffffu, p1, 1); p1 += __shfl_xor_sync(0xffffffffu, p1, 2);
        if (tig == 0) {
            int rloc0 = wr * 32 + mf * 16 + gid;
            rowpart[wc][rloc0]     = p0;
            rowpart[wc][rloc0 + 8] = p1;
        }
    }
    __syncthreads();
    if (tid < 128) {
        float s = rowpart[0][tid] + rowpart[1][tid];
        psum[((size_t)bh * SS + qBase + tid) * 8 + blockIdx.x] = s;
    }
}

// ---------------- fused normalize + final attn write + P.V ------------------
#define PV_V(st)  (32768 + (st) * 16384)
#define SM_PV 66048

__global__ __launch_bounds__(256, 2) void pv_mma(
    float* __restrict__ attn, const float* __restrict__ psum)
{
    extern __shared__ char smem[];
    const uint32_t sb = s2u(smem);
    float* rowinv = reinterpret_cast<float*>(smem + 65536);
    const int tid = threadIdx.x, wid = tid >> 5, lane = tid & 31;
    const int wr = wid >> 1, wc = wid & 1;
    const int bh = blockIdx.y, b = bh / NH, h = bh % NH;
    const int qBase = blockIdx.x * 128;

    const bf16* Vh = (const bf16*)(g_buf + O_VH);
    const bf16* Vl = (const bf16*)(g_buf + O_VL);
    bf16* AOh = (bf16*)(g_buf + O_AOH);
    bf16* AOl = (bf16*)(g_buf + O_AOL);

    if (tid < 128) {
        const float* pp = psum + ((size_t)bh * SS + qBase + tid) * 8;
        float s = 0.f;
        #pragma unroll
        for (int i = 0; i < 8; i++) s += pp[i];
        rowinv[tid] = 1.0f / s;
    }

    float c[2][4][4];
    #pragma unroll
    for (int i = 0; i < 2; i++)
        #pragma unroll
        for (int j = 0; j < 4; j++)
            #pragma unroll
            for (int q = 0; q < 4; q++) c[i][j][q] = 0.f;

    #pragma unroll
    for (int p = 0; p < 2; p++) {
        tile_async(sb + PV_V(p),        Vh + (size_t)bh * DK * SS + p * 64, SS, 64, tid);
        tile_async(sb + PV_V(p) + 8192, Vl + (size_t)bh * DK * SS + p * 64, SS, 64, tid);
        CP_COMMIT();
    }

    #pragma unroll 1
    for (int kc = 0; kc < 32; kc++) {
        const int st = kc & 1;
        if (kc < 31) { CP_WAIT1(); } else { CP_WAIT0(); }
        __syncthreads();
        {
            int r = tid >> 1, half = tid & 1;
            float inv = rowinv[r];
            float* gp = attn + ((size_t)bh * SS + qBase + r) * SS + kc * 64 + half * 32;
            #pragma unroll
            for (int j = 0; j < 8; j++) {
                float4 e = __ldcs(reinterpret_cast<const float4*>(gp + j * 4));
                float p0 = e.x * inv, p1 = e.y * inv, p2 = e.z * inv, p3 = e.w * inv;
                __stcs(reinterpret_cast<float4*>(gp + j * 4), make_float4(p0, p1, p2, p3));
                bf16 h0, h1, l0, l1;
                int cb = half * 32 + j * 4;
                uint32_t off0 = SWZ((uint32_t)(r * 128 + cb * 2));
                splitf(p0, h0, l0); splitf(p1, h1, l1);
                asm volatile("st.shared.b32 [%0], %1;" :: "r"(sb + off0), "r"(pk2(h0, h1)) : "memory");
                asm volatile("st.shared.b32 [%0], %1;" :: "r"(sb + 16384 + off0), "r"(pk2(l0, l1)) : "memory");
                splitf(p2, h0, l0); splitf(p3, h1, l1);
                asm volatile("st.shared.b32 [%0], %1;" :: "r"(sb + off0 + 4), "r"(pk2(h0, h1)) : "memory");
                asm volatile("st.shared.b32 [%0], %1;" :: "r"(sb + 16384 + off0 + 4), "r"(pk2(l0, l1)) : "memory");
            }
        }
        __syncthreads();
        mma_stage(sb, sb + 16384, sb + PV_V(st), sb + PV_V(st) + 8192, wr, wc, lane, c);
        __syncthreads();
        if (kc + 2 < 32) {
            tile_async(sb + PV_V(st),        Vh + (size_t)bh * DK * SS + (kc + 2) * 64, SS, 64, tid);
            tile_async(sb + PV_V(st) + 8192, Vl + (size_t)bh * DK * SS + (kc + 2) * 64, SS, 64, tid);
            CP_COMMIT();
        }
    }

    const int gid = lane >> 2, tig = lane & 3;
    #pragma unroll
    for (int mf = 0; mf < 2; mf++)
        #pragma unroll
        for (int nf = 0; nf < 4; nf++) {
            int rloc = wr * 32 + mf * 16 + gid;
            int col  = wc * 32 + nf * 8 + tig * 2;
            #pragma unroll
            for (int rr = 0; rr < 2; rr++) {
                int s = qBase + rloc + rr * 8;
                float f0 = c[mf][nf][rr * 2 + 0], f1 = c[mf][nf][rr * 2 + 1];
                bf16 h0, h1, l0, l1;
                splitf(f0, h0, l0); splitf(f1, h1, l1);
                size_t dst = ((size_t)b * SS + s) * DM + h * DK + col;
                *reinterpret_cast<uint32_t*>(&AOh[dst]) = pk2(h0, h1);
                *reinterpret_cast<uint32_t*>(&AOl[dst]) = pk2(l0, l1);
            }
        }
}

// ---------------------------------------------------------------------------
extern "C" void kernel_launch(void* const* d_in, const int* in_sizes, int n_in,
                              void* d_out, int out_size)
{
    (void)in_sizes; (void)n_in; (void)out_size;
    const float* q  = (const float*)d_in[0];
    const float* k  = (const float*)d_in[1];
    const float* v  = (const float*)d_in[2];
    const float* Wq = (const float*)d_in[3];
    const float* bq = (const float*)d_in[4];
    const float* Wk = (const float*)d_in[5];
    const float* bk = (const float*)d_in[6];
    const float* Wv = (const float*)d_in[7];
    const float* bv = (const float*)d_in[8];
    const float* Wo = (const float*)d_in[9];
    const float* bo = (const float*)d_in[10];

    float* out  = (float*)d_out;
    float* attn = out + (size_t)NT * DM;

    char* base = nullptr;
    cudaGetSymbolAddress((void**)&base, g_buf);
    bf16* wb  = (bf16*)(base + O_W);
    bf16* woh = wb + 6*(size_t)DM*DM; bf16* wol = wb + 7*(size_t)DM*DM;
    bf16* AOh = (bf16*)(base + O_AOH); bf16* AOl = (bf16*)(base + O_AOL);
    float* psum = (float*)(base + O_PSUM);

    cudaFuncSetAttribute(qkv_mma,    cudaFuncAttributeMaxDynamicSharedMemorySize, SM_G);
    cudaFuncSetAttribute(oproj_mma,  cudaFuncAttributeMaxDynamicSharedMemorySize, SM_G);
    cudaFuncSetAttribute(scores_mma, cudaFuncAttributeMaxDynamicSharedMemorySize, SM_S);
    cudaFuncSetAttribute(pv_mma,     cudaFuncAttributeMaxDynamicSharedMemorySize, SM_PV);

    const int n4 = NT * DM / 4;
    split3<<<dim3((n4 + 255) / 256, 3), 256>>>(q, k, v);
    wsplit4<<<dim3((DM * DM + 255) / 256, 4), 256>>>(Wq, Wk, Wv, Wo);

    dim3 gProj(DM / 64, NT / 128, 3);  // 12 x 64 x 3
    qkv_mma<<<gProj, 256, SM_G>>>(bq, bk, bv);

    dim3 gS(SS / 256, SS / 128, BHN);  // 8 x 16 x 48
    scores_mma<<<gS, 256, SM_S>>>(attn, psum);

    dim3 gPV(SS / 128, BHN);           // 16 x 48
    pv_mma<<<gPV, 256, SM_PV>>>(attn, psum);

    dim3 gO(DM / 64, NT / 128);        // 12 x 64
    oproj_mma<<<gO, 256, SM_G>>>(AOh, AOl, woh, wol, bo, out);
}

// round 14
// speedup vs baseline: 3.6201x; 1.0439x over previous
#include <cuda_runtime.h>
#include <cuda_bf16.h>
#include <stdint.h>
#include <math.h>

#define BB 4
#define SS 2048
#define DM 768
#define NH 12
#define DK 64
#define NT (BB*SS)
#define BHN (BB*NH)

typedef __nv_bfloat16 bf16;
typedef __nv_bfloat162 bf162;

// ---------------- scratch arena ---------------------------------------------
#define SZ_X   ((size_t)NT*DM*2)
#define SZ_W   ((size_t)DM*DM*2)
#define SZ_HS  ((size_t)BHN*SS*DK*2)
#define O_XQH  (0*SZ_X)
#define O_XQL  (1*SZ_X)
#define O_XKH  (2*SZ_X)
#define O_XKL  (3*SZ_X)
#define O_XVH  (4*SZ_X)
#define O_XVL  (5*SZ_X)
#define O_W    (6*SZ_X)
#define O_QH   (O_W + 8*SZ_W)
#define O_QL   (O_QH + 1*SZ_HS)
#define O_KH   (O_QH + 2*SZ_HS)
#define O_KL   (O_QH + 3*SZ_HS)
#define O_VH   (O_QH + 4*SZ_HS)         // V^T: [B,H,dk,S]
#define O_VL   (O_QH + 5*SZ_HS)
#define O_AOH  (O_QH + 6*SZ_HS)
#define O_AOL  (O_AOH + SZ_X)
#define O_PSUM (O_AOL + SZ_X)           // [BHN*SS][8] fp32
#define ARENA  (O_PSUM + (size_t)BHN*SS*8*4)

__device__ __align__(1024) char g_buf[ARENA];

// ---------------- helpers ----------------------------------------------------
#define SWZ(o) ((o) ^ (((o) >> 3) & 0x70))

__device__ __forceinline__ uint32_t s2u(const void* p) {
    uint32_t a;
    asm("{ .reg .u64 t; cvta.to.shared.u64 t, %1; cvt.u32.u64 %0, t; }" : "=r"(a) : "l"(p));
    return a;
}
__device__ __forceinline__ void ldsm4(uint32_t* r, uint32_t a) {
    asm volatile("ldmatrix.sync.aligned.m8n8.x4.shared.b16 {%0,%1,%2,%3}, [%4];"
                 : "=r"(r[0]), "=r"(r[1]), "=r"(r[2]), "=r"(r[3]) : "r"(a));
}
__device__ __forceinline__ void hmma(float* c, const uint32_t* a, const uint32_t* b) {
    asm volatile("mma.sync.aligned.m16n8k16.row.col.f32.bf16.bf16.f32 "
                 "{%0,%1,%2,%3}, {%4,%5,%6,%7}, {%8,%9}, {%0,%1,%2,%3};"
                 : "+f"(c[0]), "+f"(c[1]), "+f"(c[2]), "+f"(c[3])
                 : "r"(a[0]), "r"(a[1]), "r"(a[2]), "r"(a[3]), "r"(b[0]), "r"(b[1]));
}
__device__ __forceinline__ uint32_t a_addr(uint32_t sbase, int rowBase, int kb, int lane) {
    int m = rowBase + (lane & 7) + ((lane >> 3) & 1) * 8;
    int kk = kb + (lane >> 4) * 8;
    return sbase + SWZ((uint32_t)(m * 128 + kk * 2));
}
// x4 B load: two n8 blocks (colBase.., colBase+8..) x k16
__device__ __forceinline__ uint32_t b_addr4(uint32_t sbase, int colBase, int kb, int lane) {
    int n = colBase + (lane & 7) + ((lane >> 4) & 1) * 8;
    int kk = kb + ((lane >> 3) & 1) * 8;
    return sbase + SWZ((uint32_t)(n * 128 + kk * 2));
}
__device__ __forceinline__ void cpasync16(uint32_t dst, const void* src) {
    asm volatile("cp.async.cg.shared.global [%0], [%1], 16;" :: "r"(dst), "l"(src));
}
#define CP_COMMIT() asm volatile("cp.async.commit_group;" ::: "memory")
#define CP_WAIT0()  asm volatile("cp.async.wait_group 0;" ::: "memory")
#define CP_WAIT1()  asm volatile("cp.async.wait_group 1;" ::: "memory")

__device__ __forceinline__ void tile_async(uint32_t dst, const bf16* __restrict__ src,
                                           int ld, int rows, int tid) {
    const int units = rows * 8;
    for (int u = tid; u < units; u += 256) {
        int r = u >> 3, j = u & 7;
        cpasync16(dst + SWZ((uint32_t)(r * 128 + j * 16)), src + (size_t)r * ld + j * 8);
    }
}
__device__ __forceinline__ uint32_t pk2(bf16 a, bf16 b) {
    bf162 t; t.x = a; t.y = b; return *reinterpret_cast<uint32_t*>(&t);
}
__device__ __forceinline__ void splitf(float f, bf16& h, bf16& l) {
    h = __float2bfloat16(f);
    l = __float2bfloat16(f - __bfloat162float(h));
}

// Shared mainloop: A 128x64 hi/lo, B 64x64 hi/lo (swizzled) -> c[2][4][4]
__device__ __forceinline__ void mma_stage(uint32_t ahb, uint32_t alb, uint32_t bhb, uint32_t blb,
                                          int wr, int wc, int lane, float (&c)[2][4][4]) {
    #pragma unroll
    for (int ks = 0; ks < 4; ks++) {
        uint32_t fah[2][4], fal[2][4], fbh[2][4], fbl[2][4];
        #pragma unroll
        for (int mf = 0; mf < 2; mf++) {
            ldsm4(fah[mf], a_addr(ahb, wr * 32 + mf * 16, ks * 16, lane));
            ldsm4(fal[mf], a_addr(alb, wr * 32 + mf * 16, ks * 16, lane));
        }
        #pragma unroll
        for (int g = 0; g < 2; g++) {
            ldsm4(fbh[g], b_addr4(bhb, wc * 32 + g * 16, ks * 16, lane));
            ldsm4(fbl[g], b_addr4(blb, wc * 32 + g * 16, ks * 16, lane));
        }
        #pragma unroll
        for (int mf = 0; mf < 2; mf++)
            #pragma unroll
            for (int nf = 0; nf < 4; nf++) {
                const uint32_t* bh_ = &fbh[nf >> 1][(nf & 1) * 2];
                const uint32_t* bl_ = &fbl[nf >> 1][(nf & 1) * 2];
                hmma(c[mf][nf], fah[mf], bh_);
                hmma(c[mf][nf], fah[mf], bl_);
                hmma(c[mf][nf], fal[mf], bh_);
            }
    }
}

// ---------------- merged pre-split kernels ----------------------------------
__global__ __launch_bounds__(256) void split3(
    const float* __restrict__ q, const float* __restrict__ k, const float* __restrict__ v) {
    const int n4 = NT * DM / 4;
    int i = blockIdx.x * 256 + threadIdx.x;
    if (i >= n4) return;
    int sel = blockIdx.y;
    const float* x = sel == 0 ? q : sel == 1 ? k : v;
    bf16* hi = (bf16*)(g_buf + (size_t)(2 * sel) * SZ_X);
    bf16* lo = (bf16*)(g_buf + (size_t)(2 * sel + 1) * SZ_X);
    float4 f = reinterpret_cast<const float4*>(x)[i];
    bf16 h0, h1, h2, h3, l0, l1, l2, l3;
    splitf(f.x, h0, l0); splitf(f.y, h1, l1);
    splitf(f.z, h2, l2); splitf(f.w, h3, l3);
    uint2 hv = { pk2(h0, h1), pk2(h2, h3) };
    uint2 lv = { pk2(l0, l1), pk2(l2, l3) };
    reinterpret_cast<uint2*>(hi)[i] = hv;
    reinterpret_cast<uint2*>(lo)[i] = lv;
}
__global__ __launch_bounds__(256) void wsplit4(
    const float* __restrict__ Wq, const float* __restrict__ Wk,
    const float* __restrict__ Wv, const float* __restrict__ Wo) {
    int idx = blockIdx.x * 256 + threadIdx.x;
    if (idx >= DM * DM) return;
    int sel = blockIdx.y;
    const float* W = sel == 0 ? Wq : sel == 1 ? Wk : sel == 2 ? Wv : Wo;
    bf16* th = (bf16*)(g_buf + O_W) + (size_t)sel * 2 * (DM * DM);
    bf16* tl = th + DM * DM;
    int n = idx / DM, k = idx % DM;
    bf16 h, l; splitf(W[(size_t)k * DM + n], h, l);
    th[idx] = h; tl[idx] = l;
}

// ---------------- merged QKV projection (grid.z = sel) -----------------------
#define G_ST 49152
#define SM_G 98304

__global__ __launch_bounds__(256, 2) void qkv_mma(
    const float* __restrict__ bq, const float* __restrict__ bk, const float* __restrict__ bv)
{
    extern __shared__ char smem[];
    const uint32_t sb = s2u(smem);
    const int tid = threadIdx.x, wid = tid >> 5, lane = tid & 31;
    const int wr = wid >> 1, wc = wid & 1;
    const int sel = blockIdx.z;
    const int mBase = blockIdx.y * 128, nBase = blockIdx.x * 64;
    const int NK = DM / 64;

    const bf16* Ahi = (const bf16*)(g_buf + (size_t)(2 * sel) * SZ_X);
    const bf16* Alo = (const bf16*)(g_buf + (size_t)(2 * sel + 1) * SZ_X);
    const bf16* Bhi = (const bf16*)(g_buf + O_W) + (size_t)sel * 2 * (DM * DM);
    const bf16* Blo = Bhi + DM * DM;
    const float* bias = sel == 0 ? bq : sel == 1 ? bk : bv;
    bf16* Ohi = (bf16*)(g_buf + O_QH + (size_t)(2 * sel) * SZ_HS);
    bf16* Olo = (bf16*)(g_buf + O_QH + (size_t)(2 * sel + 1) * SZ_HS);

    float c[2][4][4];
    #pragma unroll
    for (int i = 0; i < 2; i++)
        #pragma unroll
        for (int j = 0; j < 4; j++)
            #pragma unroll
            for (int q = 0; q < 4; q++) c[i][j][q] = 0.f;

    tile_async(sb + 0,     Ahi + (size_t)mBase * DM, DM, 128, tid);
    tile_async(sb + 16384, Alo + (size_t)mBase * DM, DM, 128, tid);
    tile_async(sb + 32768, Bhi + (size_t)nBase * DM, DM, 64, tid);
    tile_async(sb + 40960, Blo + (size_t)nBase * DM, DM, 64, tid);
    CP_COMMIT();

    #pragma unroll 1
    for (int kc = 0; kc < NK; kc++) {
        if (kc + 1 < NK) {
            uint32_t st = ((kc + 1) & 1) * G_ST;
            tile_async(sb + st + 0,     Ahi + (size_t)mBase * DM + (kc + 1) * 64, DM, 128, tid);
            tile_async(sb + st + 16384, Alo + (size_t)mBase * DM + (kc + 1) * 64, DM, 128, tid);
            tile_async(sb + st + 32768, Bhi + (size_t)nBase * DM + (kc + 1) * 64, DM, 64, tid);
            tile_async(sb + st + 40960, Blo + (size_t)nBase * DM + (kc + 1) * 64, DM, 64, tid);
            CP_COMMIT();
            CP_WAIT1();
        } else {
            CP_WAIT0();
        }
        __syncthreads();
        uint32_t st = (kc & 1) * G_ST;
        mma_stage(sb + st, sb + st + 16384, sb + st + 32768, sb + st + 40960, wr, wc, lane, c);
        __syncthreads();
    }

    const int gid = lane >> 2, tig = lane & 3;
    #pragma unroll
    for (int mf = 0; mf < 2; mf++)
        #pragma unroll
        for (int nf = 0; nf < 4; nf++) {
            int row0 = mBase + wr * 32 + mf * 16 + gid;
            int col  = nBase + wc * 32 + nf * 8 + tig * 2;
            float v0 = c[mf][nf][0] + bias[col];
            float v1 = c[mf][nf][1] + bias[col + 1];
            float v2 = c[mf][nf][2] + bias[col];
            float v3 = c[mf][nf][3] + bias[col + 1];
            int h = col >> 6, kk = col & 63;
            if (sel < 2) {
                #pragma unroll
                for (int rr = 0; rr < 2; rr++) {
                    int m = row0 + rr * 8;
                    int b = m >> 11, s = m & 2047;
                    float f0 = rr ? v2 : v0, f1 = rr ? v3 : v1;
                    bf16 h0, h1, l0, l1;
                    splitf(f0, h0, l0); splitf(f1, h1, l1);
                    size_t dst = (((size_t)b * NH + h) * SS + s) * DK + kk;
                    *reinterpret_cast<uint32_t*>(&Ohi[dst]) = pk2(h0, h1);
                    *reinterpret_cast<uint32_t*>(&Olo[dst]) = pk2(l0, l1);
                }
            } else {
                #pragma unroll
                for (int rr = 0; rr < 2; rr++) {
                    int m = row0 + rr * 8;
                    int b = m >> 11, s = m & 2047;
                    float f0 = rr ? v2 : v0, f1 = rr ? v3 : v1;
                    bf16 hh, ll;
                    size_t dst0 = (((size_t)b * NH + h) * DK + kk) * SS + s;
                    splitf(f0, hh, ll); Ohi[dst0] = hh; Olo[dst0] = ll;
                    size_t dst1 = (((size_t)b * NH + h) * DK + kk + 1) * SS + s;
                    splitf(f1, hh, ll); Ohi[dst1] = hh; Olo[dst1] = ll;
                }
            }
        }
}

// ---------------- output projection (fp32 epilogue) --------------------------
__global__ __launch_bounds__(256, 2) void oproj_mma(
    const bf16* __restrict__ Ahi, const bf16* __restrict__ Alo,
    const bf16* __restrict__ Bhi, const bf16* __restrict__ Blo,
    const float* __restrict__ bias, float* __restrict__ Cf)
{
    extern __shared__ char smem[];
    const uint32_t sb = s2u(smem);
    const int tid = threadIdx.x, wid = tid >> 5, lane = tid & 31;
    const int wr = wid >> 1, wc = wid & 1;
    const int mBase = blockIdx.y * 128, nBase = blockIdx.x * 64;
    const int NK = DM / 64;

    float c[2][4][4];
    #pragma unroll
    for (int i = 0; i < 2; i++)
        #pragma unroll
        for (int j = 0; j < 4; j++)
            #pragma unroll
            for (int q = 0; q < 4; q++) c[i][j][q] = 0.f;

    tile_async(sb + 0,     Ahi + (size_t)mBase * DM, DM, 128, tid);
    tile_async(sb + 16384, Alo + (size_t)mBase * DM, DM, 128, tid);
    tile_async(sb + 32768, Bhi + (size_t)nBase * DM, DM, 64, tid);
    tile_async(sb + 40960, Blo + (size_t)nBase * DM, DM, 64, tid);
    CP_COMMIT();

    #pragma unroll 1
    for (int kc = 0; kc < NK; kc++) {
        if (kc + 1 < NK) {
            uint32_t st = ((kc + 1) & 1) * G_ST;
            tile_async(sb + st + 0,     Ahi + (size_t)mBase * DM + (kc + 1) * 64, DM, 128, tid);
            tile_async(sb + st + 16384, Alo + (size_t)mBase * DM + (kc + 1) * 64, DM, 128, tid);
            tile_async(sb + st + 32768, Bhi + (size_t)nBase * DM + (kc + 1) * 64, DM, 64, tid);
            tile_async(sb + st + 40960, Blo + (size_t)nBase * DM + (kc + 1) * 64, DM, 64, tid);
            CP_COMMIT();
            CP_WAIT1();
        } else {
            CP_WAIT0();
        }
        __syncthreads();
        uint32_t st = (kc & 1) * G_ST;
        mma_stage(sb + st, sb + st + 16384, sb + st + 32768, sb + st + 40960, wr, wc, lane, c);
        __syncthreads();
    }

    const int gid = lane >> 2, tig = lane & 3;
    #pragma unroll
    for (int mf = 0; mf < 2; mf++)
        #pragma unroll
        for (int nf = 0; nf < 4; nf++) {
            int row0 = mBase + wr * 32 + mf * 16 + gid;
            int col  = nBase + wc * 32 + nf * 8 + tig * 2;
            float v0 = c[mf][nf][0] + bias[col];
            float v1 = c[mf][nf][1] + bias[col + 1];
            float v2 = c[mf][nf][2] + bias[col];
            float v3 = c[mf][nf][3] + bias[col + 1];
            *reinterpret_cast<float2*>(&Cf[(size_t)row0 * DM + col])       = make_float2(v0, v1);
            *reinterpret_cast<float2*>(&Cf[(size_t)(row0 + 8) * DM + col]) = make_float2(v2, v3);
        }
}

// ---------------- scores: Q-resident, 4 K-chunks, exp + row sums -------------
#define SC_K(st) (32768 + (st) * 16384)
#define SM_S 66560

__global__ __launch_bounds__(256, 2) void scores_mma(
    float* __restrict__ attn, float* __restrict__ psum)
{
    extern __shared__ char smem[];
    const uint32_t sb = s2u(smem);
    float (*rowpart)[128] = reinterpret_cast<float(*)[128]>(smem + 65536);
    const int tid = threadIdx.x, wid = tid >> 5, lane = tid & 31;
    const int wr = wid >> 1, wc = wid & 1;
    const int bh = blockIdx.z, qBase = blockIdx.y * 128, kBase0 = blockIdx.x * 256;

    const bf16* Qh = (const bf16*)(g_buf + O_QH);
    const bf16* Ql = (const bf16*)(g_buf + O_QL);
    const bf16* Kh = (const bf16*)(g_buf + O_KH);
    const bf16* Kl = (const bf16*)(g_buf + O_KL);

    tile_async(sb + 0,     Qh + ((size_t)bh * SS + qBase) * DK, DK, 128, tid);
    tile_async(sb + 16384, Ql + ((size_t)bh * SS + qBase) * DK, DK, 128, tid);
    tile_async(sb + SC_K(0),        Kh + ((size_t)bh * SS + kBase0) * DK, DK, 64, tid);
    tile_async(sb + SC_K(0) + 8192, Kl + ((size_t)bh * SS + kBase0) * DK, DK, 64, tid);
    CP_COMMIT();
    tile_async(sb + SC_K(1),        Kh + ((size_t)bh * SS + kBase0 + 64) * DK, DK, 64, tid);
    tile_async(sb + SC_K(1) + 8192, Kl + ((size_t)bh * SS + kBase0 + 64) * DK, DK, 64, tid);
    CP_COMMIT();

    const int gid = lane >> 2, tig = lane & 3;
    float pacc[2][2] = {{0.f, 0.f}, {0.f, 0.f}};

    #pragma unroll 1
    for (int kc = 0; kc < 4; kc++) {
        const int st = kc & 1;
        if (kc < 3) { CP_WAIT1(); } else { CP_WAIT0(); }
        __syncthreads();

        float c[2][4][4];
        #pragma unroll
        for (int i = 0; i < 2; i++)
            #pragma unroll
            for (int j = 0; j < 4; j++)
                #pragma unroll
                for (int q = 0; q < 4; q++) c[i][j][q] = 0.f;

        mma_stage(sb, sb + 16384, sb + SC_K(st), sb + SC_K(st) + 8192, wr, wc, lane, c);
        __syncthreads();
        if (kc + 2 < 4) {
            tile_async(sb + SC_K(st),        Kh + ((size_t)bh * SS + kBase0 + (kc + 2) * 64) * DK, DK, 64, tid);
            tile_async(sb + SC_K(st) + 8192, Kl + ((size_t)bh * SS + kBase0 + (kc + 2) * 64) * DK, DK, 64, tid);
            CP_COMMIT();
        }

        #pragma unroll
        for (int mf = 0; mf < 2; mf++) {
            int rloc0 = wr * 32 + mf * 16 + gid;
            float* arow0 = attn + ((size_t)bh * SS + qBase + rloc0) * SS;
            float* arow1 = arow0 + (size_t)8 * SS;
            #pragma unroll
            for (int nf = 0; nf < 4; nf++) {
                int col = kBase0 + kc * 64 + wc * 32 + nf * 8 + tig * 2;
                float e0 = __expf(c[mf][nf][0] * 0.125f);
                float e1 = __expf(c[mf][nf][1] * 0.125f);
                float e2 = __expf(c[mf][nf][2] * 0.125f);
                float e3 = __expf(c[mf][nf][3] * 0.125f);
                pacc[mf][0] += e0 + e1; pacc[mf][1] += e2 + e3;
                *reinterpret_cast<float2*>(arow0 + col) = make_float2(e0, e1);
                *reinterpret_cast<float2*>(arow1 + col) = make_float2(e2, e3);
            }
        }
    }

    #pragma unroll
    for (int mf = 0; mf < 2; mf++) {
        float p0 = pacc[mf][0], p1 = pacc[mf][1];
        p0 += __shfl_xor_sync(0xffffffffu, p0, 1); p0 += __shfl_xor_sync(0xffffffffu, p0, 2);
        p1 += __shfl_xor_sync(0xffffffffu, p1, 1); p1 += __shfl_xor_sync(0xffffffffu, p1, 2);
        if (tig == 0) {
            int rloc0 = wr * 32 + mf * 16 + gid;
            rowpart[wc][rloc0]     = p0;
            rowpart[wc][rloc0 + 8] = p1;
        }
    }
    __syncthreads();
    if (tid < 128) {
        float s = rowpart[0][tid] + rowpart[1][tid];
        psum[((size_t)bh * SS + qBase + tid) * 8 + blockIdx.x] = s;
    }
}

// ---------------- pv: deep-pipelined normalize + attn write + P.V ------------
// smem: P ring-2 @0 (2x32K: hi s*32768, lo +16384), V ring-4 @65536 (4x16K),
//       E ring-3 @131072 (3x32K, custom granule swizzle), rowinv @229376.
#define PV_P(s)  ((uint32_t)(s) * 32768u)
#define PV_V4(s) (65536u + (uint32_t)(s) * 16384u)
#define PV_E(s)  (131072u + (uint32_t)(s) * 32768u)
#define PV_RI    229376u
#define SM_PV    229888

__global__ __launch_bounds__(256, 1) void pv_mma(
    float* __restrict__ attn, const float* __restrict__ psum)
{
    extern __shared__ char smem[];
    const uint32_t sb = s2u(smem);
    float* rowinv = reinterpret_cast<float*>(smem + PV_RI);
    const int tid = threadIdx.x, wid = tid >> 5, lane = tid & 31;
    const int wr = wid >> 1, wc = wid & 1;
    const int bh = blockIdx.y, b = bh / NH, h = bh % NH;
    const int qBase = blockIdx.x * 128;

    const bf16* Vh = (const bf16*)(g_buf + O_VH);
    const bf16* Vl = (const bf16*)(g_buf + O_VL);
    bf16* AOh = (bf16*)(g_buf + O_AOH);
    bf16* AOl = (bf16*)(g_buf + O_AOL);
    float* arow0 = attn + ((size_t)bh * SS + qBase) * SS;
    const size_t vbase = (size_t)bh * DK * SS;

    if (tid < 128) {
        const float* pp = psum + ((size_t)bh * SS + qBase + tid) * 8;
        float s = 0.f;
        #pragma unroll
        for (int i = 0; i < 8; i++) s += pp[i];
        rowinv[tid] = 1.0f / s;
    }

    float c[2][4][4];
    #pragma unroll
    for (int i = 0; i < 2; i++)
        #pragma unroll
        for (int j = 0; j < 4; j++)
            #pragma unroll
            for (int q = 0; q < 4; q++) c[i][j][q] = 0.f;

    // prologue: groups 0,1 (E + V each)
    #pragma unroll
    for (int g = 0; g < 2; g++) {
        uint32_t eb = PV_E(g % 3);
        for (int u = tid; u < 2048; u += 256) {
            int r = u >> 4, ch = u & 15;
            cpasync16(sb + eb + (uint32_t)(r * 256) + (uint32_t)((ch ^ (r & 15)) << 4),
                      arow0 + (size_t)r * SS + g * 64 + ch * 4);
        }
        uint32_t vb = PV_V4(g & 3);
        tile_async(sb + vb,        Vh + vbase + g * 64, SS, 64, tid);
        tile_async(sb + vb + 8192, Vl + vbase + g * 64, SS, 64, tid);
        CP_COMMIT();
    }

    #pragma unroll 1
    for (int kc = 0; kc <= 32; kc++) {
        if (kc < 31) { CP_WAIT1(); } else if (kc == 31) { CP_WAIT0(); }
        __syncthreads();
        if (kc < 32) {
            // normalize chunk kc from E smem -> write final attn + split into P(kc&1)
            int r = tid >> 1, half = tid & 1;
            float inv = rowinv[r];
            uint32_t eb = sb + PV_E(kc % 3) + (uint32_t)(r * 256);
            uint32_t pb = sb + PV_P(kc & 1);
            float* gp = arow0 + (size_t)r * SS + kc * 64 + half * 32;
            int rx = r & 15;
            #pragma unroll
            for (int j = 0; j < 8; j++) {
                int chunk = half * 8 + j;
                float4 e;
                asm volatile("ld.shared.v4.f32 {%0,%1,%2,%3}, [%4];"
                             : "=f"(e.x), "=f"(e.y), "=f"(e.z), "=f"(e.w)
                             : "r"(eb + (uint32_t)((chunk ^ rx) << 4)));
                float p0 = e.x * inv, p1 = e.y * inv, p2 = e.z * inv, p3 = e.w * inv;
                __stcs(reinterpret_cast<float4*>(gp + j * 4), make_float4(p0, p1, p2, p3));
                bf16 h0, h1, l0, l1;
                uint32_t off0 = SWZ((uint32_t)(r * 128 + (half * 32 + j * 4) * 2));
                splitf(p0, h0, l0); splitf(p1, h1, l1);
                asm volatile("st.shared.b32 [%0], %1;" :: "r"(pb + off0), "r"(pk2(h0, h1)) : "memory");
                asm volatile("st.shared.b32 [%0], %1;" :: "r"(pb + 16384 + off0), "r"(pk2(l0, l1)) : "memory");
                splitf(p2, h0, l0); splitf(p3, h1, l1);
                asm volatile("st.shared.b32 [%0], %1;" :: "r"(pb + off0 + 4), "r"(pk2(h0, h1)) : "memory");
                asm volatile("st.shared.b32 [%0], %1;" :: "r"(pb + 16384 + off0 + 4), "r"(pk2(l0, l1)) : "memory");
            }
            if (kc + 2 < 32) {
                int g = kc + 2;
                uint32_t ebn = PV_E(g % 3);
                for (int u = tid; u < 2048; u += 256) {
                    int rr = u >> 4, ch = u & 15;
                    cpasync16(sb + ebn + (uint32_t)(rr * 256) + (uint32_t)((ch ^ (rr & 15)) << 4),
                              arow0 + (size_t)rr * SS + g * 64 + ch * 4);
                }
                uint32_t vb = PV_V4(g & 3);
                tile_async(sb + vb,        Vh + vbase + g * 64, SS, 64, tid);
                tile_async(sb + vb + 8192, Vl + vbase + g * 64, SS, 64, tid);
                CP_COMMIT();
            }
        }
        if (kc >= 1) {
            int m = kc - 1;
            uint32_t pb = sb + PV_P(m & 1);
            uint32_t vb = sb + PV_V4(m & 3);
            mma_stage(pb, pb + 16384, vb, vb + 8192, wr, wc, lane, c);
        }
    }

    const int gid = lane >> 2, tig = lane & 3;
    #pragma unroll
    for (int mf = 0; mf < 2; mf++)
        #pragma unroll
        for (int nf = 0; nf < 4; nf++) {
            int rloc = wr * 32 + mf * 16 + gid;
            int col  = wc * 32 + nf * 8 + tig * 2;
            #pragma unroll
            for (int rr = 0; rr < 2; rr++) {
                int s = qBase + rloc + rr * 8;
                float f0 = c[mf][nf][rr * 2 + 0], f1 = c[mf][nf][rr * 2 + 1];
                bf16 h0, h1, l0, l1;
                splitf(f0, h0, l0); splitf(f1, h1, l1);
                size_t dst = ((size_t)b * SS + s) * DM + h * DK + col;
                *reinterpret_cast<uint32_t*>(&AOh[dst]) = pk2(h0, h1);
                *reinterpret_cast<uint32_t*>(&AOl[dst]) = pk2(l0, l1);
            }
        }
}

// ---------------------------------------------------------------------------
extern "C" void kernel_launch(void* const* d_in, const int* in_sizes, int n_in,
                              void* d_out, int out_size)
{
    (void)in_sizes; (void)n_in; (void)out_size;
    const float* q  = (const float*)d_in[0];
    const float* k  = (const float*)d_in[1];
    const float* v  = (const float*)d_in[2];
    const float* Wq = (const float*)d_in[3];
    const float* bq = (const float*)d_in[4];
    const float* Wk = (const float*)d_in[5];
    const float* bk = (const float*)d_in[6];
    const float* Wv = (const float*)d_in[7];
    const float* bv = (const float*)d_in[8];
    const float* Wo = (const float*)d_in[9];
    const float* bo = (const float*)d_in[10];

    float* out  = (float*)d_out;
    float* attn = out + (size_t)NT * DM;

    char* base = nullptr;
    cudaGetSymbolAddress((void**)&base, g_buf);
    bf16* wb  = (bf16*)(base + O_W);
    bf16* woh = wb + 6*(size_t)DM*DM; bf16* wol = wb + 7*(size_t)DM*DM;
    bf16* AOh = (bf16*)(base + O_AOH); bf16* AOl = (bf16*)(base + O_AOL);
    float* psum = (float*)(base + O_PSUM);

    cudaFuncSetAttribute(qkv_mma,    cudaFuncAttributeMaxDynamicSharedMemorySize, SM_G);
    cudaFuncSetAttribute(oproj_mma,  cudaFuncAttributeMaxDynamicSharedMemorySize, SM_G);
    cudaFuncSetAttribute(scores_mma, cudaFuncAttributeMaxDynamicSharedMemorySize, SM_S);
    cudaFuncSetAttribute(pv_mma,     cudaFuncAttributeMaxDynamicSharedMemorySize, SM_PV);

    const int n4 = NT * DM / 4;
    split3<<<dim3((n4 + 255) / 256, 3), 256>>>(q, k, v);
    wsplit4<<<dim3((DM * DM + 255) / 256, 4), 256>>>(Wq, Wk, Wv, Wo);

    dim3 gProj(DM / 64, NT / 128, 3);  // 12 x 64 x 3
    qkv_mma<<<gProj, 256, SM_G>>>(bq, bk, bv);

    dim3 gS(SS / 256, SS / 128, BHN);  // 8 x 16 x 48
    scores_mma<<<gS, 256, SM_S>>>(attn, psum);

    dim3 gPV(SS / 128, BHN);           // 16 x 48
    pv_mma<<<gPV, 256, SM_PV>>>(attn, psum);

    dim3 gO(DM / 64, NT / 128);        // 12 x 64
    oproj_mma<<<gO, 256, SM_G>>>(AOh, AOl, woh, wol, bo, out);
}

// round 15
// speedup vs baseline: 3.7488x; 1.0355x over previous
#include <cuda_runtime.h>
#include <cuda_bf16.h>
#include <stdint.h>
#include <math.h>

#define BB 4
#define SS 2048
#define DM 768
#define NH 12
#define DK 64
#define NT (BB*SS)
#define BHN (BB*NH)

typedef __nv_bfloat16 bf16;
typedef __nv_bfloat162 bf162;

// ---------------- scratch arena ---------------------------------------------
#define SZ_X   ((size_t)NT*DM*2)
#define SZ_W   ((size_t)DM*DM*2)
#define SZ_HS  ((size_t)BHN*SS*DK*2)
#define SZ_E   ((size_t)BHN*SS*SS*2)    // one bf16 E plane: 402 MB
#define O_XQH  (0*SZ_X)
#define O_XQL  (1*SZ_X)
#define O_XKH  (2*SZ_X)
#define O_XKL  (3*SZ_X)
#define O_XVH  (4*SZ_X)
#define O_XVL  (5*SZ_X)
#define O_W    (6*SZ_X)
#define O_QH   (O_W + 8*SZ_W)
#define O_QL   (O_QH + 1*SZ_HS)
#define O_KH   (O_QH + 2*SZ_HS)
#define O_KL   (O_QH + 3*SZ_HS)
#define O_VH   (O_QH + 4*SZ_HS)         // V^T: [B,H,dk,S]
#define O_VL   (O_QH + 5*SZ_HS)
#define O_AOH  (O_QH + 6*SZ_HS)
#define O_AOL  (O_AOH + SZ_X)
#define O_PSUM (O_AOL + SZ_X)           // [BHN*SS][8] fp32
#define O_EH   (O_PSUM + (size_t)BHN*SS*8*4)
#define O_EL   (O_EH + SZ_E)
#define ARENA  (O_EL + SZ_E)

__device__ __align__(1024) char g_buf[ARENA];

// ---------------- helpers ----------------------------------------------------
#define SWZ(o) ((o) ^ (((o) >> 3) & 0x70))

__device__ __forceinline__ uint32_t s2u(const void* p) {
    uint32_t a;
    asm("{ .reg .u64 t; cvta.to.shared.u64 t, %1; cvt.u32.u64 %0, t; }" : "=r"(a) : "l"(p));
    return a;
}
__device__ __forceinline__ void ldsm4(uint32_t* r, uint32_t a) {
    asm volatile("ldmatrix.sync.aligned.m8n8.x4.shared.b16 {%0,%1,%2,%3}, [%4];"
                 : "=r"(r[0]), "=r"(r[1]), "=r"(r[2]), "=r"(r[3]) : "r"(a));
}
__device__ __forceinline__ void hmma(float* c, const uint32_t* a, const uint32_t* b) {
    asm volatile("mma.sync.aligned.m16n8k16.row.col.f32.bf16.bf16.f32 "
                 "{%0,%1,%2,%3}, {%4,%5,%6,%7}, {%8,%9}, {%0,%1,%2,%3};"
                 : "+f"(c[0]), "+f"(c[1]), "+f"(c[2]), "+f"(c[3])
                 : "r"(a[0]), "r"(a[1]), "r"(a[2]), "r"(a[3]), "r"(b[0]), "r"(b[1]));
}
__device__ __forceinline__ uint32_t a_addr(uint32_t sbase, int rowBase, int kb, int lane) {
    int m = rowBase + (lane & 7) + ((lane >> 3) & 1) * 8;
    int kk = kb + (lane >> 4) * 8;
    return sbase + SWZ((uint32_t)(m * 128 + kk * 2));
}
__device__ __forceinline__ uint32_t b_addr4(uint32_t sbase, int colBase, int kb, int lane) {
    int n = colBase + (lane & 7) + ((lane >> 4) & 1) * 8;
    int kk = kb + ((lane >> 3) & 1) * 8;
    return sbase + SWZ((uint32_t)(n * 128 + kk * 2));
}
__device__ __forceinline__ void cpasync16(uint32_t dst, const void* src) {
    asm volatile("cp.async.cg.shared.global [%0], [%1], 16;" :: "r"(dst), "l"(src));
}
#define CP_COMMIT() asm volatile("cp.async.commit_group;" ::: "memory")
#define CP_WAIT0()  asm volatile("cp.async.wait_group 0;" ::: "memory")
#define CP_WAIT1()  asm volatile("cp.async.wait_group 1;" ::: "memory")

__device__ __forceinline__ void tile_async(uint32_t dst, const bf16* __restrict__ src,
                                           int ld, int rows, int tid) {
    const int units = rows * 8;
    for (int u = tid; u < units; u += 256) {
        int r = u >> 3, j = u & 7;
        cpasync16(dst + SWZ((uint32_t)(r * 128 + j * 16)), src + (size_t)r * ld + j * 8);
    }
}
__device__ __forceinline__ uint32_t pk2(bf16 a, bf16 b) {
    bf162 t; t.x = a; t.y = b; return *reinterpret_cast<uint32_t*>(&t);
}
__device__ __forceinline__ void splitf(float f, bf16& h, bf16& l) {
    h = __float2bfloat16(f);
    l = __float2bfloat16(f - __bfloat162float(h));
}

// Shared mainloop: A 128x64 hi/lo, B 64x64 hi/lo (swizzled) -> c[2][4][4]
__device__ __forceinline__ void mma_stage(uint32_t ahb, uint32_t alb, uint32_t bhb, uint32_t blb,
                                          int wr, int wc, int lane, float (&c)[2][4][4]) {
    #pragma unroll
    for (int ks = 0; ks < 4; ks++) {
        uint32_t fah[2][4], fal[2][4], fbh[2][4], fbl[2][4];
        #pragma unroll
        for (int mf = 0; mf < 2; mf++) {
            ldsm4(fah[mf], a_addr(ahb, wr * 32 + mf * 16, ks * 16, lane));
            ldsm4(fal[mf], a_addr(alb, wr * 32 + mf * 16, ks * 16, lane));
        }
        #pragma unroll
        for (int g = 0; g < 2; g++) {
            ldsm4(fbh[g], b_addr4(bhb, wc * 32 + g * 16, ks * 16, lane));
            ldsm4(fbl[g], b_addr4(blb, wc * 32 + g * 16, ks * 16, lane));
        }
        #pragma unroll
        for (int mf = 0; mf < 2; mf++)
            #pragma unroll
            for (int nf = 0; nf < 4; nf++) {
                const uint32_t* bh_ = &fbh[nf >> 1][(nf & 1) * 2];
                const uint32_t* bl_ = &fbl[nf >> 1][(nf & 1) * 2];
                hmma(c[mf][nf], fah[mf], bh_);
                hmma(c[mf][nf], fah[mf], bl_);
                hmma(c[mf][nf], fal[mf], bh_);
            }
    }
}

// ---------------- merged pre-split kernels ----------------------------------
__global__ __launch_bounds__(256) void split3(
    const float* __restrict__ q, const float* __restrict__ k, const float* __restrict__ v) {
    const int n4 = NT * DM / 4;
    int i = blockIdx.x * 256 + threadIdx.x;
    if (i >= n4) return;
    int sel = blockIdx.y;
    const float* x = sel == 0 ? q : sel == 1 ? k : v;
    bf16* hi = (bf16*)(g_buf + (size_t)(2 * sel) * SZ_X);
    bf16* lo = (bf16*)(g_buf + (size_t)(2 * sel + 1) * SZ_X);
    float4 f = reinterpret_cast<const float4*>(x)[i];
    bf16 h0, h1, h2, h3, l0, l1, l2, l3;
    splitf(f.x, h0, l0); splitf(f.y, h1, l1);
    splitf(f.z, h2, l2); splitf(f.w, h3, l3);
    uint2 hv = { pk2(h0, h1), pk2(h2, h3) };
    uint2 lv = { pk2(l0, l1), pk2(l2, l3) };
    reinterpret_cast<uint2*>(hi)[i] = hv;
    reinterpret_cast<uint2*>(lo)[i] = lv;
}
__global__ __launch_bounds__(256) void wsplit4(
    const float* __restrict__ Wq, const float* __restrict__ Wk,
    const float* __restrict__ Wv, const float* __restrict__ Wo) {
    int idx = blockIdx.x * 256 + threadIdx.x;
    if (idx >= DM * DM) return;
    int sel = blockIdx.y;
    const float* W = sel == 0 ? Wq : sel == 1 ? Wk : sel == 2 ? Wv : Wo;
    bf16* th = (bf16*)(g_buf + O_W) + (size_t)sel * 2 * (DM * DM);
    bf16* tl = th + DM * DM;
    int n = idx / DM, k = idx % DM;
    bf16 h, l; splitf(W[(size_t)k * DM + n], h, l);
    th[idx] = h; tl[idx] = l;
}

// ---------------- merged QKV projection (grid.z = sel) -----------------------
#define G_ST 49152
#define SM_G 98304

__global__ __launch_bounds__(256, 2) void qkv_mma(
    const float* __restrict__ bq, const float* __restrict__ bk, const float* __restrict__ bv)
{
    extern __shared__ char smem[];
    const uint32_t sb = s2u(smem);
    const int tid = threadIdx.x, wid = tid >> 5, lane = tid & 31;
    const int wr = wid >> 1, wc = wid & 1;
    const int sel = blockIdx.z;
    const int mBase = blockIdx.y * 128, nBase = blockIdx.x * 64;
    const int NK = DM / 64;

    const bf16* Ahi = (const bf16*)(g_buf + (size_t)(2 * sel) * SZ_X);
    const bf16* Alo = (const bf16*)(g_buf + (size_t)(2 * sel + 1) * SZ_X);
    const bf16* Bhi = (const bf16*)(g_buf + O_W) + (size_t)sel * 2 * (DM * DM);
    const bf16* Blo = Bhi + DM * DM;
    const float* bias = sel == 0 ? bq : sel == 1 ? bk : bv;
    bf16* Ohi = (bf16*)(g_buf + O_QH + (size_t)(2 * sel) * SZ_HS);
    bf16* Olo = (bf16*)(g_buf + O_QH + (size_t)(2 * sel + 1) * SZ_HS);

    float c[2][4][4];
    #pragma unroll
    for (int i = 0; i < 2; i++)
        #pragma unroll
        for (int j = 0; j < 4; j++)
            #pragma unroll
            for (int q = 0; q < 4; q++) c[i][j][q] = 0.f;

    tile_async(sb + 0,     Ahi + (size_t)mBase * DM, DM, 128, tid);
    tile_async(sb + 16384, Alo + (size_t)mBase * DM, DM, 128, tid);
    tile_async(sb + 32768, Bhi + (size_t)nBase * DM, DM, 64, tid);
    tile_async(sb + 40960, Blo + (size_t)nBase * DM, DM, 64, tid);
    CP_COMMIT();

    #pragma unroll 1
    for (int kc = 0; kc < NK; kc++) {
        if (kc + 1 < NK) {
            uint32_t st = ((kc + 1) & 1) * G_ST;
            tile_async(sb + st + 0,     Ahi + (size_t)mBase * DM + (kc + 1) * 64, DM, 128, tid);
            tile_async(sb + st + 16384, Alo + (size_t)mBase * DM + (kc + 1) * 64, DM, 128, tid);
            tile_async(sb + st + 32768, Bhi + (size_t)nBase * DM + (kc + 1) * 64, DM, 64, tid);
            tile_async(sb + st + 40960, Blo + (size_t)nBase * DM + (kc + 1) * 64, DM, 64, tid);
            CP_COMMIT();
            CP_WAIT1();
        } else {
            CP_WAIT0();
        }
        __syncthreads();
        uint32_t st = (kc & 1) * G_ST;
        mma_stage(sb + st, sb + st + 16384, sb + st + 32768, sb + st + 40960, wr, wc, lane, c);
        __syncthreads();
    }

    const int gid = lane >> 2, tig = lane & 3;
    #pragma unroll
    for (int mf = 0; mf < 2; mf++)
        #pragma unroll
        for (int nf = 0; nf < 4; nf++) {
            int row0 = mBase + wr * 32 + mf * 16 + gid;
            int col  = nBase + wc * 32 + nf * 8 + tig * 2;
            float v0 = c[mf][nf][0] + bias[col];
            float v1 = c[mf][nf][1] + bias[col + 1];
            float v2 = c[mf][nf][2] + bias[col];
            float v3 = c[mf][nf][3] + bias[col + 1];
            int h = col >> 6, kk = col & 63;
            if (sel < 2) {
                #pragma unroll
                for (int rr = 0; rr < 2; rr++) {
                    int m = row0 + rr * 8;
                    int b = m >> 11, s = m & 2047;
                    float f0 = rr ? v2 : v0, f1 = rr ? v3 : v1;
                    bf16 h0, h1, l0, l1;
                    splitf(f0, h0, l0); splitf(f1, h1, l1);
                    size_t dst = (((size_t)b * NH + h) * SS + s) * DK + kk;
                    *reinterpret_cast<uint32_t*>(&Ohi[dst]) = pk2(h0, h1);
                    *reinterpret_cast<uint32_t*>(&Olo[dst]) = pk2(l0, l1);
                }
            } else {
                #pragma unroll
                for (int rr = 0; rr < 2; rr++) {
                    int m = row0 + rr * 8;
                    int b = m >> 11, s = m & 2047;
                    float f0 = rr ? v2 : v0, f1 = rr ? v3 : v1;
                    bf16 hh, ll;
                    size_t dst0 = (((size_t)b * NH + h) * DK + kk) * SS + s;
                    splitf(f0, hh, ll); Ohi[dst0] = hh; Olo[dst0] = ll;
                    size_t dst1 = (((size_t)b * NH + h) * DK + kk + 1) * SS + s;
                    splitf(f1, hh, ll); Ohi[dst1] = hh; Olo[dst1] = ll;
                }
            }
        }
}

// ---------------- output projection (fp32 epilogue) --------------------------
__global__ __launch_bounds__(256, 2) void oproj_mma(
    const bf16* __restrict__ Ahi, const bf16* __restrict__ Alo,
    const bf16* __restrict__ Bhi, const bf16* __restrict__ Blo,
    const float* __restrict__ bias, float* __restrict__ Cf)
{
    extern __shared__ char smem[];
    const uint32_t sb = s2u(smem);
    const int tid = threadIdx.x, wid = tid >> 5, lane = tid & 31;
    const int wr = wid >> 1, wc = wid & 1;
    const int mBase = blockIdx.y * 128, nBase = blockIdx.x * 64;
    const int NK = DM / 64;

    float c[2][4][4];
    #pragma unroll
    for (int i = 0; i < 2; i++)
        #pragma unroll
        for (int j = 0; j < 4; j++)
            #pragma unroll
            for (int q = 0; q < 4; q++) c[i][j][q] = 0.f;

    tile_async(sb + 0,     Ahi + (size_t)mBase * DM, DM, 128, tid);
    tile_async(sb + 16384, Alo + (size_t)mBase * DM, DM, 128, tid);
    tile_async(sb + 32768, Bhi + (size_t)nBase * DM, DM, 64, tid);
    tile_async(sb + 40960, Blo + (size_t)nBase * DM, DM, 64, tid);
    CP_COMMIT();

    #pragma unroll 1
    for (int kc = 0; kc < NK; kc++) {
        if (kc + 1 < NK) {
            uint32_t st = ((kc + 1) & 1) * G_ST;
            tile_async(sb + st + 0,     Ahi + (size_t)mBase * DM + (kc + 1) * 64, DM, 128, tid);
            tile_async(sb + st + 16384, Alo + (size_t)mBase * DM + (kc + 1) * 64, DM, 128, tid);
            tile_async(sb + st + 32768, Bhi + (size_t)nBase * DM + (kc + 1) * 64, DM, 64, tid);
            tile_async(sb + st + 40960, Blo + (size_t)nBase * DM + (kc + 1) * 64, DM, 64, tid);
            CP_COMMIT();
            CP_WAIT1();
        } else {
            CP_WAIT0();
        }
        __syncthreads();
        uint32_t st = (kc & 1) * G_ST;
        mma_stage(sb + st, sb + st + 16384, sb + st + 32768, sb + st + 40960, wr, wc, lane, c);
        __syncthreads();
    }

    const int gid = lane >> 2, tig = lane & 3;
    #pragma unroll
    for (int mf = 0; mf < 2; mf++)
        #pragma unroll
        for (int nf = 0; nf < 4; nf++) {
            int row0 = mBase + wr * 32 + mf * 16 + gid;
            int col  = nBase + wc * 32 + nf * 8 + tig * 2;
            float v0 = c[mf][nf][0] + bias[col];
            float v1 = c[mf][nf][1] + bias[col + 1];
            float v2 = c[mf][nf][2] + bias[col];
            float v3 = c[mf][nf][3] + bias[col + 1];
            *reinterpret_cast<float2*>(&Cf[(size_t)row0 * DM + col])       = make_float2(v0, v1);
            *reinterpret_cast<float2*>(&Cf[(size_t)(row0 + 8) * DM + col]) = make_float2(v2, v3);
        }
}

// ---------------- scores: Q-resident, exp -> Eh/El bf16 planes + row sums ----
#define SC_K(st) (32768 + (st) * 16384)
#define SM_S 66560

__global__ __launch_bounds__(256, 2) void scores_mma(float* __restrict__ psum)
{
    extern __shared__ char smem[];
    const uint32_t sb = s2u(smem);
    float (*rowpart)[128] = reinterpret_cast<float(*)[128]>(smem + 65536);
    const int tid = threadIdx.x, wid = tid >> 5, lane = tid & 31;
    const int wr = wid >> 1, wc = wid & 1;
    const int bh = blockIdx.z, qBase = blockIdx.y * 128, kBase0 = blockIdx.x * 256;

    const bf16* Qh = (const bf16*)(g_buf + O_QH);
    const bf16* Ql = (const bf16*)(g_buf + O_QL);
    const bf16* Kh = (const bf16*)(g_buf + O_KH);
    const bf16* Kl = (const bf16*)(g_buf + O_KL);
    bf16* EhP = (bf16*)(g_buf + O_EH);
    bf16* ElP = (bf16*)(g_buf + O_EL);

    tile_async(sb + 0,     Qh + ((size_t)bh * SS + qBase) * DK, DK, 128, tid);
    tile_async(sb + 16384, Ql + ((size_t)bh * SS + qBase) * DK, DK, 128, tid);
    tile_async(sb + SC_K(0),        Kh + ((size_t)bh * SS + kBase0) * DK, DK, 64, tid);
    tile_async(sb + SC_K(0) + 8192, Kl + ((size_t)bh * SS + kBase0) * DK, DK, 64, tid);
    CP_COMMIT();
    tile_async(sb + SC_K(1),        Kh + ((size_t)bh * SS + kBase0 + 64) * DK, DK, 64, tid);
    tile_async(sb + SC_K(1) + 8192, Kl + ((size_t)bh * SS + kBase0 + 64) * DK, DK, 64, tid);
    CP_COMMIT();

    const int gid = lane >> 2, tig = lane & 3;
    float pacc[2][2] = {{0.f, 0.f}, {0.f, 0.f}};

    #pragma unroll 1
    for (int kc = 0; kc < 4; kc++) {
        const int st = kc & 1;
        if (kc < 3) { CP_WAIT1(); } else { CP_WAIT0(); }
        __syncthreads();

        float c[2][4][4];
        #pragma unroll
        for (int i = 0; i < 2; i++)
            #pragma unroll
            for (int j = 0; j < 4; j++)
                #pragma unroll
                for (int q = 0; q < 4; q++) c[i][j][q] = 0.f;

        mma_stage(sb, sb + 16384, sb + SC_K(st), sb + SC_K(st) + 8192, wr, wc, lane, c);
        __syncthreads();
        if (kc + 2 < 4) {
            tile_async(sb + SC_K(st),        Kh + ((size_t)bh * SS + kBase0 + (kc + 2) * 64) * DK, DK, 64, tid);
            tile_async(sb + SC_K(st) + 8192, Kl + ((size_t)bh * SS + kBase0 + (kc + 2) * 64) * DK, DK, 64, tid);
            CP_COMMIT();
        }

        #pragma unroll
        for (int mf = 0; mf < 2; mf++) {
            int rloc0 = wr * 32 + mf * 16 + gid;
            size_t row0 = ((size_t)bh * SS + qBase + rloc0) * SS;
            size_t row1 = row0 + (size_t)8 * SS;
            #pragma unroll
            for (int nf = 0; nf < 4; nf++) {
                int col = kBase0 + kc * 64 + wc * 32 + nf * 8 + tig * 2;
                float e0 = __expf(c[mf][nf][0] * 0.125f);
                float e1 = __expf(c[mf][nf][1] * 0.125f);
                float e2 = __expf(c[mf][nf][2] * 0.125f);
                float e3 = __expf(c[mf][nf][3] * 0.125f);
                pacc[mf][0] += e0 + e1; pacc[mf][1] += e2 + e3;
                bf16 h0, h1, l0, l1;
                splitf(e0, h0, l0); splitf(e1, h1, l1);
                *reinterpret_cast<uint32_t*>(&EhP[row0 + col]) = pk2(h0, h1);
                *reinterpret_cast<uint32_t*>(&ElP[row0 + col]) = pk2(l0, l1);
                splitf(e2, h0, l0); splitf(e3, h1, l1);
                *reinterpret_cast<uint32_t*>(&EhP[row1 + col]) = pk2(h0, h1);
                *reinterpret_cast<uint32_t*>(&ElP[row1 + col]) = pk2(l0, l1);
            }
        }
    }

    #pragma unroll
    for (int mf = 0; mf < 2; mf++) {
        float p0 = pacc[mf][0], p1 = pacc[mf][1];
        p0 += __shfl_xor_sync(0xffffffffu, p0, 1); p0 += __shfl_xor_sync(0xffffffffu, p0, 2);
        p1 += __shfl_xor_sync(0xffffffffu, p1, 1); p1 += __shfl_xor_sync(0xffffffffu, p1, 2);
        if (tig == 0) {
            int rloc0 = wr * 32 + mf * 16 + gid;
            rowpart[wc][rloc0]     = p0;
            rowpart[wc][rloc0 + 8] = p1;
        }
    }
    __syncthreads();
    if (tid < 128) {
        float s = rowpart[0][tid] + rowpart[1][tid];
        psum[((size_t)bh * SS + qBase + tid) * 8 + blockIdx.x] = s;
    }
}

// ---------------- pv: GEMM on Eh/El bf16 planes + attn write + epilogue scale
// smem: E ring-2 @ s*32768 (hi 16K, lo 16K), V ring-2 @ 65536 + s*16384,
//       rowinv @ 98304;  SM_PV = 98816 -> 2 CTAs/SM
#define PV_E(s)  ((uint32_t)(s) * 32768u)
#define PV_V2(s) (65536u + (uint32_t)(s) * 16384u)
#define PV_RI    98304u
#define SM_PV    98816

__global__ __launch_bounds__(256, 2) void pv_mma(
    float* __restrict__ attn, const float* __restrict__ psum)
{
    extern __shared__ char smem[];
    const uint32_t sb = s2u(smem);
    float* rowinv = reinterpret_cast<float*>(smem + PV_RI);
    const int tid = threadIdx.x, wid = tid >> 5, lane = tid & 31;
    const int wr = wid >> 1, wc = wid & 1;
    const int bh = blockIdx.y, b = bh / NH, h = bh % NH;
    const int qBase = blockIdx.x * 128;

    const bf16* Vh = (const bf16*)(g_buf + O_VH);
    const bf16* Vl = (const bf16*)(g_buf + O_VL);
    const bf16* Eh0 = (const bf16*)(g_buf + O_EH) + ((size_t)bh * SS + qBase) * SS;
    const bf16* El0 = (const bf16*)(g_buf + O_EL) + ((size_t)bh * SS + qBase) * SS;
    bf16* AOh = (bf16*)(g_buf + O_AOH);
    bf16* AOl = (bf16*)(g_buf + O_AOL);
    float* arow0 = attn + ((size_t)bh * SS + qBase) * SS;
    const size_t vbase = (size_t)bh * DK * SS;

    if (tid < 128) {
        const float* pp = psum + ((size_t)bh * SS + qBase + tid) * 8;
        float s = 0.f;
        #pragma unroll
        for (int i = 0; i < 8; i++) s += pp[i];
        rowinv[tid] = 1.0f / s;
    }

    float c[2][4][4];
    #pragma unroll
    for (int i = 0; i < 2; i++)
        #pragma unroll
        for (int j = 0; j < 4; j++)
            #pragma unroll
            for (int q = 0; q < 4; q++) c[i][j][q] = 0.f;

    // prologue: stages 0,1
    #pragma unroll
    for (int g = 0; g < 2; g++) {
        tile_async(sb + PV_E(g),         Eh0 + g * 64, SS, 128, tid);
        tile_async(sb + PV_E(g) + 16384, El0 + g * 64, SS, 128, tid);
        tile_async(sb + PV_V2(g),        Vh + vbase + g * 64, SS, 64, tid);
        tile_async(sb + PV_V2(g) + 8192, Vl + vbase + g * 64, SS, 64, tid);
        CP_COMMIT();
    }

    #pragma unroll 1
    for (int kc = 0; kc < 32; kc++) {
        const int st = kc & 1;
        if (kc < 31) { CP_WAIT1(); } else { CP_WAIT0(); }
        __syncthreads();
        // normalize + attn write from E smem (hi/lo reconstruct)
        {
            int r = tid >> 1, half = tid & 1;
            float inv = rowinv[r];
            uint32_t eb = sb + PV_E(st);
            float* gp = arow0 + (size_t)r * SS + kc * 64 + half * 32;
            #pragma unroll
            for (int j = 0; j < 8; j++) {
                int cb = half * 32 + j * 4;
                uint32_t off = SWZ((uint32_t)(r * 128 + cb * 2));
                uint32_t hx, hy, lx, ly;
                asm volatile("ld.shared.v2.b32 {%0,%1}, [%2];" : "=r"(hx), "=r"(hy) : "r"(eb + off));
                asm volatile("ld.shared.v2.b32 {%0,%1}, [%2];" : "=r"(lx), "=r"(ly) : "r"(eb + 16384 + off));
                float f0 = __uint_as_float(hx << 16)          + __uint_as_float(lx << 16);
                float f1 = __uint_as_float(hx & 0xffff0000u)  + __uint_as_float(lx & 0xffff0000u);
                float f2 = __uint_as_float(hy << 16)          + __uint_as_float(ly << 16);
                float f3 = __uint_as_float(hy & 0xffff0000u)  + __uint_as_float(ly & 0xffff0000u);
                __stcs(reinterpret_cast<float4*>(gp + j * 4),
                       make_float4(f0 * inv, f1 * inv, f2 * inv, f3 * inv));
            }
        }
        // P.V accumulate (unnormalized E)
        mma_stage(sb + PV_E(st), sb + PV_E(st) + 16384,
                  sb + PV_V2(st), sb + PV_V2(st) + 8192, wr, wc, lane, c);
        __syncthreads();
        if (kc + 2 < 32) {
            int g = kc + 2;
            tile_async(sb + PV_E(st),         Eh0 + g * 64, SS, 128, tid);
            tile_async(sb + PV_E(st) + 16384, El0 + g * 64, SS, 128, tid);
            tile_async(sb + PV_V2(st),        Vh + vbase + g * 64, SS, 64, tid);
            tile_async(sb + PV_V2(st) + 8192, Vl + vbase + g * 64, SS, 64, tid);
            CP_COMMIT();
        }
    }

    const int gid = lane >> 2, tig = lane & 3;
    #pragma unroll
    for (int mf = 0; mf < 2; mf++)
        #pragma unroll
        for (int nf = 0; nf < 4; nf++) {
            int rloc = wr * 32 + mf * 16 + gid;
            int col  = wc * 32 + nf * 8 + tig * 2;
            float inv0 = rowinv[rloc], inv1 = rowinv[rloc + 8];
            #pragma unroll
            for (int rr = 0; rr < 2; rr++) {
                int s = qBase + rloc + rr * 8;
                float inv = rr ? inv1 : inv0;
                float f0 = c[mf][nf][rr * 2 + 0] * inv, f1 = c[mf][nf][rr * 2 + 1] * inv;
                bf16 h0, h1, l0, l1;
                splitf(f0, h0, l0); splitf(f1, h1, l1);
                size_t dst = ((size_t)b * SS + s) * DM + h * DK + col;
                *reinterpret_cast<uint32_t*>(&AOh[dst]) = pk2(h0, h1);
                *reinterpret_cast<uint32_t*>(&AOl[dst]) = pk2(l0, l1);
            }
        }
}

// ---------------------------------------------------------------------------
extern "C" void kernel_launch(void* const* d_in, const int* in_sizes, int n_in,
                              void* d_out, int out_size)
{
    (void)in_sizes; (void)n_in; (void)out_size;
    const float* q  = (const float*)d_in[0];
    const float* k  = (const float*)d_in[1];
    const float* v  = (const float*)d_in[2];
    const float* Wq = (const float*)d_in[3];
    const float* bq = (const float*)d_in[4];
    const float* Wk = (const float*)d_in[5];
    const float* bk = (const float*)d_in[6];
    const float* Wv = (const float*)d_in[7];
    const float* bv = (const float*)d_in[8];
    const float* Wo = (const float*)d_in[9];
    const float* bo = (const float*)d_in[10];

    float* out  = (float*)d_out;
    float* attn = out + (size_t)NT * DM;

    char* base = nullptr;
    cudaGetSymbolAddress((void**)&base, g_buf);
    bf16* wb  = (bf16*)(base + O_W);
    bf16* woh = wb + 6*(size_t)DM*DM; bf16* wol = wb + 7*(size_t)DM*DM;
    bf16* AOh = (bf16*)(base + O_AOH); bf16* AOl = (bf16*)(base + O_AOL);
    float* psum = (float*)(base + O_PSUM);

    cudaFuncSetAttribute(qkv_mma,    cudaFuncAttributeMaxDynamicSharedMemorySize, SM_G);
    cudaFuncSetAttribute(oproj_mma,  cudaFuncAttributeMaxDynamicSharedMemorySize, SM_G);
    cudaFuncSetAttribute(scores_mma, cudaFuncAttributeMaxDynamicSharedMemorySize, SM_S);
    cudaFuncSetAttribute(pv_mma,     cudaFuncAttributeMaxDynamicSharedMemorySize, SM_PV);

    const int n4 = NT * DM / 4;
    split3<<<dim3((n4 + 255) / 256, 3), 256>>>(q, k, v);
    wsplit4<<<dim3((DM * DM + 255) / 256, 4), 256>>>(Wq, Wk, Wv, Wo);

    dim3 gProj(DM / 64, NT / 128, 3);  // 12 x 64 x 3
    qkv_mma<<<gProj, 256, SM_G>>>(bq, bk, bv);

    dim3 gS(SS / 256, SS / 128, BHN);  // 8 x 16 x 48
    scores_mma<<<gS, 256, SM_S>>>(psum);

    dim3 gPV(SS / 128, BHN);           // 16 x 48
    pv_mma<<<gPV, 256, SM_PV>>>(attn, psum);

    dim3 gO(DM / 64, NT / 128);        // 12 x 64
    oproj_mma<<<gO, 256, SM_G>>>(AOh, AOl, woh, wol, bo, out);
}

// round 16
// speedup vs baseline: 3.7851x; 1.0097x over previous
#include <cuda_runtime.h>
#include <cuda_bf16.h>
#include <stdint.h>
#include <math.h>

#define BB 4
#define SS 2048
#define DM 768
#define NH 12
#define DK 64
#define NT (BB*SS)
#define BHN (BB*NH)

typedef __nv_bfloat16 bf16;
typedef __nv_bfloat162 bf162;

// ---------------- scratch arena ---------------------------------------------
#define SZ_X   ((size_t)NT*DM*2)
#define SZ_W   ((size_t)DM*DM*2)
#define SZ_HS  ((size_t)BHN*SS*DK*2)
#define SZ_E   ((size_t)BHN*SS*SS*2)    // one bf16 E plane: 402 MB
#define O_XQH  (0*SZ_X)
#define O_XQL  (1*SZ_X)
#define O_XKH  (2*SZ_X)
#define O_XKL  (3*SZ_X)
#define O_XVH  (4*SZ_X)
#define O_XVL  (5*SZ_X)
#define O_W    (6*SZ_X)
#define O_QH   (O_W + 8*SZ_W)
#define O_QL   (O_QH + 1*SZ_HS)
#define O_KH   (O_QH + 2*SZ_HS)
#define O_KL   (O_QH + 3*SZ_HS)
#define O_VH   (O_QH + 4*SZ_HS)         // V^T: [B,H,dk,S]
#define O_VL   (O_QH + 5*SZ_HS)
#define O_AOH  (O_QH + 6*SZ_HS)
#define O_AOL  (O_AOH + SZ_X)
#define O_PSUM (O_AOL + SZ_X)           // [BHN*SS][8] fp32
#define O_EH   (O_PSUM + (size_t)BHN*SS*8*4)
#define O_EL   (O_EH + SZ_E)
#define ARENA  (O_EL + SZ_E)

__device__ __align__(1024) char g_buf[ARENA];

// ---------------- helpers ----------------------------------------------------
#define SWZ(o) ((o) ^ (((o) >> 3) & 0x70))

__device__ __forceinline__ uint32_t s2u(const void* p) {
    uint32_t a;
    asm("{ .reg .u64 t; cvta.to.shared.u64 t, %1; cvt.u32.u64 %0, t; }" : "=r"(a) : "l"(p));
    return a;
}
__device__ __forceinline__ void ldsm4(uint32_t* r, uint32_t a) {
    asm volatile("ldmatrix.sync.aligned.m8n8.x4.shared.b16 {%0,%1,%2,%3}, [%4];"
                 : "=r"(r[0]), "=r"(r[1]), "=r"(r[2]), "=r"(r[3]) : "r"(a));
}
__device__ __forceinline__ void hmma(float* c, const uint32_t* a, const uint32_t* b) {
    asm volatile("mma.sync.aligned.m16n8k16.row.col.f32.bf16.bf16.f32 "
                 "{%0,%1,%2,%3}, {%4,%5,%6,%7}, {%8,%9}, {%0,%1,%2,%3};"
                 : "+f"(c[0]), "+f"(c[1]), "+f"(c[2]), "+f"(c[3])
                 : "r"(a[0]), "r"(a[1]), "r"(a[2]), "r"(a[3]), "r"(b[0]), "r"(b[1]));
}
__device__ __forceinline__ uint32_t a_addr(uint32_t sbase, int rowBase, int kb, int lane) {
    int m = rowBase + (lane & 7) + ((lane >> 3) & 1) * 8;
    int kk = kb + (lane >> 4) * 8;
    return sbase + SWZ((uint32_t)(m * 128 + kk * 2));
}
__device__ __forceinline__ uint32_t b_addr4(uint32_t sbase, int colBase, int kb, int lane) {
    int n = colBase + (lane & 7) + ((lane >> 4) & 1) * 8;
    int kk = kb + ((lane >> 3) & 1) * 8;
    return sbase + SWZ((uint32_t)(n * 128 + kk * 2));
}
__device__ __forceinline__ void cpasync16(uint32_t dst, const void* src) {
    asm volatile("cp.async.cg.shared.global [%0], [%1], 16;" :: "r"(dst), "l"(src));
}
#define CP_COMMIT() asm volatile("cp.async.commit_group;" ::: "memory")
#define CP_WAIT0()  asm volatile("cp.async.wait_group 0;" ::: "memory")
#define CP_WAIT1()  asm volatile("cp.async.wait_group 1;" ::: "memory")

__device__ __forceinline__ void tile_async(uint32_t dst, const bf16* __restrict__ src,
                                           int ld, int rows, int tid) {
    const int units = rows * 8;
    for (int u = tid; u < units; u += 256) {
        int r = u >> 3, j = u & 7;
        cpasync16(dst + SWZ((uint32_t)(r * 128 + j * 16)), src + (size_t)r * ld + j * 8);
    }
}
__device__ __forceinline__ uint32_t pk2(bf16 a, bf16 b) {
    bf162 t; t.x = a; t.y = b; return *reinterpret_cast<uint32_t*>(&t);
}
__device__ __forceinline__ void splitf(float f, bf16& h, bf16& l) {
    h = __float2bfloat16(f);
    l = __float2bfloat16(f - __bfloat162float(h));
}
// packed pair split via F2FP: hi/lo are bf16x2 words (lower=f0, upper=f1)
__device__ __forceinline__ void splitf2(float f0, float f1, uint32_t& hi, uint32_t& lo) {
    asm("cvt.rn.bf16x2.f32 %0, %2, %1;" : "=r"(hi) : "f"(f0), "f"(f1));
    float h0 = __uint_as_float(hi << 16);
    float h1 = __uint_as_float(hi & 0xffff0000u);
    float l0 = f0 - h0, l1 = f1 - h1;
    asm("cvt.rn.bf16x2.f32 %0, %2, %1;" : "=r"(lo) : "f"(l0), "f"(l1));
}

// Shared mainloop: A 128x64 hi/lo, B 64x64 hi/lo (swizzled) -> c[2][4][4]
__device__ __forceinline__ void mma_stage(uint32_t ahb, uint32_t alb, uint32_t bhb, uint32_t blb,
                                          int wr, int wc, int lane, float (&c)[2][4][4]) {
    #pragma unroll
    for (int ks = 0; ks < 4; ks++) {
        uint32_t fah[2][4], fal[2][4], fbh[2][4], fbl[2][4];
        #pragma unroll
        for (int mf = 0; mf < 2; mf++) {
            ldsm4(fah[mf], a_addr(ahb, wr * 32 + mf * 16, ks * 16, lane));
            ldsm4(fal[mf], a_addr(alb, wr * 32 + mf * 16, ks * 16, lane));
        }
        #pragma unroll
        for (int g = 0; g < 2; g++) {
            ldsm4(fbh[g], b_addr4(bhb, wc * 32 + g * 16, ks * 16, lane));
            ldsm4(fbl[g], b_addr4(blb, wc * 32 + g * 16, ks * 16, lane));
        }
        #pragma unroll
        for (int mf = 0; mf < 2; mf++)
            #pragma unroll
            for (int nf = 0; nf < 4; nf++) {
                const uint32_t* bh_ = &fbh[nf >> 1][(nf & 1) * 2];
                const uint32_t* bl_ = &fbl[nf >> 1][(nf & 1) * 2];
                hmma(c[mf][nf], fah[mf], bh_);
                hmma(c[mf][nf], fah[mf], bl_);
                hmma(c[mf][nf], fal[mf], bh_);
            }
    }
}

// ---------------- merged pre-split kernels ----------------------------------
__global__ __launch_bounds__(256) void split3(
    const float* __restrict__ q, const float* __restrict__ k, const float* __restrict__ v) {
    const int n4 = NT * DM / 4;
    int i = blockIdx.x * 256 + threadIdx.x;
    if (i >= n4) return;
    int sel = blockIdx.y;
    const float* x = sel == 0 ? q : sel == 1 ? k : v;
    bf16* hi = (bf16*)(g_buf + (size_t)(2 * sel) * SZ_X);
    bf16* lo = (bf16*)(g_buf + (size_t)(2 * sel + 1) * SZ_X);
    float4 f = reinterpret_cast<const float4*>(x)[i];
    uint2 hv, lv;
    splitf2(f.x, f.y, hv.x, lv.x);
    splitf2(f.z, f.w, hv.y, lv.y);
    reinterpret_cast<uint2*>(hi)[i] = hv;
    reinterpret_cast<uint2*>(lo)[i] = lv;
}
__global__ __launch_bounds__(256) void wsplit4(
    const float* __restrict__ Wq, const float* __restrict__ Wk,
    const float* __restrict__ Wv, const float* __restrict__ Wo) {
    int idx = blockIdx.x * 256 + threadIdx.x;
    if (idx >= DM * DM) return;
    int sel = blockIdx.y;
    const float* W = sel == 0 ? Wq : sel == 1 ? Wk : sel == 2 ? Wv : Wo;
    bf16* th = (bf16*)(g_buf + O_W) + (size_t)sel * 2 * (DM * DM);
    bf16* tl = th + DM * DM;
    int n = idx / DM, k = idx % DM;
    bf16 h, l; splitf(W[(size_t)k * DM + n], h, l);
    th[idx] = h; tl[idx] = l;
}

// ---------------- merged QKV projection (grid.z = sel) -----------------------
#define G_ST 49152
#define SM_G 98304

__global__ __launch_bounds__(256, 2) void qkv_mma(
    const float* __restrict__ bq, const float* __restrict__ bk, const float* __restrict__ bv)
{
    extern __shared__ char smem[];
    const uint32_t sb = s2u(smem);
    const int tid = threadIdx.x, wid = tid >> 5, lane = tid & 31;
    const int wr = wid >> 1, wc = wid & 1;
    const int sel = blockIdx.z;
    const int mBase = blockIdx.y * 128, nBase = blockIdx.x * 64;
    const int NK = DM / 64;

    const bf16* Ahi = (const bf16*)(g_buf + (size_t)(2 * sel) * SZ_X);
    const bf16* Alo = (const bf16*)(g_buf + (size_t)(2 * sel + 1) * SZ_X);
    const bf16* Bhi = (const bf16*)(g_buf + O_W) + (size_t)sel * 2 * (DM * DM);
    const bf16* Blo = Bhi + DM * DM;
    const float* bias = sel == 0 ? bq : sel == 1 ? bk : bv;
    bf16* Ohi = (bf16*)(g_buf + O_QH + (size_t)(2 * sel) * SZ_HS);
    bf16* Olo = (bf16*)(g_buf + O_QH + (size_t)(2 * sel + 1) * SZ_HS);

    float c[2][4][4];
    #pragma unroll
    for (int i = 0; i < 2; i++)
        #pragma unroll
        for (int j = 0; j < 4; j++)
            #pragma unroll
            for (int q = 0; q < 4; q++) c[i][j][q] = 0.f;

    tile_async(sb + 0,     Ahi + (size_t)mBase * DM, DM, 128, tid);
    tile_async(sb + 16384, Alo + (size_t)mBase * DM, DM, 128, tid);
    tile_async(sb + 32768, Bhi + (size_t)nBase * DM, DM, 64, tid);
    tile_async(sb + 40960, Blo + (size_t)nBase * DM, DM, 64, tid);
    CP_COMMIT();

    #pragma unroll 1
    for (int kc = 0; kc < NK; kc++) {
        if (kc + 1 < NK) {
            uint32_t st = ((kc + 1) & 1) * G_ST;
            tile_async(sb + st + 0,     Ahi + (size_t)mBase * DM + (kc + 1) * 64, DM, 128, tid);
            tile_async(sb + st + 16384, Alo + (size_t)mBase * DM + (kc + 1) * 64, DM, 128, tid);
            tile_async(sb + st + 32768, Bhi + (size_t)nBase * DM + (kc + 1) * 64, DM, 64, tid);
            tile_async(sb + st + 40960, Blo + (size_t)nBase * DM + (kc + 1) * 64, DM, 64, tid);
            CP_COMMIT();
            CP_WAIT1();
        } else {
            CP_WAIT0();
        }
        __syncthreads();
        uint32_t st = (kc & 1) * G_ST;
        mma_stage(sb + st, sb + st + 16384, sb + st + 32768, sb + st + 40960, wr, wc, lane, c);
        __syncthreads();
    }

    const int gid = lane >> 2, tig = lane & 3;
    #pragma unroll
    for (int mf = 0; mf < 2; mf++)
        #pragma unroll
        for (int nf = 0; nf < 4; nf++) {
            int row0 = mBase + wr * 32 + mf * 16 + gid;
            int col  = nBase + wc * 32 + nf * 8 + tig * 2;
            float v0 = c[mf][nf][0] + bias[col];
            float v1 = c[mf][nf][1] + bias[col + 1];
            float v2 = c[mf][nf][2] + bias[col];
            float v3 = c[mf][nf][3] + bias[col + 1];
            int h = col >> 6, kk = col & 63;
            if (sel < 2) {
                #pragma unroll
                for (int rr = 0; rr < 2; rr++) {
                    int m = row0 + rr * 8;
                    int b = m >> 11, s = m & 2047;
                    float f0 = rr ? v2 : v0, f1 = rr ? v3 : v1;
                    uint32_t hw, lw;
                    splitf2(f0, f1, hw, lw);
                    size_t dst = (((size_t)b * NH + h) * SS + s) * DK + kk;
                    *reinterpret_cast<uint32_t*>(&Ohi[dst]) = hw;
                    *reinterpret_cast<uint32_t*>(&Olo[dst]) = lw;
                }
            } else {
                #pragma unroll
                for (int rr = 0; rr < 2; rr++) {
                    int m = row0 + rr * 8;
                    int b = m >> 11, s = m & 2047;
                    float f0 = rr ? v2 : v0, f1 = rr ? v3 : v1;
                    bf16 hh, ll;
                    size_t dst0 = (((size_t)b * NH + h) * DK + kk) * SS + s;
                    splitf(f0, hh, ll); Ohi[dst0] = hh; Olo[dst0] = ll;
                    size_t dst1 = (((size_t)b * NH + h) * DK + kk + 1) * SS + s;
                    splitf(f1, hh, ll); Ohi[dst1] = hh; Olo[dst1] = ll;
                }
            }
        }
}

// ---------------- output projection (fp32 epilogue) --------------------------
__global__ __launch_bounds__(256, 2) void oproj_mma(
    const bf16* __restrict__ Ahi, const bf16* __restrict__ Alo,
    const bf16* __restrict__ Bhi, const bf16* __restrict__ Blo,
    const float* __restrict__ bias, float* __restrict__ Cf)
{
    extern __shared__ char smem[];
    const uint32_t sb = s2u(smem);
    const int tid = threadIdx.x, wid = tid >> 5, lane = tid & 31;
    const int wr = wid >> 1, wc = wid & 1;
    const int mBase = blockIdx.y * 128, nBase = blockIdx.x * 64;
    const int NK = DM / 64;

    float c[2][4][4];
    #pragma unroll
    for (int i = 0; i < 2; i++)
        #pragma unroll
        for (int j = 0; j < 4; j++)
            #pragma unroll
            for (int q = 0; q < 4; q++) c[i][j][q] = 0.f;

    tile_async(sb + 0,     Ahi + (size_t)mBase * DM, DM, 128, tid);
    tile_async(sb + 16384, Alo + (size_t)mBase * DM, DM, 128, tid);
    tile_async(sb + 32768, Bhi + (size_t)nBase * DM, DM, 64, tid);
    tile_async(sb + 40960, Blo + (size_t)nBase * DM, DM, 64, tid);
    CP_COMMIT();

    #pragma unroll 1
    for (int kc = 0; kc < NK; kc++) {
        if (kc + 1 < NK) {
            uint32_t st = ((kc + 1) & 1) * G_ST;
            tile_async(sb + st + 0,     Ahi + (size_t)mBase * DM + (kc + 1) * 64, DM, 128, tid);
            tile_async(sb + st + 16384, Alo + (size_t)mBase * DM + (kc + 1) * 64, DM, 128, tid);
            tile_async(sb + st + 32768, Bhi + (size_t)nBase * DM + (kc + 1) * 64, DM, 64, tid);
            tile_async(sb + st + 40960, Blo + (size_t)nBase * DM + (kc + 1) * 64, DM, 64, tid);
            CP_COMMIT();
            CP_WAIT1();
        } else {
            CP_WAIT0();
        }
        __syncthreads();
        uint32_t st = (kc & 1) * G_ST;
        mma_stage(sb + st, sb + st + 16384, sb + st + 32768, sb + st + 40960, wr, wc, lane, c);
        __syncthreads();
    }

    const int gid = lane >> 2, tig = lane & 3;
    #pragma unroll
    for (int mf = 0; mf < 2; mf++)
        #pragma unroll
        for (int nf = 0; nf < 4; nf++) {
            int row0 = mBase + wr * 32 + mf * 16 + gid;
            int col  = nBase + wc * 32 + nf * 8 + tig * 2;
            float v0 = c[mf][nf][0] + bias[col];
            float v1 = c[mf][nf][1] + bias[col + 1];
            float v2 = c[mf][nf][2] + bias[col];
            float v3 = c[mf][nf][3] + bias[col + 1];
            *reinterpret_cast<float2*>(&Cf[(size_t)row0 * DM + col])       = make_float2(v0, v1);
            *reinterpret_cast<float2*>(&Cf[(size_t)(row0 + 8) * DM + col]) = make_float2(v2, v3);
        }
}

// ---------------- scores: Q-resident, exp -> Eh/El bf16 planes + row sums ----
#define SC_K(st) (32768 + (st) * 16384)
#define SM_S 66560

__global__ __launch_bounds__(256, 2) void scores_mma(float* __restrict__ psum)
{
    extern __shared__ char smem[];
    const uint32_t sb = s2u(smem);
    float (*rowpart)[128] = reinterpret_cast<float(*)[128]>(smem + 65536);
    const int tid = threadIdx.x, wid = tid >> 5, lane = tid & 31;
    const int wr = wid >> 1, wc = wid & 1;
    const int bh = blockIdx.z, qBase = blockIdx.y * 128, kBase0 = blockIdx.x * 256;

    const bf16* Qh = (const bf16*)(g_buf + O_QH);
    const bf16* Ql = (const bf16*)(g_buf + O_QL);
    const bf16* Kh = (const bf16*)(g_buf + O_KH);
    const bf16* Kl = (const bf16*)(g_buf + O_KL);
    bf16* EhP = (bf16*)(g_buf + O_EH);
    bf16* ElP = (bf16*)(g_buf + O_EL);

    tile_async(sb + 0,     Qh + ((size_t)bh * SS + qBase) * DK, DK, 128, tid);
    tile_async(sb + 16384, Ql + ((size_t)bh * SS + qBase) * DK, DK, 128, tid);
    tile_async(sb + SC_K(0),        Kh + ((size_t)bh * SS + kBase0) * DK, DK, 64, tid);
    tile_async(sb + SC_K(0) + 8192, Kl + ((size_t)bh * SS + kBase0) * DK, DK, 64, tid);
    CP_COMMIT();
    tile_async(sb + SC_K(1),        Kh + ((size_t)bh * SS + kBase0 + 64) * DK, DK, 64, tid);
    tile_async(sb + SC_K(1) + 8192, Kl + ((size_t)bh * SS + kBase0 + 64) * DK, DK, 64, tid);
    CP_COMMIT();

    const int gid = lane >> 2, tig = lane & 3;
    float pacc[2][2] = {{0.f, 0.f}, {0.f, 0.f}};

    #pragma unroll 1
    for (int kc = 0; kc < 4; kc++) {
        const int st = kc & 1;
        if (kc < 3) { CP_WAIT1(); } else { CP_WAIT0(); }
        __syncthreads();

        float c[2][4][4];
        #pragma unroll
        for (int i = 0; i < 2; i++)
            #pragma unroll
            for (int j = 0; j < 4; j++)
                #pragma unroll
                for (int q = 0; q < 4; q++) c[i][j][q] = 0.f;

        mma_stage(sb, sb + 16384, sb + SC_K(st), sb + SC_K(st) + 8192, wr, wc, lane, c);
        __syncthreads();
        if (kc + 2 < 4) {
            tile_async(sb + SC_K(st),        Kh + ((size_t)bh * SS + kBase0 + (kc + 2) * 64) * DK, DK, 64, tid);
            tile_async(sb + SC_K(st) + 8192, Kl + ((size_t)bh * SS + kBase0 + (kc + 2) * 64) * DK, DK, 64, tid);
            CP_COMMIT();
        }

        #pragma unroll
        for (int mf = 0; mf < 2; mf++) {
            int rloc0 = wr * 32 + mf * 16 + gid;
            size_t row0 = ((size_t)bh * SS + qBase + rloc0) * SS;
            size_t row1 = row0 + (size_t)8 * SS;
            #pragma unroll
            for (int nf = 0; nf < 4; nf++) {
                int col = kBase0 + kc * 64 + wc * 32 + nf * 8 + tig * 2;
                float e0 = __expf(c[mf][nf][0] * 0.125f);
                float e1 = __expf(c[mf][nf][1] * 0.125f);
                float e2 = __expf(c[mf][nf][2] * 0.125f);
                float e3 = __expf(c[mf][nf][3] * 0.125f);
                pacc[mf][0] += e0 + e1; pacc[mf][1] += e2 + e3;
                uint32_t hA, lA, hB, lB;
                splitf2(e0, e1, hA, lA);
                splitf2(e2, e3, hB, lB);
                *reinterpret_cast<uint32_t*>(&EhP[row0 + col]) = hA;
                *reinterpret_cast<uint32_t*>(&ElP[row0 + col]) = lA;
                *reinterpret_cast<uint32_t*>(&EhP[row1 + col]) = hB;
                *reinterpret_cast<uint32_t*>(&ElP[row1 + col]) = lB;
            }
        }
    }

    #pragma unroll
    for (int mf = 0; mf < 2; mf++) {
        float p0 = pacc[mf][0], p1 = pacc[mf][1];
        p0 += __shfl_xor_sync(0xffffffffu, p0, 1); p0 += __shfl_xor_sync(0xffffffffu, p0, 2);
        p1 += __shfl_xor_sync(0xffffffffu, p1, 1); p1 += __shfl_xor_sync(0xffffffffu, p1, 2);
        if (tig == 0) {
            int rloc0 = wr * 32 + mf * 16 + gid;
            rowpart[wc][rloc0]     = p0;
            rowpart[wc][rloc0 + 8] = p1;
        }
    }
    __syncthreads();
    if (tid < 128) {
        float s = rowpart[0][tid] + rowpart[1][tid];
        psum[((size_t)bh * SS + qBase + tid) * 8 + blockIdx.x] = s;
    }
}

// ---------------- pv: GEMM on Eh/El bf16 planes + attn write + epilogue scale
#define PV_E(s)  ((uint32_t)(s) * 32768u)
#define PV_V2(s) (65536u + (uint32_t)(s) * 16384u)
#define PV_RI    98304u
#define SM_PV    98816

__global__ __launch_bounds__(256, 2) void pv_mma(
    float* __restrict__ attn, const float* __restrict__ psum)
{
    extern __shared__ char smem[];
    const uint32_t sb = s2u(smem);
    float* rowinv = reinterpret_cast<float*>(smem + PV_RI);
    const int tid = threadIdx.x, wid = tid >> 5, lane = tid & 31;
    const int wr = wid >> 1, wc = wid & 1;
    const int bh = blockIdx.y, b = bh / NH, h = bh % NH;
    const int qBase = blockIdx.x * 128;

    const bf16* Vh = (const bf16*)(g_buf + O_VH);
    const bf16* Vl = (const bf16*)(g_buf + O_VL);
    const bf16* Eh0 = (const bf16*)(g_buf + O_EH) + ((size_t)bh * SS + qBase) * SS;
    const bf16* El0 = (const bf16*)(g_buf + O_EL) + ((size_t)bh * SS + qBase) * SS;
    bf16* AOh = (bf16*)(g_buf + O_AOH);
    bf16* AOl = (bf16*)(g_buf + O_AOL);
    float* arow0 = attn + ((size_t)bh * SS + qBase) * SS;
    const size_t vbase = (size_t)bh * DK * SS;

    if (tid < 128) {
        const float* pp = psum + ((size_t)bh * SS + qBase + tid) * 8;
        float s = 0.f;
        #pragma unroll
        for (int i = 0; i < 8; i++) s += pp[i];
        rowinv[tid] = 1.0f / s;
    }

    float c[2][4][4];
    #pragma unroll
    for (int i = 0; i < 2; i++)
        #pragma unroll
        for (int j = 0; j < 4; j++)
            #pragma unroll
            for (int q = 0; q < 4; q++) c[i][j][q] = 0.f;

    // prologue: stages 0,1
    #pragma unroll
    for (int g = 0; g < 2; g++) {
        tile_async(sb + PV_E(g),         Eh0 + g * 64, SS, 128, tid);
        tile_async(sb + PV_E(g) + 16384, El0 + g * 64, SS, 128, tid);
        tile_async(sb + PV_V2(g),        Vh + vbase + g * 64, SS, 64, tid);
        tile_async(sb + PV_V2(g) + 8192, Vl + vbase + g * 64, SS, 64, tid);
        CP_COMMIT();
    }

    #pragma unroll 1
    for (int kc = 0; kc < 32; kc++) {
        const int st = kc & 1;
        if (kc < 31) { CP_WAIT1(); } else { CP_WAIT0(); }
        __syncthreads();
        // normalize + attn write from E smem (hi/lo reconstruct)
        {
            int r = tid >> 1, half = tid & 1;
            float inv = rowinv[r];
            uint32_t eb = sb + PV_E(st);
            float* gp = arow0 + (size_t)r * SS + kc * 64 + half * 32;
            #pragma unroll
            for (int j = 0; j < 8; j++) {
                int cb = half * 32 + j * 4;
                uint32_t off = SWZ((uint32_t)(r * 128 + cb * 2));
                uint32_t hx, hy, lx, ly;
                asm volatile("ld.shared.v2.b32 {%0,%1}, [%2];" : "=r"(hx), "=r"(hy) : "r"(eb + off));
                asm volatile("ld.shared.v2.b32 {%0,%1}, [%2];" : "=r"(lx), "=r"(ly) : "r"(eb + 16384 + off));
                float f0 = __uint_as_float(hx << 16)          + __uint_as_float(lx << 16);
                float f1 = __uint_as_float(hx & 0xffff0000u)  + __uint_as_float(lx & 0xffff0000u);
                float f2 = __uint_as_float(hy << 16)          + __uint_as_float(ly << 16);
                float f3 = __uint_as_float(hy & 0xffff0000u)  + __uint_as_float(ly & 0xffff0000u);
                __stcs(reinterpret_cast<float4*>(gp + j * 4),
                       make_float4(f0 * inv, f1 * inv, f2 * inv, f3 * inv));
            }
        }
        // P.V accumulate (unnormalized E)
        mma_stage(sb + PV_E(st), sb + PV_E(st) + 16384,
                  sb + PV_V2(st), sb + PV_V2(st) + 8192, wr, wc, lane, c);
        __syncthreads();
        if (kc + 2 < 32) {
            int g = kc + 2;
            tile_async(sb + PV_E(st),         Eh0 + g * 64, SS, 128, tid);
            tile_async(sb + PV_E(st) + 16384, El0 + g * 64, SS, 128, tid);
            tile_async(sb + PV_V2(st),        Vh + vbase + g * 64, SS, 64, tid);
            tile_async(sb + PV_V2(st) + 8192, Vl + vbase + g * 64, SS, 64, tid);
            CP_COMMIT();
        }
    }

    const int gid = lane >> 2, tig = lane & 3;
    #pragma unroll
    for (int mf = 0; mf < 2; mf++)
        #pragma unroll
        for (int nf = 0; nf < 4; nf++) {
            int rloc = wr * 32 + mf * 16 + gid;
            int col  = wc * 32 + nf * 8 + tig * 2;
            float inv0 = rowinv[rloc], inv1 = rowinv[rloc + 8];
            #pragma unroll
            for (int rr = 0; rr < 2; rr++) {
                int s = qBase + rloc + rr * 8;
                float inv = rr ? inv1 : inv0;
                float f0 = c[mf][nf][rr * 2 + 0] * inv, f1 = c[mf][nf][rr * 2 + 1] * inv;
                uint32_t hw, lw;
                splitf2(f0, f1, hw, lw);
                size_t dst = ((size_t)b * SS + s) * DM + h * DK + col;
                *reinterpret_cast<uint32_t*>(&AOh[dst]) = hw;
                *reinterpret_cast<uint32_t*>(&AOl[dst]) = lw;
            }
        }
}

// ---------------------------------------------------------------------------
extern "C" void kernel_launch(void* const* d_in, const int* in_sizes, int n_in,
                              void* d_out, int out_size)
{
    (void)in_sizes; (void)n_in; (void)out_size;
    const float* q  = (const float*)d_in[0];
    const float* k  = (const float*)d_in[1];
    const float* v  = (const float*)d_in[2];
    const float* Wq = (const float*)d_in[3];
    const float* bq = (const float*)d_in[4];
    const float* Wk = (const float*)d_in[5];
    const float* bk = (const float*)d_in[6];
    const float* Wv = (const float*)d_in[7];
    const float* bv = (const float*)d_in[8];
    const float* Wo = (const float*)d_in[9];
    const float* bo = (const float*)d_in[10];

    float* out  = (float*)d_out;
    float* attn = out + (size_t)NT * DM;

    char* base = nullptr;
    cudaGetSymbolAddress((void**)&base, g_buf);
    bf16* wb  = (bf16*)(base + O_W);
    bf16* woh = wb + 6*(size_t)DM*DM; bf16* wol = wb + 7*(size_t)DM*DM;
    bf16* AOh = (bf16*)(base + O_AOH); bf16* AOl = (bf16*)(base + O_AOL);
    float* psum = (float*)(base + O_PSUM);

    cudaFuncSetAttribute(qkv_mma,    cudaFuncAttributeMaxDynamicSharedMemorySize, SM_G);
    cudaFuncSetAttribute(oproj_mma,  cudaFuncAttributeMaxDynamicSharedMemorySize, SM_G);
    cudaFuncSetAttribute(scores_mma, cudaFuncAttributeMaxDynamicSharedMemorySize, SM_S);
    cudaFuncSetAttribute(pv_mma,     cudaFuncAttributeMaxDynamicSharedMemorySize, SM_PV);

    const int n4 = NT * DM / 4;
    split3<<<dim3((n4 + 255) / 256, 3), 256>>>(q, k, v);
    wsplit4<<<dim3((DM * DM + 255) / 256, 4), 256>>>(Wq, Wk, Wv, Wo);

    dim3 gProj(DM / 64, NT / 128, 3);  // 12 x 64 x 3
    qkv_mma<<<gProj, 256, SM_G>>>(bq, bk, bv);

    dim3 gS(SS / 256, SS / 128, BHN);  // 8 x 16 x 48
    scores_mma<<<gS, 256, SM_S>>>(psum);

    dim3 gPV(SS / 128, BHN);           // 16 x 48
    pv_mma<<<gPV, 256, SM_PV>>>(attn, psum);

    dim3 gO(DM / 64, NT / 128);        // 12 x 64
    oproj_mma<<<gO, 256, SM_G>>>(AOh, AOl, woh, wol, bo, out);
}

// round 17
// speedup vs baseline: 4.9350x; 1.3038x over previous
#include <cuda_runtime.h>
#include <cuda_bf16.h>
#include <stdint.h>
#include <math.h>

#define BB 4
#define SS 2048
#define DM 768
#define NH 12
#define DK 64
#define NT (BB*SS)
#define BHN (BB*NH)

typedef __nv_bfloat16 bf16;
typedef __nv_bfloat162 bf162;

// ---------------- scratch arena ---------------------------------------------
#define SZ_X   ((size_t)NT*DM*2)
#define SZ_W   ((size_t)DM*DM*2)
#define SZ_HS  ((size_t)BHN*SS*DK*2)
#define SZ_E   ((size_t)BHN*SS*SS*2)
#define O_XQH  (0*SZ_X)
#define O_XQL  (1*SZ_X)
#define O_XKH  (2*SZ_X)
#define O_XKL  (3*SZ_X)
#define O_XVH  (4*SZ_X)
#define O_XVL  (5*SZ_X)
#define O_W    (6*SZ_X)
#define O_QH   (O_W + 8*SZ_W)
#define O_QL   (O_QH + 1*SZ_HS)
#define O_KH   (O_QH + 2*SZ_HS)
#define O_KL   (O_QH + 3*SZ_HS)
#define O_VH   (O_QH + 4*SZ_HS)         // V^T: [B,H,dk,S]
#define O_VL   (O_QH + 5*SZ_HS)
#define O_AOH  (O_QH + 6*SZ_HS)
#define O_AOL  (O_AOH + SZ_X)
#define O_PSUM (O_AOL + SZ_X)           // [BHN*SS][8] fp32
#define O_EH   (O_PSUM + (size_t)BHN*SS*8*4)
#define O_EL   (O_EH + SZ_E)
#define ARENA  (O_EL + SZ_E)

__device__ __align__(1024) char g_buf[ARENA];

// ---------------- helpers ----------------------------------------------------
#define SWZ(o) ((o) ^ (((o) >> 3) & 0x70))

__device__ __forceinline__ uint32_t s2u(const void* p) {
    uint32_t a;
    asm("{ .reg .u64 t; cvta.to.shared.u64 t, %1; cvt.u32.u64 %0, t; }" : "=r"(a) : "l"(p));
    return a;
}
__device__ __forceinline__ void ldsm4(uint32_t* r, uint32_t a) {
    asm volatile("ldmatrix.sync.aligned.m8n8.x4.shared.b16 {%0,%1,%2,%3}, [%4];"
                 : "=r"(r[0]), "=r"(r[1]), "=r"(r[2]), "=r"(r[3]) : "r"(a));
}
__device__ __forceinline__ void hmma(float* c, const uint32_t* a, const uint32_t* b) {
    asm volatile("mma.sync.aligned.m16n8k16.row.col.f32.bf16.bf16.f32 "
                 "{%0,%1,%2,%3}, {%4,%5,%6,%7}, {%8,%9}, {%0,%1,%2,%3};"
                 : "+f"(c[0]), "+f"(c[1]), "+f"(c[2]), "+f"(c[3])
                 : "r"(a[0]), "r"(a[1]), "r"(a[2]), "r"(a[3]), "r"(b[0]), "r"(b[1]));
}
__device__ __forceinline__ uint32_t a_addr(uint32_t sbase, int rowBase, int kb, int lane) {
    int m = rowBase + (lane & 7) + ((lane >> 3) & 1) * 8;
    int kk = kb + (lane >> 4) * 8;
    return sbase + SWZ((uint32_t)(m * 128 + kk * 2));
}
__device__ __forceinline__ uint32_t b_addr4(uint32_t sbase, int colBase, int kb, int lane) {
    int n = colBase + (lane & 7) + ((lane >> 4) & 1) * 8;
    int kk = kb + ((lane >> 3) & 1) * 8;
    return sbase + SWZ((uint32_t)(n * 128 + kk * 2));
}
__device__ __forceinline__ void cpasync16(uint32_t dst, const void* src) {
    asm volatile("cp.async.cg.shared.global [%0], [%1], 16;" :: "r"(dst), "l"(src));
}
#define CP_COMMIT() asm volatile("cp.async.commit_group;" ::: "memory")
#define CP_WAIT0()  asm volatile("cp.async.wait_group 0;" ::: "memory")
#define CP_WAIT1()  asm volatile("cp.async.wait_group 1;" ::: "memory")

__device__ __forceinline__ void tile_async(uint32_t dst, const bf16* __restrict__ src,
                                           int ld, int rows, int tid) {
    const int units = rows * 8;
    for (int u = tid; u < units; u += 256) {
        int r = u >> 3, j = u & 7;
        cpasync16(dst + SWZ((uint32_t)(r * 128 + j * 16)), src + (size_t)r * ld + j * 8);
    }
}
__device__ __forceinline__ uint32_t pk2(bf16 a, bf16 b) {
    bf162 t; t.x = a; t.y = b; return *reinterpret_cast<uint32_t*>(&t);
}
__device__ __forceinline__ void splitf(float f, bf16& h, bf16& l) {
    h = __float2bfloat16(f);
    l = __float2bfloat16(f - __bfloat162float(h));
}
// packed pair split via F2FP: hi/lo are bf16x2 words (lower=f0, upper=f1)
__device__ __forceinline__ void splitf2(float f0, float f1, uint32_t& hi, uint32_t& lo) {
    asm("cvt.rn.bf16x2.f32 %0, %2, %1;" : "=r"(hi) : "f"(f0), "f"(f1));
    float h0 = __uint_as_float(hi << 16);
    float h1 = __uint_as_float(hi & 0xffff0000u);
    float l0 = f0 - h0, l1 = f1 - h1;
    asm("cvt.rn.bf16x2.f32 %0, %2, %1;" : "=r"(lo) : "f"(l0), "f"(l1));
}

// Shared mainloop: A 128x64 hi/lo, B 64x64 hi/lo (swizzled) -> c[2][4][4]
__device__ __forceinline__ void mma_stage(uint32_t ahb, uint32_t alb, uint32_t bhb, uint32_t blb,
                                          int wr, int wc, int lane, float (&c)[2][4][4]) {
    #pragma unroll
    for (int ks = 0; ks < 4; ks++) {
        uint32_t fah[2][4], fal[2][4], fbh[2][4], fbl[2][4];
        #pragma unroll
        for (int mf = 0; mf < 2; mf++) {
            ldsm4(fah[mf], a_addr(ahb, wr * 32 + mf * 16, ks * 16, lane));
            ldsm4(fal[mf], a_addr(alb, wr * 32 + mf * 16, ks * 16, lane));
        }
        #pragma unroll
        for (int g = 0; g < 2; g++) {
            ldsm4(fbh[g], b_addr4(bhb, wc * 32 + g * 16, ks * 16, lane));
            ldsm4(fbl[g], b_addr4(blb, wc * 32 + g * 16, ks * 16, lane));
        }
        #pragma unroll
        for (int mf = 0; mf < 2; mf++)
            #pragma unroll
            for (int nf = 0; nf < 4; nf++) {
                const uint32_t* bh_ = &fbh[nf >> 1][(nf & 1) * 2];
                const uint32_t* bl_ = &fbl[nf >> 1][(nf & 1) * 2];
                hmma(c[mf][nf], fah[mf], bh_);
                hmma(c[mf][nf], fah[mf], bl_);
                hmma(c[mf][nf], fal[mf], bh_);
            }
    }
}

// ---------------- merged pre-split kernels ----------------------------------
__global__ __launch_bounds__(256) void split3(
    const float* __restrict__ q, const float* __restrict__ k, const float* __restrict__ v) {
    const int n4 = NT * DM / 4;
    int i = blockIdx.x * 256 + threadIdx.x;
    if (i >= n4) return;
    int sel = blockIdx.y;
    const float* x = sel == 0 ? q : sel == 1 ? k : v;
    bf16* hi = (bf16*)(g_buf + (size_t)(2 * sel) * SZ_X);
    bf16* lo = (bf16*)(g_buf + (size_t)(2 * sel + 1) * SZ_X);
    float4 f = reinterpret_cast<const float4*>(x)[i];
    uint2 hv, lv;
    splitf2(f.x, f.y, hv.x, lv.x);
    splitf2(f.z, f.w, hv.y, lv.y);
    reinterpret_cast<uint2*>(hi)[i] = hv;
    reinterpret_cast<uint2*>(lo)[i] = lv;
}
__global__ __launch_bounds__(256) void wsplit4(
    const float* __restrict__ Wq, const float* __restrict__ Wk,
    const float* __restrict__ Wv, const float* __restrict__ Wo) {
    int idx = blockIdx.x * 256 + threadIdx.x;
    if (idx >= DM * DM) return;
    int sel = blockIdx.y;
    const float* W = sel == 0 ? Wq : sel == 1 ? Wk : sel == 2 ? Wv : Wo;
    bf16* th = (bf16*)(g_buf + O_W) + (size_t)sel * 2 * (DM * DM);
    bf16* tl = th + DM * DM;
    int n = idx / DM, k = idx % DM;
    bf16 h, l; splitf(W[(size_t)k * DM + n], h, l);
    th[idx] = h; tl[idx] = l;
}

// ---------------- merged QKV projection (grid.z = sel) -----------------------
#define G_ST 49152
#define SM_G 98304

__global__ __launch_bounds__(256, 2) void qkv_mma(
    const float* __restrict__ bq, const float* __restrict__ bk, const float* __restrict__ bv)
{
    extern __shared__ char smem[];
    const uint32_t sb = s2u(smem);
    const int tid = threadIdx.x, wid = tid >> 5, lane = tid & 31;
    const int wr = wid >> 1, wc = wid & 1;
    const int sel = blockIdx.z;
    const int mBase = blockIdx.y * 128, nBase = blockIdx.x * 64;
    const int NK = DM / 64;

    const bf16* Ahi = (const bf16*)(g_buf + (size_t)(2 * sel) * SZ_X);
    const bf16* Alo = (const bf16*)(g_buf + (size_t)(2 * sel + 1) * SZ_X);
    const bf16* Bhi = (const bf16*)(g_buf + O_W) + (size_t)sel * 2 * (DM * DM);
    const bf16* Blo = Bhi + DM * DM;
    const float* bias = sel == 0 ? bq : sel == 1 ? bk : bv;
    bf16* Ohi = (bf16*)(g_buf + O_QH + (size_t)(2 * sel) * SZ_HS);
    bf16* Olo = (bf16*)(g_buf + O_QH + (size_t)(2 * sel + 1) * SZ_HS);

    float c[2][4][4];
    #pragma unroll
    for (int i = 0; i < 2; i++)
        #pragma unroll
        for (int j = 0; j < 4; j++)
            #pragma unroll
            for (int q = 0; q < 4; q++) c[i][j][q] = 0.f;

    tile_async(sb + 0,     Ahi + (size_t)mBase * DM, DM, 128, tid);
    tile_async(sb + 16384, Alo + (size_t)mBase * DM, DM, 128, tid);
    tile_async(sb + 32768, Bhi + (size_t)nBase * DM, DM, 64, tid);
    tile_async(sb + 40960, Blo + (size_t)nBase * DM, DM, 64, tid);
    CP_COMMIT();

    #pragma unroll 1
    for (int kc = 0; kc < NK; kc++) {
        if (kc + 1 < NK) {
            uint32_t st = ((kc + 1) & 1) * G_ST;
            tile_async(sb + st + 0,     Ahi + (size_t)mBase * DM + (kc + 1) * 64, DM, 128, tid);
            tile_async(sb + st + 16384, Alo + (size_t)mBase * DM + (kc + 1) * 64, DM, 128, tid);
            tile_async(sb + st + 32768, Bhi + (size_t)nBase * DM + (kc + 1) * 64, DM, 64, tid);
            tile_async(sb + st + 40960, Blo + (size_t)nBase * DM + (kc + 1) * 64, DM, 64, tid);
            CP_COMMIT();
            CP_WAIT1();
        } else {
            CP_WAIT0();
        }
        __syncthreads();
        uint32_t st = (kc & 1) * G_ST;
        mma_stage(sb + st, sb + st + 16384, sb + st + 32768, sb + st + 40960, wr, wc, lane, c);
        __syncthreads();
    }

    const int gid = lane >> 2, tig = lane & 3;
    #pragma unroll
    for (int mf = 0; mf < 2; mf++)
        #pragma unroll
        for (int nf = 0; nf < 4; nf++) {
            int row0 = mBase + wr * 32 + mf * 16 + gid;
            int col  = nBase + wc * 32 + nf * 8 + tig * 2;
            float v0 = c[mf][nf][0] + bias[col];
            float v1 = c[mf][nf][1] + bias[col + 1];
            float v2 = c[mf][nf][2] + bias[col];
            float v3 = c[mf][nf][3] + bias[col + 1];
            int h = col >> 6, kk = col & 63;
            if (sel < 2) {
                #pragma unroll
                for (int rr = 0; rr < 2; rr++) {
                    int m = row0 + rr * 8;
                    int b = m >> 11, s = m & 2047;
                    float f0 = rr ? v2 : v0, f1 = rr ? v3 : v1;
                    uint32_t hw, lw;
                    splitf2(f0, f1, hw, lw);
                    size_t dst = (((size_t)b * NH + h) * SS + s) * DK + kk;
                    *reinterpret_cast<uint32_t*>(&Ohi[dst]) = hw;
                    *reinterpret_cast<uint32_t*>(&Olo[dst]) = lw;
                }
            } else {
                #pragma unroll
                for (int rr = 0; rr < 2; rr++) {
                    int m = row0 + rr * 8;
                    int b = m >> 11, s = m & 2047;
                    float f0 = rr ? v2 : v0, f1 = rr ? v3 : v1;
                    bf16 hh, ll;
                    size_t dst0 = (((size_t)b * NH + h) * DK + kk) * SS + s;
                    splitf(f0, hh, ll); Ohi[dst0] = hh; Olo[dst0] = ll;
                    size_t dst1 = (((size_t)b * NH + h) * DK + kk + 1) * SS + s;
                    splitf(f1, hh, ll); Ohi[dst1] = hh; Olo[dst1] = ll;
                }
            }
        }
}

// ---------------- output projection (fp32 epilogue) --------------------------
__global__ __launch_bounds__(256, 2) void oproj_mma(
    const bf16* __restrict__ Ahi, const bf16* __restrict__ Alo,
    const bf16* __restrict__ Bhi, const bf16* __restrict__ Blo,
    const float* __restrict__ bias, float* __restrict__ Cf)
{
    extern __shared__ char smem[];
    const uint32_t sb = s2u(smem);
    const int tid = threadIdx.x, wid = tid >> 5, lane = tid & 31;
    const int wr = wid >> 1, wc = wid & 1;
    const int mBase = blockIdx.y * 128, nBase = blockIdx.x * 64;
    const int NK = DM / 64;

    float c[2][4][4];
    #pragma unroll
    for (int i = 0; i < 2; i++)
        #pragma unroll
        for (int j = 0; j < 4; j++)
            #pragma unroll
            for (int q = 0; q < 4; q++) c[i][j][q] = 0.f;

    tile_async(sb + 0,     Ahi + (size_t)mBase * DM, DM, 128, tid);
    tile_async(sb + 16384, Alo + (size_t)mBase * DM, DM, 128, tid);
    tile_async(sb + 32768, Bhi + (size_t)nBase * DM, DM, 64, tid);
    tile_async(sb + 40960, Blo + (size_t)nBase * DM, DM, 64, tid);
    CP_COMMIT();

    #pragma unroll 1
    for (int kc = 0; kc < NK; kc++) {
        if (kc + 1 < NK) {
            uint32_t st = ((kc + 1) & 1) * G_ST;
            tile_async(sb + st + 0,     Ahi + (size_t)mBase * DM + (kc + 1) * 64, DM, 128, tid);
            tile_async(sb + st + 16384, Alo + (size_t)mBase * DM + (kc + 1) * 64, DM, 128, tid);
            tile_async(sb + st + 32768, Bhi + (size_t)nBase * DM + (kc + 1) * 64, DM, 64, tid);
            tile_async(sb + st + 40960, Blo + (size_t)nBase * DM + (kc + 1) * 64, DM, 64, tid);
            CP_COMMIT();
            CP_WAIT1();
        } else {
            CP_WAIT0();
        }
        __syncthreads();
        uint32_t st = (kc & 1) * G_ST;
        mma_stage(sb + st, sb + st + 16384, sb + st + 32768, sb + st + 40960, wr, wc, lane, c);
        __syncthreads();
    }

    const int gid = lane >> 2, tig = lane & 3;
    #pragma unroll
    for (int mf = 0; mf < 2; mf++)
        #pragma unroll
        for (int nf = 0; nf < 4; nf++) {
            int row0 = mBase + wr * 32 + mf * 16 + gid;
            int col  = nBase + wc * 32 + nf * 8 + tig * 2;
            float v0 = c[mf][nf][0] + bias[col];
            float v1 = c[mf][nf][1] + bias[col + 1];
            float v2 = c[mf][nf][2] + bias[col];
            float v3 = c[mf][nf][3] + bias[col + 1];
            *reinterpret_cast<float2*>(&Cf[(size_t)row0 * DM + col])       = make_float2(v0, v1);
            *reinterpret_cast<float2*>(&Cf[(size_t)(row0 + 8) * DM + col]) = make_float2(v2, v3);
        }
}

// ---------------- scores: Q-resident, staged E epilogue (coalesced STG) ------
// smem: Q 0..32K, K ring 32768..65536, Eh stage 65536, El stage 81920,
//       rowpart 98304;  SM_S = 99328
#define SC_K(st)  (32768 + (st) * 16384)
#define SC_EH     65536
#define SC_EL     81920
#define SM_S      99328

__global__ __launch_bounds__(256, 2) void scores_mma(float* __restrict__ psum)
{
    extern __shared__ char smem[];
    const uint32_t sb = s2u(smem);
    float (*rowpart)[128] = reinterpret_cast<float(*)[128]>(smem + 98304);
    const int tid = threadIdx.x, wid = tid >> 5, lane = tid & 31;
    const int wr = wid >> 1, wc = wid & 1;
    const int bh = blockIdx.z, qBase = blockIdx.y * 128, kBase0 = blockIdx.x * 256;

    const bf16* Qh = (const bf16*)(g_buf + O_QH);
    const bf16* Ql = (const bf16*)(g_buf + O_QL);
    const bf16* Kh = (const bf16*)(g_buf + O_KH);
    const bf16* Kl = (const bf16*)(g_buf + O_KL);
    bf16* EhP = (bf16*)(g_buf + O_EH);
    bf16* ElP = (bf16*)(g_buf + O_EL);

    tile_async(sb + 0,     Qh + ((size_t)bh * SS + qBase) * DK, DK, 128, tid);
    tile_async(sb + 16384, Ql + ((size_t)bh * SS + qBase) * DK, DK, 128, tid);
    tile_async(sb + SC_K(0),        Kh + ((size_t)bh * SS + kBase0) * DK, DK, 64, tid);
    tile_async(sb + SC_K(0) + 8192, Kl + ((size_t)bh * SS + kBase0) * DK, DK, 64, tid);
    CP_COMMIT();
    tile_async(sb + SC_K(1),        Kh + ((size_t)bh * SS + kBase0 + 64) * DK, DK, 64, tid);
    tile_async(sb + SC_K(1) + 8192, Kl + ((size_t)bh * SS + kBase0 + 64) * DK, DK, 64, tid);
    CP_COMMIT();

    const int gid = lane >> 2, tig = lane & 3;
    float pacc[2][2] = {{0.f, 0.f}, {0.f, 0.f}};

    #pragma unroll 1
    for (int kc = 0; kc < 4; kc++) {
        const int st = kc & 1;
        if (kc < 3) { CP_WAIT1(); } else { CP_WAIT0(); }
        __syncthreads();

        float c[2][4][4];
        #pragma unroll
        for (int i = 0; i < 2; i++)
            #pragma unroll
            for (int j = 0; j < 4; j++)
                #pragma unroll
                for (int q = 0; q < 4; q++) c[i][j][q] = 0.f;

        mma_stage(sb, sb + 16384, sb + SC_K(st), sb + SC_K(st) + 8192, wr, wc, lane, c);

        // exp + split -> staged smem tiles (SWZ, bank-spread)
        #pragma unroll
        for (int mf = 0; mf < 2; mf++) {
            int rloc0 = wr * 32 + mf * 16 + gid;
            #pragma unroll
            for (int nf = 0; nf < 4; nf++) {
                int colin = wc * 32 + nf * 8 + tig * 2;
                float e0 = __expf(c[mf][nf][0] * 0.125f);
                float e1 = __expf(c[mf][nf][1] * 0.125f);
                float e2 = __expf(c[mf][nf][2] * 0.125f);
                float e3 = __expf(c[mf][nf][3] * 0.125f);
                pacc[mf][0] += e0 + e1; pacc[mf][1] += e2 + e3;
                uint32_t hA, lA, hB, lB;
                splitf2(e0, e1, hA, lA);
                splitf2(e2, e3, hB, lB);
                uint32_t o0 = SWZ((uint32_t)(rloc0 * 128 + colin * 2));
                uint32_t o1 = SWZ((uint32_t)((rloc0 + 8) * 128 + colin * 2));
                asm volatile("st.shared.b32 [%0], %1;" :: "r"(sb + SC_EH + o0), "r"(hA) : "memory");
                asm volatile("st.shared.b32 [%0], %1;" :: "r"(sb + SC_EL + o0), "r"(lA) : "memory");
                asm volatile("st.shared.b32 [%0], %1;" :: "r"(sb + SC_EH + o1), "r"(hB) : "memory");
                asm volatile("st.shared.b32 [%0], %1;" :: "r"(sb + SC_EL + o1), "r"(lB) : "memory");
            }
        }
        __syncthreads();
        // prefetch next K chunk (ring slot now free)
        if (kc + 2 < 4) {
            tile_async(sb + SC_K(st),        Kh + ((size_t)bh * SS + kBase0 + (kc + 2) * 64) * DK, DK, 64, tid);
            tile_async(sb + SC_K(st) + 8192, Kl + ((size_t)bh * SS + kBase0 + (kc + 2) * 64) * DK, DK, 64, tid);
            CP_COMMIT();
        }
        // cooperative coalesced writeout of both E planes
        {
            const size_t gb = ((size_t)bh * SS + qBase) * SS + kBase0 + kc * 64;
            #pragma unroll 1
            for (int u = tid; u < 1024; u += 256) {
                int r = u >> 3, j = u & 7;
                uint32_t off = SWZ((uint32_t)(r * 128 + j * 16));
                uint4 vh_, vl_;
                asm volatile("ld.shared.v4.b32 {%0,%1,%2,%3}, [%4];"
                             : "=r"(vh_.x), "=r"(vh_.y), "=r"(vh_.z), "=r"(vh_.w) : "r"(sb + SC_EH + off));
                asm volatile("ld.shared.v4.b32 {%0,%1,%2,%3}, [%4];"
                             : "=r"(vl_.x), "=r"(vl_.y), "=r"(vl_.z), "=r"(vl_.w) : "r"(sb + SC_EL + off));
                *reinterpret_cast<uint4*>(&EhP[gb + (size_t)r * SS + j * 8]) = vh_;
                *reinterpret_cast<uint4*>(&ElP[gb + (size_t)r * SS + j * 8]) = vl_;
            }
        }
    }

    #pragma unroll
    for (int mf = 0; mf < 2; mf++) {
        float p0 = pacc[mf][0], p1 = pacc[mf][1];
        p0 += __shfl_xor_sync(0xffffffffu, p0, 1); p0 += __shfl_xor_sync(0xffffffffu, p0, 2);
        p1 += __shfl_xor_sync(0xffffffffu, p1, 1); p1 += __shfl_xor_sync(0xffffffffu, p1, 2);
        if (tig == 0) {
            int rloc0 = wr * 32 + mf * 16 + gid;
            rowpart[wc][rloc0]     = p0;
            rowpart[wc][rloc0 + 8] = p1;
        }
    }
    __syncthreads();
    if (tid < 128) {
        float s = rowpart[0][tid] + rowpart[1][tid];
        psum[((size_t)bh * SS + qBase + tid) * 8 + blockIdx.x] = s;
    }
}

// ---------------- pv: GEMM on Eh/El bf16 planes + attn write + epilogue scale
#define PV_E(s)  ((uint32_t)(s) * 32768u)
#define PV_V2(s) (65536u + (uint32_t)(s) * 16384u)
#define PV_RI    98304u
#define SM_PV    98816

__global__ __launch_bounds__(256, 2) void pv_mma(
    float* __restrict__ attn, const float* __restrict__ psum)
{
    extern __shared__ char smem[];
    const uint32_t sb = s2u(smem);
    float* rowinv = reinterpret_cast<float*>(smem + PV_RI);
    const int tid = threadIdx.x, wid = tid >> 5, lane = tid & 31;
    const int wr = wid >> 1, wc = wid & 1;
    const int bh = blockIdx.y, b = bh / NH, h = bh % NH;
    const int qBase = blockIdx.x * 128;

    const bf16* Vh = (const bf16*)(g_buf + O_VH);
    const bf16* Vl = (const bf16*)(g_buf + O_VL);
    const bf16* Eh0 = (const bf16*)(g_buf + O_EH) + ((size_t)bh * SS + qBase) * SS;
    const bf16* El0 = (const bf16*)(g_buf + O_EL) + ((size_t)bh * SS + qBase) * SS;
    bf16* AOh = (bf16*)(g_buf + O_AOH);
    bf16* AOl = (bf16*)(g_buf + O_AOL);
    float* arow0 = attn + ((size_t)bh * SS + qBase) * SS;
    const size_t vbase = (size_t)bh * DK * SS;

    if (tid < 128) {
        const float* pp = psum + ((size_t)bh * SS + qBase + tid) * 8;
        float s = 0.f;
        #pragma unroll
        for (int i = 0; i < 8; i++) s += pp[i];
        rowinv[tid] = 1.0f / s;
    }

    float c[2][4][4];
    #pragma unroll
    for (int i = 0; i < 2; i++)
        #pragma unroll
        for (int j = 0; j < 4; j++)
            #pragma unroll
            for (int q = 0; q < 4; q++) c[i][j][q] = 0.f;

    #pragma unroll
    for (int g = 0; g < 2; g++) {
        tile_async(sb + PV_E(g),         Eh0 + g * 64, SS, 128, tid);
        tile_async(sb + PV_E(g) + 16384, El0 + g * 64, SS, 128, tid);
        tile_async(sb + PV_V2(g),        Vh + vbase + g * 64, SS, 64, tid);
        tile_async(sb + PV_V2(g) + 8192, Vl + vbase + g * 64, SS, 64, tid);
        CP_COMMIT();
    }

    #pragma unroll 1
    for (int kc = 0; kc < 32; kc++) {
        const int st = kc & 1;
        if (kc < 31) { CP_WAIT1(); } else { CP_WAIT0(); }
        __syncthreads();
        // normalize + attn write (row-contiguous units: 4 lines/STG instr)
        {
            uint32_t eb = sb + PV_E(st);
            #pragma unroll
            for (int it = 0; it < 8; it++) {
                int u = tid + it * 256;
                int r = u >> 4, ch = u & 15;
                float inv = rowinv[r];
                uint32_t off = SWZ((uint32_t)(r * 128 + ch * 8));
                uint32_t hx, hy, lx, ly;
                asm volatile("ld.shared.v2.b32 {%0,%1}, [%2];" : "=r"(hx), "=r"(hy) : "r"(eb + off));
                asm volatile("ld.shared.v2.b32 {%0,%1}, [%2];" : "=r"(lx), "=r"(ly) : "r"(eb + 16384 + off));
                float f0 = __uint_as_float(hx << 16)          + __uint_as_float(lx << 16);
                float f1 = __uint_as_float(hx & 0xffff0000u)  + __uint_as_float(lx & 0xffff0000u);
                float f2 = __uint_as_float(hy << 16)          + __uint_as_float(ly << 16);
                float f3 = __uint_as_float(hy & 0xffff0000u)  + __uint_as_float(ly & 0xffff0000u);
                __stcs(reinterpret_cast<float4*>(arow0 + (size_t)r * SS + kc * 64 + ch * 4),
                       make_float4(f0 * inv, f1 * inv, f2 * inv, f3 * inv));
            }
        }
        mma_stage(sb + PV_E(st), sb + PV_E(st) + 16384,
                  sb + PV_V2(st), sb + PV_V2(st) + 8192, wr, wc, lane, c);
        __syncthreads();
        if (kc + 2 < 32) {
            int g = kc + 2;
            tile_async(sb + PV_E(st),         Eh0 + g * 64, SS, 128, tid);
            tile_async(sb + PV_E(st) + 16384, El0 + g * 64, SS, 128, tid);
            tile_async(sb + PV_V2(st),        Vh + vbase + g * 64, SS, 64, tid);
            tile_async(sb + PV_V2(st) + 8192, Vl + vbase + g * 64, SS, 64, tid);
            CP_COMMIT();
        }
    }

    const int gid = lane >> 2, tig = lane & 3;
    #pragma unroll
    for (int mf = 0; mf < 2; mf++)
        #pragma unroll
        for (int nf = 0; nf < 4; nf++) {
            int rloc = wr * 32 + mf * 16 + gid;
            int col  = wc * 32 + nf * 8 + tig * 2;
            float inv0 = rowinv[rloc], inv1 = rowinv[rloc + 8];
            #pragma unroll
            for (int rr = 0; rr < 2; rr++) {
                int s = qBase + rloc + rr * 8;
                float inv = rr ? inv1 : inv0;
                float f0 = c[mf][nf][rr * 2 + 0] * inv, f1 = c[mf][nf][rr * 2 + 1] * inv;
                uint32_t hw, lw;
                splitf2(f0, f1, hw, lw);
                size_t dst = ((size_t)b * SS + s) * DM + h * DK + col;
                *reinterpret_cast<uint32_t*>(&AOh[dst]) = hw;
                *reinterpret_cast<uint32_t*>(&AOl[dst]) = lw;
            }
        }
}

// ---------------------------------------------------------------------------
extern "C" void kernel_launch(void* const* d_in, const int* in_sizes, int n_in,
                              void* d_out, int out_size)
{
    (void)in_sizes; (void)n_in; (void)out_size;
    const float* q  = (const float*)d_in[0];
    const float* k  = (const float*)d_in[1];
    const float* v  = (const float*)d_in[2];
    const float* Wq = (const float*)d_in[3];
    const float* bq = (const float*)d_in[4];
    const float* Wk = (const float*)d_in[5];
    const float* bk = (const float*)d_in[6];
    const float* Wv = (const float*)d_in[7];
    const float* bv = (const float*)d_in[8];
    const float* Wo = (const float*)d_in[9];
    const float* bo = (const float*)d_in[10];

    float* out  = (float*)d_out;
    float* attn = out + (size_t)NT * DM;

    char* base = nullptr;
    cudaGetSymbolAddress((void**)&base, g_buf);
    bf16* wb  = (bf16*)(base + O_W);
    bf16* woh = wb + 6*(size_t)DM*DM; bf16* wol = wb + 7*(size_t)DM*DM;
    bf16* AOh = (bf16*)(base + O_AOH); bf16* AOl = (bf16*)(base + O_AOL);
    float* psum = (float*)(base + O_PSUM);

    cudaFuncSetAttribute(qkv_mma,    cudaFuncAttributeMaxDynamicSharedMemorySize, SM_G);
    cudaFuncSetAttribute(oproj_mma,  cudaFuncAttributeMaxDynamicSharedMemorySize, SM_G);
    cudaFuncSetAttribute(scores_mma, cudaFuncAttributeMaxDynamicSharedMemorySize, SM_S);
    cudaFuncSetAttribute(pv_mma,     cudaFuncAttributeMaxDynamicSharedMemorySize, SM_PV);

    const int n4 = NT * DM / 4;
    split3<<<dim3((n4 + 255) / 256, 3), 256>>>(q, k, v);
    wsplit4<<<dim3((DM * DM + 255) / 256, 4), 256>>>(Wq, Wk, Wv, Wo);

    dim3 gProj(DM / 64, NT / 128, 3);  // 12 x 64 x 3
    qkv_mma<<<gProj, 256, SM_G>>>(bq, bk, bv);

    dim3 gS(SS / 256, SS / 128, BHN);  // 8 x 16 x 48
    scores_mma<<<gS, 256, SM_S>>>(psum);

    dim3 gPV(SS / 128, BHN);           // 16 x 48
    pv_mma<<<gPV, 256, SM_PV>>>(attn, psum);

    dim3 gO(DM / 64, NT / 128);        // 12 x 64
    oproj_mma<<<gO, 256, SM_G>>>(AOh, AOl, woh, wol, bo, out);
}